// round 1
// baseline (speedup 1.0000x reference)
#include <cuda_runtime.h>
#include <cstdio>

// Problem constants
#define B_  4
#define S_  2048
#define D_  1024
#define H_  16
#define HD_ 64
#define M_  (B_ * S_)   // 8192 rows

// Scratch (allocation-free rule: __device__ globals)
__device__ float g_q[M_ * D_];
__device__ float g_k[M_ * D_];
__device__ float g_v[M_ * D_];
__device__ float g_c[M_ * D_];

// ---------------------------------------------------------------------------
// SGEMM: C[M,N] = A[M,K] @ B[K,N] (+ bias). M=8192, N=K=1024 fixed.
// 128x128 block tile, BK=8, 256 threads, 8x8 per-thread register tile.
// ---------------------------------------------------------------------------
__global__ __launch_bounds__(256) void sgemm128(const float* __restrict__ A,
                                                const float* __restrict__ Bm,
                                                const float* __restrict__ bias,
                                                float* __restrict__ C) {
    const int K = D_, N = D_;
    __shared__ float As[8][128];   // [k][m] (transposed on load)
    __shared__ float Bs[8][128];   // [k][n]

    const int tid = threadIdx.x;
    const int bx = blockIdx.x, by = blockIdx.y;
    const int tx = tid & 15, ty = tid >> 4;

    const int aRow = tid >> 1;          // 0..127
    const int aCol = (tid & 1) * 4;     // 0 or 4
    const int bRow = tid >> 5;          // 0..7
    const int bCol = (tid & 31) * 4;    // 0..124

    const float* Ag = A + (size_t)(by * 128 + aRow) * K + aCol;
    const float* Bg = Bm + (size_t)bRow * N + bx * 128 + bCol;

    float acc[8][8] = {};

    for (int k0 = 0; k0 < K; k0 += 8) {
        float4 av = *(const float4*)Ag; Ag += 8;
        float4 bv = *(const float4*)Bg; Bg += (size_t)8 * N;
        As[aCol + 0][aRow] = av.x;
        As[aCol + 1][aRow] = av.y;
        As[aCol + 2][aRow] = av.z;
        As[aCol + 3][aRow] = av.w;
        *(float4*)&Bs[bRow][bCol] = bv;
        __syncthreads();

#pragma unroll
        for (int kk = 0; kk < 8; kk++) {
            float a[8], b[8];
            *(float4*)&a[0] = *(const float4*)&As[kk][ty * 8];
            *(float4*)&a[4] = *(const float4*)&As[kk][ty * 8 + 4];
            *(float4*)&b[0] = *(const float4*)&Bs[kk][tx * 8];
            *(float4*)&b[4] = *(const float4*)&Bs[kk][tx * 8 + 4];
#pragma unroll
            for (int i = 0; i < 8; i++)
#pragma unroll
                for (int j = 0; j < 8; j++)
                    acc[i][j] += a[i] * b[j];
        }
        __syncthreads();
    }

#pragma unroll
    for (int i = 0; i < 8; i++) {
        const int row = by * 128 + ty * 8 + i;
#pragma unroll
        for (int j = 0; j < 8; j += 4) {
            const int col = bx * 128 + tx * 8 + j;
            float4 r;
            r.x = acc[i][j + 0];
            r.y = acc[i][j + 1];
            r.z = acc[i][j + 2];
            r.w = acc[i][j + 3];
            if (bias) {
                r.x += bias[col + 0];
                r.y += bias[col + 1];
                r.z += bias[col + 2];
                r.w += bias[col + 3];
            }
            *(float4*)&C[(size_t)row * N + col] = r;
        }
    }
}

// ---------------------------------------------------------------------------
// Causal attention, flash-style without running max (scores/4096 are tiny,
// exp cannot overflow; streaming exp-sum softmax is exact).
// One CTA per (64-query-tile, head, batch). 256 threads, 4x4 register tiles.
// ctx[b,q,h,:] = softmax_k(q.k/4096, causal) @ V
// ---------------------------------------------------------------------------
#define PITCH 68   // float pitch for 64-wide smem tiles (16B-aligned rows)

__global__ __launch_bounds__(256) void attn_kernel(const float* __restrict__ q,
                                                   const float* __restrict__ k,
                                                   const float* __restrict__ v,
                                                   float* __restrict__ ctx) {
    extern __shared__ float sm[];
    float (*Qs)[PITCH] = (float(*)[PITCH])(sm);                 // [d][i]
    float (*Ks)[PITCH] = (float(*)[PITCH])(sm + 64 * PITCH);    // [d][j]
    float (*Vs)[PITCH] = (float(*)[PITCH])(sm + 2 * 64 * PITCH);// [j][c]
    float (*Ps)[PITCH] = (float(*)[PITCH])(sm + 3 * 64 * PITCH);// [j][i]

    const int tid = threadIdx.x;
    const int qt = blockIdx.x;       // query tile (0..31)
    const int h  = blockIdx.y;
    const int b  = blockIdx.z;
    const int tx = tid & 15, ty = tid >> 4;
    const int i0 = ty * 4;           // rows owned (scores + output)
    const int j0 = tx * 4;           // cols owned (keys for scores, dims for output)

    const size_t base = ((size_t)b * S_) * D_ + (size_t)h * HD_;

    // Load Q tile transposed: Qs[d][i]
    for (int t = tid; t < 64 * 16; t += 256) {
        const int row = t >> 4, dc = (t & 15) * 4;
        float4 vq = *(const float4*)&q[base + (size_t)(qt * 64 + row) * D_ + dc];
        Qs[dc + 0][row] = vq.x;
        Qs[dc + 1][row] = vq.y;
        Qs[dc + 2][row] = vq.z;
        Qs[dc + 3][row] = vq.w;
    }

    float acc[4][4] = {};
    float lrow[4]   = {};

    for (int kt = 0; kt <= qt; kt++) {
        __syncthreads();   // protect K/V/P from previous iteration's readers (and Qs load)
        // Load K (transposed) and V tiles
        for (int t = tid; t < 64 * 16; t += 256) {
            const int row = t >> 4, dc = (t & 15) * 4;
            const size_t goff = base + (size_t)(kt * 64 + row) * D_ + dc;
            float4 vk = *(const float4*)&k[goff];
            Ks[dc + 0][row] = vk.x;
            Ks[dc + 1][row] = vk.y;
            Ks[dc + 2][row] = vk.z;
            Ks[dc + 3][row] = vk.w;
            float4 vv = *(const float4*)&v[goff];
            *(float4*)&Vs[row][dc] = vv;
        }
        __syncthreads();

        // S = Q @ K^T  (4x4 per thread)
        float s[4][4] = {};
#pragma unroll 16
        for (int d = 0; d < 64; d++) {
            float4 qa = *(const float4*)&Qs[d][i0];
            float4 kb = *(const float4*)&Ks[d][j0];
            const float qr[4] = {qa.x, qa.y, qa.z, qa.w};
            const float kr[4] = {kb.x, kb.y, kb.z, kb.w};
#pragma unroll
            for (int ii = 0; ii < 4; ii++)
#pragma unroll
                for (int jj = 0; jj < 4; jj++)
                    s[ii][jj] += qr[ii] * kr[jj];
        }

        // mask -> exp -> stash in Ps[j][i]; accumulate per-row partial sums
        const bool diag = (kt == qt);
#pragma unroll
        for (int ii = 0; ii < 4; ii++) {
#pragma unroll
            for (int jj = 0; jj < 4; jj++) {
                float p;
                if (diag && (j0 + jj > i0 + ii)) {
                    p = 0.0f;
                } else {
                    p = __expf(s[ii][jj] * (1.0f / 4096.0f));
                }
                Ps[j0 + jj][i0 + ii] = p;
                lrow[ii] += p;
            }
        }
        __syncthreads();   // Ps ready

        // acc += P @ V  (thread owns rows i0.., output dims j0..)
#pragma unroll 16
        for (int j = 0; j < 64; j++) {
            float4 pa = *(const float4*)&Ps[j][i0];
            float4 vb = *(const float4*)&Vs[j][j0];
            const float pr[4] = {pa.x, pa.y, pa.z, pa.w};
            const float vr[4] = {vb.x, vb.y, vb.z, vb.w};
#pragma unroll
            for (int ii = 0; ii < 4; ii++)
#pragma unroll
                for (int cc = 0; cc < 4; cc++)
                    acc[ii][cc] += pr[ii] * vr[cc];
        }
    }

    // Reduce row sums across the 16 tx lanes sharing each row group
#pragma unroll
    for (int off = 8; off >= 1; off >>= 1) {
#pragma unroll
        for (int ii = 0; ii < 4; ii++)
            lrow[ii] += __shfl_xor_sync(0xffffffffu, lrow[ii], off);
    }

    // Write ctx[b, qrow, h*HD + c] = acc / l
#pragma unroll
    for (int ii = 0; ii < 4; ii++) {
        const float inv = 1.0f / lrow[ii];
        const size_t off = base + (size_t)(qt * 64 + i0 + ii) * D_ + j0;
        float4 r;
        r.x = acc[ii][0] * inv;
        r.y = acc[ii][1] * inv;
        r.z = acc[ii][2] * inv;
        r.w = acc[ii][3] * inv;
        *(float4*)&ctx[off] = r;
    }
}

// ---------------------------------------------------------------------------
// Launch
// ---------------------------------------------------------------------------
extern "C" void kernel_launch(void* const* d_in, const int* in_sizes, int n_in,
                              void* d_out, int out_size) {
    const float* x  = (const float*)d_in[0];
    const float* Wq = (const float*)d_in[1];
    const float* Wk = (const float*)d_in[2];
    const float* Wv = (const float*)d_in[3];
    const float* Wo = (const float*)d_in[4];
    const float* bo = (const float*)d_in[5];
    float* out = (float*)d_out;

    float *pq, *pk, *pv, *pc;
    cudaGetSymbolAddress((void**)&pq, g_q);
    cudaGetSymbolAddress((void**)&pk, g_k);
    cudaGetSymbolAddress((void**)&pv, g_v);
    cudaGetSymbolAddress((void**)&pc, g_c);

    const int attn_smem = 4 * 64 * PITCH * (int)sizeof(float);  // 69632 B
    cudaFuncSetAttribute(attn_kernel, cudaFuncAttributeMaxDynamicSharedMemorySize,
                         attn_smem);

    dim3 ggemm(D_ / 128, M_ / 128);   // (8, 64)
    sgemm128<<<ggemm, 256>>>(x, Wq, nullptr, pq);
    sgemm128<<<ggemm, 256>>>(x, Wk, nullptr, pk);
    sgemm128<<<ggemm, 256>>>(x, Wv, nullptr, pv);

    dim3 gattn(S_ / 64, H_, B_);      // (32, 16, 4)
    attn_kernel<<<gattn, 256, attn_smem>>>(pq, pk, pv, pc);

    sgemm128<<<ggemm, 256>>>(pc, Wo, bo, out);
}

// round 4
// speedup vs baseline: 1.2250x; 1.2250x over previous
#include <cuda_runtime.h>
#include <cstdint>

// Problem constants
#define B_  4
#define S_  2048
#define D_  1024
#define H_  16
#define HD_ 64
#define M_  (B_ * S_)   // 8192 rows

// Scratch (allocation-free rule: __device__ globals)
__device__ float g_q[M_ * D_];
__device__ float g_k[M_ * D_];
__device__ float g_v[M_ * D_];
__device__ float g_c[M_ * D_];

// ---------------------------------------------------------------------------
// cp.async helpers
// ---------------------------------------------------------------------------
__device__ __forceinline__ void cp_async16(void* smem, const void* gmem) {
    uint32_t s = (uint32_t)__cvta_generic_to_shared(smem);
    asm volatile("cp.async.cg.shared.global [%0], [%1], 16;\n" :: "r"(s), "l"(gmem));
}
__device__ __forceinline__ void cp_commit() {
    asm volatile("cp.async.commit_group;\n");
}
template <int N>
__device__ __forceinline__ void cp_wait() {
    asm volatile("cp.async.wait_group %0;\n" :: "n"(N));
}

#define MMA_TF32(c, a, b)                                                     \
    asm volatile(                                                             \
        "mma.sync.aligned.m16n8k8.row.col.f32.tf32.tf32.f32 "                 \
        "{%0,%1,%2,%3},{%4,%5,%6,%7},{%8,%9},{%0,%1,%2,%3};"                  \
        : "+f"(c[0]), "+f"(c[1]), "+f"(c[2]), "+f"(c[3])                      \
        : "r"(a[0]), "r"(a[1]), "r"(a[2]), "r"(a[3]), "r"(b[0]), "r"(b[1]))

// 3xTF32 split: x = hi + lo with hi,lo representable in tf32.
__device__ __forceinline__ void split_tf32(float x, uint32_t& hi, uint32_t& lo) {
    asm("cvt.rna.tf32.f32 %0, %1;" : "=r"(hi) : "f"(x));
    float r = x - __uint_as_float(hi);
    asm("cvt.rna.tf32.f32 %0, %1;" : "=r"(lo) : "f"(r));
}

// ---------------------------------------------------------------------------
// 3xTF32 tensor-core GEMM: C[M,N] = A[M,K] @ B[K,N] (+bias). fp32-accurate.
// 128x128 CTA tile, K-chunk 32, 8 warps (4M x 2N), m16n8k8 fragments,
// cp.async double-buffered fp32 smem tiles; hi/lo split done in registers.
// Conflict-free pitches: A pitch 36, B pitch 136.
// ---------------------------------------------------------------------------
#define AP 36
#define BP 136

__global__ __launch_bounds__(256) void gemm_tf32x3(const float* __restrict__ A,
                                                   const float* __restrict__ Bm,
                                                   const float* __restrict__ bias,
                                                   float* __restrict__ C) {
    const int K = D_, N = D_;
    extern __shared__ float sm[];
    float* As = sm;                   // [2][128][AP]
    float* Bs = sm + 2 * 128 * AP;    // [2][32][BP]

    const int tid = threadIdx.x;
    const int wid = tid >> 5, lane = tid & 31;
    const int grp = lane >> 2, tg = lane & 3;
    const int wm = wid & 3;   // warp row group: 32 rows
    const int wn = wid >> 2;  // warp col group: 64 cols
    const int bx = blockIdx.x, by = blockIdx.y;

    const int KT = K / 32;

    float acc[2][8][4] = {};

    auto loadA = [&](int stage, int k0) {
        float* dst = As + stage * 128 * AP;
        const float* src = A + (size_t)(by * 128) * K + k0;
#pragma unroll
        for (int it = 0; it < 4; it++) {
            int idx = tid + it * 256;
            int row = idx >> 3, c4 = idx & 7;
            cp_async16(dst + row * AP + c4 * 4, src + (size_t)row * K + c4 * 4);
        }
    };
    auto loadB = [&](int stage, int k0) {
        float* dst = Bs + stage * 32 * BP;
        const float* src = Bm + (size_t)k0 * N + bx * 128;
#pragma unroll
        for (int it = 0; it < 4; it++) {
            int idx = tid + it * 256;
            int row = idx >> 5, c4 = idx & 31;
            cp_async16(dst + row * BP + c4 * 4, src + (size_t)row * N + c4 * 4);
        }
    };

    auto compute = [&](int stage) {
        const float* Ab = As + stage * 128 * AP + (wm * 32 + grp) * AP;
        const float* Bbase = Bs + stage * 32 * BP;
#pragma unroll
        for (int ks = 0; ks < 4; ks++) {
            const int kb = ks * 8;
            uint32_t ah[2][4], al[2][4];
#pragma unroll
            for (int mf = 0; mf < 2; mf++) {
                const float* p = Ab + mf * 16 * AP + kb;
                split_tf32(p[tg],              ah[mf][0], al[mf][0]);
                split_tf32(p[8 * AP + tg],     ah[mf][1], al[mf][1]);
                split_tf32(p[tg + 4],          ah[mf][2], al[mf][2]);
                split_tf32(p[8 * AP + tg + 4], ah[mf][3], al[mf][3]);
            }
            uint32_t bh[8][2], bl[8][2];
#pragma unroll
            for (int nf = 0; nf < 8; nf++) {
                const float* p = Bbase + (kb + tg) * BP + wn * 64 + nf * 8 + grp;
                split_tf32(p[0],      bh[nf][0], bl[nf][0]);
                split_tf32(p[4 * BP], bh[nf][1], bl[nf][1]);
            }
#pragma unroll
            for (int mf = 0; mf < 2; mf++)
#pragma unroll
                for (int nf = 0; nf < 8; nf++) {
                    MMA_TF32(acc[mf][nf], ah[mf], bh[nf]);
                    MMA_TF32(acc[mf][nf], al[mf], bh[nf]);
                    MMA_TF32(acc[mf][nf], ah[mf], bl[nf]);
                }
        }
    };

    loadA(0, 0);
    loadB(0, 0);
    cp_commit();

    int stage = 0;
    for (int kt = 0; kt < KT; kt++) {
        if (kt + 1 < KT) {
            loadA(stage ^ 1, (kt + 1) * 32);
            loadB(stage ^ 1, (kt + 1) * 32);
            cp_commit();
            cp_wait<1>();
        } else {
            cp_wait<0>();
        }
        __syncthreads();
        compute(stage);
        stage ^= 1;
        __syncthreads();
    }

#pragma unroll
    for (int mf = 0; mf < 2; mf++) {
#pragma unroll
        for (int nf = 0; nf < 8; nf++) {
            const int row = by * 128 + wm * 32 + mf * 16 + grp;
            const int col = bx * 128 + wn * 64 + nf * 8 + 2 * tg;
            float b0 = 0.f, b1 = 0.f;
            if (bias) { b0 = bias[col]; b1 = bias[col + 1]; }
            C[(size_t)row * N + col]           = acc[mf][nf][0] + b0;
            C[(size_t)row * N + col + 1]       = acc[mf][nf][1] + b1;
            C[(size_t)(row + 8) * N + col]     = acc[mf][nf][2] + b0;
            C[(size_t)(row + 8) * N + col + 1] = acc[mf][nf][3] + b1;
        }
    }
}

// ---------------------------------------------------------------------------
// Causal attention, flash-style without running max (scores/4096 are tiny,
// exp cannot overflow; streaming exp-sum softmax is exact).
// One CTA per (64-query-tile, head, batch). 256 threads, 4x4 register tiles.
// ---------------------------------------------------------------------------
#define PITCH 68

__global__ __launch_bounds__(256) void attn_kernel(const float* __restrict__ q,
                                                   const float* __restrict__ k,
                                                   const float* __restrict__ v,
                                                   float* __restrict__ ctx) {
    extern __shared__ float sm[];
    float (*Qs)[PITCH] = (float(*)[PITCH])(sm);
    float (*Ks)[PITCH] = (float(*)[PITCH])(sm + 64 * PITCH);
    float (*Vs)[PITCH] = (float(*)[PITCH])(sm + 2 * 64 * PITCH);
    float (*Ps)[PITCH] = (float(*)[PITCH])(sm + 3 * 64 * PITCH);

    const int tid = threadIdx.x;
    const int qt = blockIdx.x;
    const int h  = blockIdx.y;
    const int b  = blockIdx.z;
    const int tx = tid & 15, ty = tid >> 4;
    const int i0 = ty * 4;
    const int j0 = tx * 4;

    const size_t base = ((size_t)b * S_) * D_ + (size_t)h * HD_;

    for (int t = tid; t < 64 * 16; t += 256) {
        const int row = t >> 4, dc = (t & 15) * 4;
        float4 vq = *(const float4*)&q[base + (size_t)(qt * 64 + row) * D_ + dc];
        Qs[dc + 0][row] = vq.x;
        Qs[dc + 1][row] = vq.y;
        Qs[dc + 2][row] = vq.z;
        Qs[dc + 3][row] = vq.w;
    }

    float acc[4][4] = {};
    float lrow[4]   = {};

    for (int kt = 0; kt <= qt; kt++) {
        __syncthreads();
        for (int t = tid; t < 64 * 16; t += 256) {
            const int row = t >> 4, dc = (t & 15) * 4;
            const size_t goff = base + (size_t)(kt * 64 + row) * D_ + dc;
            float4 vk = *(const float4*)&k[goff];
            Ks[dc + 0][row] = vk.x;
            Ks[dc + 1][row] = vk.y;
            Ks[dc + 2][row] = vk.z;
            Ks[dc + 3][row] = vk.w;
            float4 vv = *(const float4*)&v[goff];
            *(float4*)&Vs[row][dc] = vv;
        }
        __syncthreads();

        float s[4][4] = {};
#pragma unroll 16
        for (int d = 0; d < 64; d++) {
            float4 qa = *(const float4*)&Qs[d][i0];
            float4 kb = *(const float4*)&Ks[d][j0];
            const float qr[4] = {qa.x, qa.y, qa.z, qa.w};
            const float kr[4] = {kb.x, kb.y, kb.z, kb.w};
#pragma unroll
            for (int ii = 0; ii < 4; ii++)
#pragma unroll
                for (int jj = 0; jj < 4; jj++)
                    s[ii][jj] += qr[ii] * kr[jj];
        }

        const bool diag = (kt == qt);
#pragma unroll
        for (int ii = 0; ii < 4; ii++) {
#pragma unroll
            for (int jj = 0; jj < 4; jj++) {
                float p;
                if (diag && (j0 + jj > i0 + ii)) {
                    p = 0.0f;
                } else {
                    p = __expf(s[ii][jj] * (1.0f / 4096.0f));
                }
                Ps[j0 + jj][i0 + ii] = p;
                lrow[ii] += p;
            }
        }
        __syncthreads();

#pragma unroll 16
        for (int j = 0; j < 64; j++) {
            float4 pa = *(const float4*)&Ps[j][i0];
            float4 vb = *(const float4*)&Vs[j][j0];
            const float pr[4] = {pa.x, pa.y, pa.z, pa.w};
            const float vr[4] = {vb.x, vb.y, vb.z, vb.w};
#pragma unroll
            for (int ii = 0; ii < 4; ii++)
#pragma unroll
                for (int cc = 0; cc < 4; cc++)
                    acc[ii][cc] += pr[ii] * vr[cc];
        }
    }

#pragma unroll
    for (int off = 8; off >= 1; off >>= 1) {
#pragma unroll
        for (int ii = 0; ii < 4; ii++)
            lrow[ii] += __shfl_xor_sync(0xffffffffu, lrow[ii], off);
    }

#pragma unroll
    for (int ii = 0; ii < 4; ii++) {
        const float inv = 1.0f / lrow[ii];
        const size_t off = base + (size_t)(qt * 64 + i0 + ii) * D_ + j0;
        float4 r;
        r.x = acc[ii][0] * inv;
        r.y = acc[ii][1] * inv;
        r.z = acc[ii][2] * inv;
        r.w = acc[ii][3] * inv;
        *(float4*)&ctx[off] = r;
    }
}

// ---------------------------------------------------------------------------
// Launch
// ---------------------------------------------------------------------------
extern "C" void kernel_launch(void* const* d_in, const int* in_sizes, int n_in,
                              void* d_out, int out_size) {
    const float* x  = (const float*)d_in[0];
    const float* Wq = (const float*)d_in[1];
    const float* Wk = (const float*)d_in[2];
    const float* Wv = (const float*)d_in[3];
    const float* Wo = (const float*)d_in[4];
    const float* bo = (const float*)d_in[5];
    float* out = (float*)d_out;

    float *pq, *pk, *pv, *pc;
    cudaGetSymbolAddress((void**)&pq, g_q);
    cudaGetSymbolAddress((void**)&pk, g_k);
    cudaGetSymbolAddress((void**)&pv, g_v);
    cudaGetSymbolAddress((void**)&pc, g_c);

    const int gemm_smem = 2 * (128 * AP + 32 * BP) * (int)sizeof(float);  // 71680 B
    cudaFuncSetAttribute(gemm_tf32x3, cudaFuncAttributeMaxDynamicSharedMemorySize,
                         gemm_smem);
    const int attn_smem = 4 * 64 * PITCH * (int)sizeof(float);            // 69632 B
    cudaFuncSetAttribute(attn_kernel, cudaFuncAttributeMaxDynamicSharedMemorySize,
                         attn_smem);

    dim3 ggemm(D_ / 128, M_ / 128);   // (8, 64)
    gemm_tf32x3<<<ggemm, 256, gemm_smem>>>(x, Wq, nullptr, pq);
    gemm_tf32x3<<<ggemm, 256, gemm_smem>>>(x, Wk, nullptr, pk);
    gemm_tf32x3<<<ggemm, 256, gemm_smem>>>(x, Wv, nullptr, pv);

    dim3 gattn(S_ / 64, H_, B_);      // (32, 16, 4)
    attn_kernel<<<gattn, 256, attn_smem>>>(pq, pk, pv, pc);

    gemm_tf32x3<<<ggemm, 256, gemm_smem>>>(pc, Wo, bo, out);
}

// round 8
// speedup vs baseline: 1.7508x; 1.4292x over previous
#include <cuda_runtime.h>
#include <cstdint>

// Problem constants
#define B_  4
#define S_  2048
#define D_  1024
#define H_  16
#define HD_ 64
#define M_  (B_ * S_)   // 8192 rows

// Scratch (allocation-free rule: __device__ globals)
__device__ float g_q[M_ * D_];
__device__ float g_k[M_ * D_];
__device__ float g_v[M_ * D_];
__device__ float g_c[M_ * D_];

// ---------------------------------------------------------------------------
// cp.async helpers
// ---------------------------------------------------------------------------
__device__ __forceinline__ void cp_async16(void* smem, const void* gmem) {
    uint32_t s = (uint32_t)__cvta_generic_to_shared(smem);
    asm volatile("cp.async.cg.shared.global [%0], [%1], 16;\n" :: "r"(s), "l"(gmem));
}
__device__ __forceinline__ void cp_commit() {
    asm volatile("cp.async.commit_group;\n");
}
template <int N>
__device__ __forceinline__ void cp_wait() {
    asm volatile("cp.async.wait_group %0;\n" :: "n"(N));
}

#define MMA_TF32(c, a, b)                                                     \
    asm volatile(                                                             \
        "mma.sync.aligned.m16n8k8.row.col.f32.tf32.tf32.f32 "                 \
        "{%0,%1,%2,%3},{%4,%5,%6,%7},{%8,%9},{%0,%1,%2,%3};"                  \
        : "+f"(c[0]), "+f"(c[1]), "+f"(c[2]), "+f"(c[3])                      \
        : "r"(a[0]), "r"(a[1]), "r"(a[2]), "r"(a[3]), "r"(b[0]), "r"(b[1]))

// 3xTF32 split: x = hi + lo with hi,lo representable in tf32.
__device__ __forceinline__ void split_tf32(float x, uint32_t& hi, uint32_t& lo) {
    asm("cvt.rna.tf32.f32 %0, %1;" : "=r"(hi) : "f"(x));
    float r = x - __uint_as_float(hi);
    asm("cvt.rna.tf32.f32 %0, %1;" : "=r"(lo) : "f"(r));
}
__device__ __forceinline__ float tf32f(float x) {
    uint32_t u;
    asm("cvt.rna.tf32.f32 %0, %1;" : "=r"(u) : "f"(x));
    return __uint_as_float(u);
}

// ---------------------------------------------------------------------------
// 3xTF32 tensor-core GEMM: C[M,N] = A[M,K] @ B[K,N] (+bias). fp32-accurate.
// 128x128 CTA tile, K-chunk 32, 8 warps (4M x 2N), m16n8k8 fragments,
// cp.async double-buffered fp32 smem tiles; hi/lo split done in registers.
// ---------------------------------------------------------------------------
#define AP 36
#define BP 136

__global__ __launch_bounds__(256) void gemm_tf32x3(const float* __restrict__ A,
                                                   const float* __restrict__ Bm,
                                                   const float* __restrict__ bias,
                                                   float* __restrict__ C) {
    const int K = D_, N = D_;
    extern __shared__ float sm[];
    float* As = sm;                   // [2][128][AP]
    float* Bs = sm + 2 * 128 * AP;    // [2][32][BP]

    const int tid = threadIdx.x;
    const int wid = tid >> 5, lane = tid & 31;
    const int grp = lane >> 2, tg = lane & 3;
    const int wm = wid & 3;
    const int wn = wid >> 2;
    const int bx = blockIdx.x, by = blockIdx.y;

    const int KT = K / 32;

    float acc[2][8][4] = {};

    auto loadA = [&](int stage, int k0) {
        float* dst = As + stage * 128 * AP;
        const float* src = A + (size_t)(by * 128) * K + k0;
#pragma unroll
        for (int it = 0; it < 4; it++) {
            int idx = tid + it * 256;
            int row = idx >> 3, c4 = idx & 7;
            cp_async16(dst + row * AP + c4 * 4, src + (size_t)row * K + c4 * 4);
        }
    };
    auto loadB = [&](int stage, int k0) {
        float* dst = Bs + stage * 32 * BP;
        const float* src = Bm + (size_t)k0 * N + bx * 128;
#pragma unroll
        for (int it = 0; it < 4; it++) {
            int idx = tid + it * 256;
            int row = idx >> 5, c4 = idx & 31;
            cp_async16(dst + row * BP + c4 * 4, src + (size_t)row * N + c4 * 4);
        }
    };

    auto compute = [&](int stage) {
        const float* Ab = As + stage * 128 * AP + (wm * 32 + grp) * AP;
        const float* Bbase = Bs + stage * 32 * BP;
#pragma unroll
        for (int ks = 0; ks < 4; ks++) {
            const int kb = ks * 8;
            uint32_t ah[2][4], al[2][4];
#pragma unroll
            for (int mf = 0; mf < 2; mf++) {
                const float* p = Ab + mf * 16 * AP + kb;
                split_tf32(p[tg],              ah[mf][0], al[mf][0]);
                split_tf32(p[8 * AP + tg],     ah[mf][1], al[mf][1]);
                split_tf32(p[tg + 4],          ah[mf][2], al[mf][2]);
                split_tf32(p[8 * AP + tg + 4], ah[mf][3], al[mf][3]);
            }
            uint32_t bh[8][2], bl[8][2];
#pragma unroll
            for (int nf = 0; nf < 8; nf++) {
                const float* p = Bbase + (kb + tg) * BP + wn * 64 + nf * 8 + grp;
                split_tf32(p[0],      bh[nf][0], bl[nf][0]);
                split_tf32(p[4 * BP], bh[nf][1], bl[nf][1]);
            }
#pragma unroll
            for (int mf = 0; mf < 2; mf++)
#pragma unroll
                for (int nf = 0; nf < 8; nf++) {
                    MMA_TF32(acc[mf][nf], ah[mf], bh[nf]);
                    MMA_TF32(acc[mf][nf], al[mf], bh[nf]);
                    MMA_TF32(acc[mf][nf], ah[mf], bl[nf]);
                }
        }
    };

    loadA(0, 0);
    loadB(0, 0);
    cp_commit();

    int stage = 0;
    for (int kt = 0; kt < KT; kt++) {
        if (kt + 1 < KT) {
            loadA(stage ^ 1, (kt + 1) * 32);
            loadB(stage ^ 1, (kt + 1) * 32);
            cp_commit();
            cp_wait<1>();
        } else {
            cp_wait<0>();
        }
        __syncthreads();
        compute(stage);
        stage ^= 1;
        __syncthreads();
    }

#pragma unroll
    for (int mf = 0; mf < 2; mf++) {
#pragma unroll
        for (int nf = 0; nf < 8; nf++) {
            const int row = by * 128 + wm * 32 + mf * 16 + grp;
            const int col = bx * 128 + wn * 64 + nf * 8 + 2 * tg;
            float b0 = 0.f, b1 = 0.f;
            if (bias) { b0 = bias[col]; b1 = bias[col + 1]; }
            C[(size_t)row * N + col]           = acc[mf][nf][0] + b0;
            C[(size_t)row * N + col + 1]       = acc[mf][nf][1] + b1;
            C[(size_t)(row + 8) * N + col]     = acc[mf][nf][2] + b0;
            C[(size_t)(row + 8) * N + col + 1] = acc[mf][nf][3] + b1;
        }
    }
}

// ---------------------------------------------------------------------------
// Tensor-core causal attention via the P = 1 + D decomposition.
//   p = exp(s/4096), |s/4096| <= ~0.01  =>  p = 1 + d, |d| <= 0.011
//   O_q = colsum(V) + D @ V        (masked entries: d = -1, exact in tf32)
//   l_q = 64*(qt+1) + sum(d)
//   d = expm1(x) = x + x^2/2 + x^3/6   (3 FFMA, no MUFU)
// S^T = K @ Q^T so Q, K, V all live in natural [token][d] layout (no
// transposes). 1-pass tf32 for QK and DV; diagonal tile adds one (d, v_lo)
// pass so the -1 cancellation against colsum is exact to 2^-22.
// One CTA per (64-query-tile, head, batch); 8 warps, m16n8k8 fragments.
// Pitches: 68 (=4 mod 32) for A-side arrays, 72 (=8 mod 32) for B-side V.
// ---------------------------------------------------------------------------
#define QP 68
#define VP 72

__global__ __launch_bounds__(256) void attn_mma(const float* __restrict__ q,
                                                const float* __restrict__ k,
                                                const float* __restrict__ v,
                                                float* __restrict__ ctx) {
    extern __shared__ float sm[];
    float* Qs    = sm;                 // [64][QP]  tf32 Q[qtok][d]   (B operand)
    float* Ks    = Qs + 64 * QP;       // [64][QP]  tf32 K[ktok][d]   (A operand)
    float* Dh    = Ks + 64 * QP;       // [64][QP]  tf32 D[qtok][ktok](A operand)
    float* Vh    = Dh + 64 * QP;       // [64][VP]  tf32 V hi [ktok][d] (B)
    float* Vl    = Vh + 64 * VP;       // [64][VP]  tf32 V lo
    float* Cpart = Vl + 64 * VP;       // [16][64]  colsum partials
    float* Csum  = Cpart + 16 * 64;    // [64]
    float* Lred  = Csum + 64;          // [4][64]   dsum partials per k-warp

    const int tid = threadIdx.x;
    const int wid = tid >> 5, lane = tid & 31;
    const int grp = lane >> 2, tg = lane & 3;
    const int wm = wid & 3;            // S^T: k-row group / PV: q-row group
    const int wn = wid >> 2;           // S^T: q-col group / PV: d-col group
    const int qt = blockIdx.x, h = blockIdx.y, b = blockIdx.z;

    const size_t base = ((size_t)b * S_) * D_ + (size_t)h * HD_;

    // Load Q tile once (tf32-converted, natural layout)
    for (int t = tid; t < 64 * 16; t += 256) {
        const int row = t >> 4, dc = (t & 15) * 4;
        float4 vq = *(const float4*)&q[base + (size_t)(qt * 64 + row) * D_ + dc];
        float4 qc;
        qc.x = tf32f(vq.x); qc.y = tf32f(vq.y);
        qc.z = tf32f(vq.z); qc.w = tf32f(vq.w);
        *(float4*)&Qs[row * QP + dc] = qc;
    }

    float acc[4][4]  = {};
    float dsum[4][2] = {};

    for (int kt = 0; kt <= qt; kt++) {
        __syncthreads();   // (A) previous tile fully consumed

        // Load K (tf32) and V (hi/lo split) tiles; fp32 colsum partials.
        float4 cs = {0.f, 0.f, 0.f, 0.f};
#pragma unroll
        for (int it = 0; it < 4; it++) {
            const int idx = tid + it * 256;
            const int row = idx >> 4, dc = (idx & 15) * 4;
            const size_t goff = base + (size_t)(kt * 64 + row) * D_ + dc;
            float4 kv = *(const float4*)&k[goff];
            float4 kc;
            kc.x = tf32f(kv.x); kc.y = tf32f(kv.y);
            kc.z = tf32f(kv.z); kc.w = tf32f(kv.w);
            *(float4*)&Ks[row * QP + dc] = kc;
            float4 vv = *(const float4*)&v[goff];
            cs.x += vv.x; cs.y += vv.y; cs.z += vv.z; cs.w += vv.w;
            float4 vhi, vlo;
            uint32_t hu, lu;
            split_tf32(vv.x, hu, lu); vhi.x = __uint_as_float(hu); vlo.x = __uint_as_float(lu);
            split_tf32(vv.y, hu, lu); vhi.y = __uint_as_float(hu); vlo.y = __uint_as_float(lu);
            split_tf32(vv.z, hu, lu); vhi.z = __uint_as_float(hu); vlo.z = __uint_as_float(lu);
            split_tf32(vv.w, hu, lu); vhi.w = __uint_as_float(hu); vlo.w = __uint_as_float(lu);
            *(float4*)&Vh[row * VP + dc] = vhi;
            *(float4*)&Vl[row * VP + dc] = vlo;
        }
        *(float4*)&Cpart[(tid >> 4) * 64 + (tid & 15) * 4] = cs;
        __syncthreads();   // (B) tiles + colsum partials ready

        // Small colsum reduce (warps 0-1)
        if (tid < 64) {
            float s = 0.f;
#pragma unroll
            for (int p2 = 0; p2 < 16; p2++) s += Cpart[p2 * 64 + tid];
            Csum[tid] = s;
        }

        // S^T = K @ Q^T  (m = k-token, n = q-token), 1-pass tf32
        float s[4][4] = {};
        const float* Ka = Ks + (wm * 16 + grp) * QP;
#pragma unroll
        for (int ks = 0; ks < 8; ks++) {
            const int kb = ks * 8;
            uint32_t a[4];
            a[0] = __float_as_uint(Ka[kb + tg]);
            a[1] = __float_as_uint(Ka[8 * QP + kb + tg]);
            a[2] = __float_as_uint(Ka[kb + tg + 4]);
            a[3] = __float_as_uint(Ka[8 * QP + kb + tg + 4]);
#pragma unroll
            for (int nf = 0; nf < 4; nf++) {
                const float* Qb = Qs + (wn * 32 + nf * 8 + grp) * QP + kb + tg;
                uint32_t bb[2] = { __float_as_uint(Qb[0]), __float_as_uint(Qb[4]) };
                MMA_TF32(s[nf], a, bb);
            }
        }

        // d = expm1(s/4096); masked (ktok > qtok) -> d = -1. Store D^T -> Dh[q][k].
        const int kg0 = kt * 64 + wm * 16 + grp;   // global k-token of c0/c1
        const int kloc = wm * 16 + grp;
#pragma unroll
        for (int nf = 0; nf < 4; nf++) {
            const int qg0  = qt * 64 + wn * 32 + nf * 8 + 2 * tg;  // global q of c0/c2
            const int qloc = wn * 32 + nf * 8 + 2 * tg;
            float d0, d1, d2, d3;
            {
                float x = s[nf][0] * (1.f / 4096.f);
                d0 = (kg0 <= qg0)     ? x * (1.f + x * (0.5f + x * (1.f / 6.f))) : -1.f;
                x = s[nf][1] * (1.f / 4096.f);
                d1 = (kg0 <= qg0 + 1) ? x * (1.f + x * (0.5f + x * (1.f / 6.f))) : -1.f;
                x = s[nf][2] * (1.f / 4096.f);
                d2 = (kg0 + 8 <= qg0)     ? x * (1.f + x * (0.5f + x * (1.f / 6.f))) : -1.f;
                x = s[nf][3] * (1.f / 4096.f);
                d3 = (kg0 + 8 <= qg0 + 1) ? x * (1.f + x * (0.5f + x * (1.f / 6.f))) : -1.f;
            }
            dsum[nf][0] += d0 + d2;
            dsum[nf][1] += d1 + d3;
            Dh[qloc * QP + kloc]           = tf32f(d0);
            Dh[(qloc + 1) * QP + kloc]     = tf32f(d1);
            Dh[qloc * QP + kloc + 8]       = tf32f(d2);
            Dh[(qloc + 1) * QP + kloc + 8] = tf32f(d3);
        }
        __syncthreads();   // (C) Dh + Csum ready

        // acc += D @ V  (m = q-token, n = d-col); diag tile adds (d, v_lo) pass
        const float* Da = Dh + (wm * 16 + grp) * QP;
        const bool diag = (kt == qt);
#pragma unroll
        for (int ks = 0; ks < 8; ks++) {
            const int kb = ks * 8;
            uint32_t a[4];
            a[0] = __float_as_uint(Da[kb + tg]);
            a[1] = __float_as_uint(Da[8 * QP + kb + tg]);
            a[2] = __float_as_uint(Da[kb + tg + 4]);
            a[3] = __float_as_uint(Da[8 * QP + kb + tg + 4]);
#pragma unroll
            for (int nf = 0; nf < 4; nf++) {
                const float* Vb = Vh + (kb + tg) * VP + wn * 32 + nf * 8 + grp;
                uint32_t bh[2] = { __float_as_uint(Vb[0]), __float_as_uint(Vb[4 * VP]) };
                MMA_TF32(acc[nf], a, bh);
            }
            if (diag) {
#pragma unroll
                for (int nf = 0; nf < 4; nf++) {
                    const float* Vb = Vl + (kb + tg) * VP + wn * 32 + nf * 8 + grp;
                    uint32_t bl[2] = { __float_as_uint(Vb[0]), __float_as_uint(Vb[4 * VP]) };
                    MMA_TF32(acc[nf], a, bl);
                }
            }
        }

        // acc += colsum(V) broadcast to every q-row
#pragma unroll
        for (int nf = 0; nf < 4; nf++) {
            const float c0 = Csum[wn * 32 + nf * 8 + 2 * tg];
            const float c1 = Csum[wn * 32 + nf * 8 + 2 * tg + 1];
            acc[nf][0] += c0; acc[nf][1] += c1;
            acc[nf][2] += c0; acc[nf][3] += c1;
        }
    }

    // Reduce dsum over grp lanes (lane = grp*4 + tg; xor 4,8,16 folds grp)
#pragma unroll
    for (int off = 16; off >= 4; off >>= 1)
#pragma unroll
        for (int nf = 0; nf < 4; nf++) {
            dsum[nf][0] += __shfl_xor_sync(0xffffffffu, dsum[nf][0], off);
            dsum[nf][1] += __shfl_xor_sync(0xffffffffu, dsum[nf][1], off);
        }
    if (grp == 0) {
#pragma unroll
        for (int nf = 0; nf < 4; nf++) {
            Lred[wm * 64 + wn * 32 + nf * 8 + 2 * tg]     = dsum[nf][0];
            Lred[wm * 64 + wn * 32 + nf * 8 + 2 * tg + 1] = dsum[nf][1];
        }
    }
    __syncthreads();

    // Epilogue: l = 64*(qt+1) + sum over the 4 k-warp partials; divide + store.
    const float nk = 64.0f * (float)(qt + 1);
    const int r0 = wm * 16 + grp, r1 = r0 + 8;
    float l0 = nk, l1 = nk;
#pragma unroll
    for (int w = 0; w < 4; w++) {
        l0 += Lred[w * 64 + r0];
        l1 += Lred[w * 64 + r1];
    }
    const float inv0 = 1.0f / l0, inv1 = 1.0f / l1;
#pragma unroll
    for (int nf = 0; nf < 4; nf++) {
        const int dcol = wn * 32 + nf * 8 + 2 * tg;
        float2 w0, w1;
        w0.x = acc[nf][0] * inv0; w0.y = acc[nf][1] * inv0;
        w1.x = acc[nf][2] * inv1; w1.y = acc[nf][3] * inv1;
        *(float2*)&ctx[base + (size_t)(qt * 64 + r0) * D_ + dcol] = w0;
        *(float2*)&ctx[base + (size_t)(qt * 64 + r1) * D_ + dcol] = w1;
    }
}

// ---------------------------------------------------------------------------
// Launch
// ---------------------------------------------------------------------------
extern "C" void kernel_launch(void* const* d_in, const int* in_sizes, int n_in,
                              void* d_out, int out_size) {
    const float* x  = (const float*)d_in[0];
    const float* Wq = (const float*)d_in[1];
    const float* Wk = (const float*)d_in[2];
    const float* Wv = (const float*)d_in[3];
    const float* Wo = (const float*)d_in[4];
    const float* bo = (const float*)d_in[5];
    float* out = (float*)d_out;

    float *pq, *pk, *pv, *pc;
    cudaGetSymbolAddress((void**)&pq, g_q);
    cudaGetSymbolAddress((void**)&pk, g_k);
    cudaGetSymbolAddress((void**)&pv, g_v);
    cudaGetSymbolAddress((void**)&pc, g_c);

    const int gemm_smem = 2 * (128 * AP + 32 * BP) * (int)sizeof(float);  // 71680 B
    cudaFuncSetAttribute(gemm_tf32x3, cudaFuncAttributeMaxDynamicSharedMemorySize,
                         gemm_smem);
    const int attn_smem = (3 * 64 * QP + 2 * 64 * VP + 16 * 64 + 64 + 4 * 64) *
                          (int)sizeof(float);                              // 94464 B
    cudaFuncSetAttribute(attn_mma, cudaFuncAttributeMaxDynamicSharedMemorySize,
                         attn_smem);

    dim3 ggemm(D_ / 128, M_ / 128);   // (8, 64)
    gemm_tf32x3<<<ggemm, 256, gemm_smem>>>(x, Wq, nullptr, pq);
    gemm_tf32x3<<<ggemm, 256, gemm_smem>>>(x, Wk, nullptr, pk);
    gemm_tf32x3<<<ggemm, 256, gemm_smem>>>(x, Wv, nullptr, pv);

    dim3 gattn(S_ / 64, H_, B_);      // (32, 16, 4)
    attn_mma<<<gattn, 256, attn_smem>>>(pq, pk, pv, pc);

    gemm_tf32x3<<<ggemm, 256, gemm_smem>>>(pc, Wo, bo, out);
}

// round 9
// speedup vs baseline: 2.5075x; 1.4322x over previous
#include <cuda_runtime.h>
#include <cuda_bf16.h>
#include <cstdint>

// Problem constants
#define B_  4
#define S_  2048
#define D_  1024
#define H_  16
#define HD_ 64
#define M_  (B_ * S_)   // 8192 rows

// Scratch (allocation-free rule: __device__ globals)
__device__ float g_q[M_ * D_];
__device__ float g_k[M_ * D_];
__device__ float g_v[M_ * D_];
__device__ float g_c[M_ * D_];
// bf16x3 pre-split operands
__device__ __nv_bfloat16 g_xh[M_ * D_], g_xl[M_ * D_];    // x hi/lo [M][K]
__device__ __nv_bfloat16 g_ch[M_ * D_], g_cl[M_ * D_];    // ctx hi/lo [M][K]
__device__ __nv_bfloat16 g_wh[4 * D_ * D_];               // W^T hi [N][K] x4
__device__ __nv_bfloat16 g_wl[4 * D_ * D_];               // W^T lo

// ---------------------------------------------------------------------------
// cp.async helpers
// ---------------------------------------------------------------------------
__device__ __forceinline__ void cp_async16(void* smem, const void* gmem) {
    uint32_t s = (uint32_t)__cvta_generic_to_shared(smem);
    asm volatile("cp.async.cg.shared.global [%0], [%1], 16;\n" :: "r"(s), "l"(gmem));
}
__device__ __forceinline__ void cp_commit() {
    asm volatile("cp.async.commit_group;\n");
}
template <int N>
__device__ __forceinline__ void cp_wait() {
    asm volatile("cp.async.wait_group %0;\n" :: "n"(N));
}

#define MMA_TF32(c, a, b)                                                     \
    asm volatile(                                                             \
        "mma.sync.aligned.m16n8k8.row.col.f32.tf32.tf32.f32 "                 \
        "{%0,%1,%2,%3},{%4,%5,%6,%7},{%8,%9},{%0,%1,%2,%3};"                  \
        : "+f"(c[0]), "+f"(c[1]), "+f"(c[2]), "+f"(c[3])                      \
        : "r"(a[0]), "r"(a[1]), "r"(a[2]), "r"(a[3]), "r"(b[0]), "r"(b[1]))

#define MMA_BF16(c, a, b)                                                     \
    asm volatile(                                                             \
        "mma.sync.aligned.m16n8k16.row.col.f32.bf16.bf16.f32 "                \
        "{%0,%1,%2,%3},{%4,%5,%6,%7},{%8,%9},{%0,%1,%2,%3};"                  \
        : "+f"(c[0]), "+f"(c[1]), "+f"(c[2]), "+f"(c[3])                      \
        : "r"(a[0]), "r"(a[1]), "r"(a[2]), "r"(a[3]), "r"(b[0]), "r"(b[1]))

// 3xTF32 split (attention V path)
__device__ __forceinline__ void split_tf32(float x, uint32_t& hi, uint32_t& lo) {
    asm("cvt.rna.tf32.f32 %0, %1;" : "=r"(hi) : "f"(x));
    float r = x - __uint_as_float(hi);
    asm("cvt.rna.tf32.f32 %0, %1;" : "=r"(lo) : "f"(r));
}
__device__ __forceinline__ float tf32f(float x) {
    uint32_t u;
    asm("cvt.rna.tf32.f32 %0, %1;" : "=r"(u) : "f"(x));
    return __uint_as_float(u);
}
__device__ __forceinline__ void split_bf16(float x, __nv_bfloat16& h, __nv_bfloat16& l) {
    h = __float2bfloat16_rn(x);
    l = __float2bfloat16_rn(x - __bfloat162float(h));
}

// ---------------------------------------------------------------------------
// Prep: elementwise fp32 -> bf16 hi/lo split (for x and ctx, [M][K] layout).
// ---------------------------------------------------------------------------
__global__ __launch_bounds__(256) void fsplit(const float* __restrict__ src,
                                              __nv_bfloat16* __restrict__ h,
                                              __nv_bfloat16* __restrict__ l) {
    const int i = blockIdx.x * 256 + threadIdx.x;   // one float4 per thread
    float4 v = ((const float4*)src)[i];
    __nv_bfloat16 h0, h1, h2, h3, l0, l1, l2, l3;
    split_bf16(v.x, h0, l0);
    split_bf16(v.y, h1, l1);
    split_bf16(v.z, h2, l2);
    split_bf16(v.w, h3, l3);
    __nv_bfloat162* hp = (__nv_bfloat162*)h;
    __nv_bfloat162* lp = (__nv_bfloat162*)l;
    hp[2 * i]     = __nv_bfloat162{h0, h1};
    hp[2 * i + 1] = __nv_bfloat162{h2, h3};
    lp[2 * i]     = __nv_bfloat162{l0, l1};
    lp[2 * i + 1] = __nv_bfloat162{l2, l3};
}

// ---------------------------------------------------------------------------
// Prep: W [K][N] -> W^T hi/lo bf16 [N][K], 32x32 smem tile transpose.
// blockIdx.z selects which of the 4 weights.
// ---------------------------------------------------------------------------
__global__ __launch_bounds__(256) void wsplit_t(const float* __restrict__ W0,
                                                const float* __restrict__ W1,
                                                const float* __restrict__ W2,
                                                const float* __restrict__ W3,
                                                __nv_bfloat16* __restrict__ dh,
                                                __nv_bfloat16* __restrict__ dl) {
    __shared__ float t[32][33];
    const float* W = (blockIdx.z == 0) ? W0 : (blockIdx.z == 1) ? W1
                   : (blockIdx.z == 2) ? W2 : W3;
    dh += (size_t)blockIdx.z * D_ * D_;
    dl += (size_t)blockIdx.z * D_ * D_;
    const int kx = blockIdx.x * 32, ny = blockIdx.y * 32;
    const int tx = threadIdx.x & 31, ty = threadIdx.x >> 5;   // 32 x 8
#pragma unroll
    for (int r = 0; r < 4; r++) {
        const int row = ty + r * 8;
        t[row][tx] = W[(size_t)(kx + row) * D_ + ny + tx];    // t[k_loc][n_loc]
    }
    __syncthreads();
#pragma unroll
    for (int r = 0; r < 4; r++) {
        const int row = ty + r * 8;                            // n_loc
        __nv_bfloat16 h, l;
        split_bf16(t[tx][row], h, l);
        dh[(size_t)(ny + row) * D_ + kx + tx] = h;
        dl[(size_t)(ny + row) * D_ + kx + tx] = l;
    }
}

// ---------------------------------------------------------------------------
// bf16x3 tensor-core GEMM: C[M,N] = A[M,K] @ B[K,N] (+bias), fp32-accurate-ish
// (rel err ~3e-5). Operands pre-split: A hi/lo [M][K] bf16, B^T hi/lo [N][K].
// 128x128 CTA tile, K-chunk 32, 8 warps (4M x 2N), m16n8k16 fragments,
// cp.async double-buffered. Smem pitch 40 bf16 (20 u32) -> conflict-free
// fragment LDS (u32 bank = (row*20 + tg) % 32, distinct over the 8 rows).
// ---------------------------------------------------------------------------
#define GP 40                     // smem pitch in bf16
#define PLANE (128 * GP)          // 5120 bf16 per plane
#define STAGE (4 * PLANE)         // Ah, Al, Bh, Bl

__global__ __launch_bounds__(256) void gemm_bf16x3(
    const __nv_bfloat16* __restrict__ Ah, const __nv_bfloat16* __restrict__ Al,
    const __nv_bfloat16* __restrict__ Bh, const __nv_bfloat16* __restrict__ Bl,
    const float* __restrict__ bias, float* __restrict__ C) {
    const int K = D_, N = D_;
    extern __shared__ __nv_bfloat16 smb[];

    const int tid = threadIdx.x;
    const int wid = tid >> 5, lane = tid & 31;
    const int grp = lane >> 2, tg = lane & 3;
    const int wm = wid & 3;       // 32 M-rows per warp group
    const int wn = wid >> 2;      // 64 N-cols per warp group
    const int bx = blockIdx.x, by = blockIdx.y;

    float acc[2][8][4] = {};

    const __nv_bfloat16* srcA_h = Ah + (size_t)(by * 128) * K;
    const __nv_bfloat16* srcA_l = Al + (size_t)(by * 128) * K;
    const __nv_bfloat16* srcB_h = Bh + (size_t)(bx * 128) * K;
    const __nv_bfloat16* srcB_l = Bl + (size_t)(bx * 128) * K;

    auto load_stage = [&](int stage, int k0) {
        __nv_bfloat16* s = smb + stage * STAGE;
        const __nv_bfloat16* srcs[4] = {srcA_h + k0, srcA_l + k0,
                                        srcB_h + k0, srcB_l + k0};
#pragma unroll
        for (int plane = 0; plane < 4; plane++) {
#pragma unroll
            for (int half = 0; half < 2; half++) {
                const int idx = tid + half * 256;      // 512 chunks of 16B
                const int row = idx >> 2, c = idx & 3; // 4 chunks per 64B row
                cp_async16(s + plane * PLANE + row * GP + c * 8,
                           srcs[plane] + (size_t)row * K + c * 8);
            }
        }
    };

    auto compute = [&](int stage) {
        const uint32_t* b32 = (const uint32_t*)(smb + stage * STAGE);
        const uint32_t* pAh = b32 + (wm * 32 + grp) * 20;
        const uint32_t* pAl = pAh + PLANE / 2;
        const uint32_t* pBh = b32 + 2 * (PLANE / 2) + (wn * 64 + grp) * 20;
        const uint32_t* pBl = pBh + PLANE / 2;
#pragma unroll
        for (int ks = 0; ks < 2; ks++) {
            const int k32 = ks * 8;                    // u32 offset (16 bf16)
            uint32_t ah[2][4], al[2][4];
#pragma unroll
            for (int mf = 0; mf < 2; mf++) {
                const uint32_t* p = pAh + mf * 16 * 20 + k32;
                ah[mf][0] = p[tg];
                ah[mf][1] = p[160 + tg];
                ah[mf][2] = p[tg + 4];
                ah[mf][3] = p[160 + tg + 4];
                const uint32_t* q2 = pAl + mf * 16 * 20 + k32;
                al[mf][0] = q2[tg];
                al[mf][1] = q2[160 + tg];
                al[mf][2] = q2[tg + 4];
                al[mf][3] = q2[160 + tg + 4];
            }
            uint32_t bh[8][2], bl[8][2];
#pragma unroll
            for (int nf = 0; nf < 8; nf++) {
                const uint32_t* p = pBh + nf * 160 + k32;
                bh[nf][0] = p[tg];
                bh[nf][1] = p[tg + 4];
                const uint32_t* q2 = pBl + nf * 160 + k32;
                bl[nf][0] = q2[tg];
                bl[nf][1] = q2[tg + 4];
            }
#pragma unroll
            for (int mf = 0; mf < 2; mf++)
#pragma unroll
                for (int nf = 0; nf < 8; nf++) {
                    MMA_BF16(acc[mf][nf], ah[mf], bh[nf]);
                    MMA_BF16(acc[mf][nf], al[mf], bh[nf]);
                    MMA_BF16(acc[mf][nf], ah[mf], bl[nf]);
                }
        }
    };

    load_stage(0, 0);
    cp_commit();

    const int KT = K / 32;
    int stage = 0;
    for (int kt = 0; kt < KT; kt++) {
        if (kt + 1 < KT) {
            load_stage(stage ^ 1, (kt + 1) * 32);
            cp_commit();
            cp_wait<1>();
        } else {
            cp_wait<0>();
        }
        __syncthreads();
        compute(stage);
        stage ^= 1;
        __syncthreads();
    }

#pragma unroll
    for (int mf = 0; mf < 2; mf++) {
#pragma unroll
        for (int nf = 0; nf < 8; nf++) {
            const int row = by * 128 + wm * 32 + mf * 16 + grp;
            const int col = bx * 128 + wn * 64 + nf * 8 + 2 * tg;
            float b0 = 0.f, b1 = 0.f;
            if (bias) { b0 = bias[col]; b1 = bias[col + 1]; }
            C[(size_t)row * N + col]           = acc[mf][nf][0] + b0;
            C[(size_t)row * N + col + 1]       = acc[mf][nf][1] + b1;
            C[(size_t)(row + 8) * N + col]     = acc[mf][nf][2] + b0;
            C[(size_t)(row + 8) * N + col + 1] = acc[mf][nf][3] + b1;
        }
    }
}

// ---------------------------------------------------------------------------
// Tensor-core causal attention via the P = 1 + D decomposition (unchanged
// from the passing round-8 kernel).
// ---------------------------------------------------------------------------
#define QP 68
#define VP 72

__global__ __launch_bounds__(256) void attn_mma(const float* __restrict__ q,
                                                const float* __restrict__ k,
                                                const float* __restrict__ v,
                                                float* __restrict__ ctx) {
    extern __shared__ float sm[];
    float* Qs    = sm;                 // [64][QP]  tf32 Q[qtok][d]   (B operand)
    float* Ks    = Qs + 64 * QP;       // [64][QP]  tf32 K[ktok][d]   (A operand)
    float* Dh    = Ks + 64 * QP;       // [64][QP]  tf32 D[qtok][ktok](A operand)
    float* Vh    = Dh + 64 * QP;       // [64][VP]  tf32 V hi [ktok][d] (B)
    float* Vl    = Vh + 64 * VP;       // [64][VP]  tf32 V lo
    float* Cpart = Vl + 64 * VP;       // [16][64]  colsum partials
    float* Csum  = Cpart + 16 * 64;    // [64]
    float* Lred  = Csum + 64;          // [4][64]   dsum partials per k-warp

    const int tid = threadIdx.x;
    const int wid = tid >> 5, lane = tid & 31;
    const int grp = lane >> 2, tg = lane & 3;
    const int wm = wid & 3;
    const int wn = wid >> 2;
    const int qt = blockIdx.x, h = blockIdx.y, b = blockIdx.z;

    const size_t base = ((size_t)b * S_) * D_ + (size_t)h * HD_;

    for (int t = tid; t < 64 * 16; t += 256) {
        const int row = t >> 4, dc = (t & 15) * 4;
        float4 vq = *(const float4*)&q[base + (size_t)(qt * 64 + row) * D_ + dc];
        float4 qc;
        qc.x = tf32f(vq.x); qc.y = tf32f(vq.y);
        qc.z = tf32f(vq.z); qc.w = tf32f(vq.w);
        *(float4*)&Qs[row * QP + dc] = qc;
    }

    float acc[4][4]  = {};
    float dsum[4][2] = {};

    for (int kt = 0; kt <= qt; kt++) {
        __syncthreads();

        float4 cs = {0.f, 0.f, 0.f, 0.f};
#pragma unroll
        for (int it = 0; it < 4; it++) {
            const int idx = tid + it * 256;
            const int row = idx >> 4, dc = (idx & 15) * 4;
            const size_t goff = base + (size_t)(kt * 64 + row) * D_ + dc;
            float4 kv = *(const float4*)&k[goff];
            float4 kc;
            kc.x = tf32f(kv.x); kc.y = tf32f(kv.y);
            kc.z = tf32f(kv.z); kc.w = tf32f(kv.w);
            *(float4*)&Ks[row * QP + dc] = kc;
            float4 vv = *(const float4*)&v[goff];
            cs.x += vv.x; cs.y += vv.y; cs.z += vv.z; cs.w += vv.w;
            float4 vhi, vlo;
            uint32_t hu, lu;
            split_tf32(vv.x, hu, lu); vhi.x = __uint_as_float(hu); vlo.x = __uint_as_float(lu);
            split_tf32(vv.y, hu, lu); vhi.y = __uint_as_float(hu); vlo.y = __uint_as_float(lu);
            split_tf32(vv.z, hu, lu); vhi.z = __uint_as_float(hu); vlo.z = __uint_as_float(lu);
            split_tf32(vv.w, hu, lu); vhi.w = __uint_as_float(hu); vlo.w = __uint_as_float(lu);
            *(float4*)&Vh[row * VP + dc] = vhi;
            *(float4*)&Vl[row * VP + dc] = vlo;
        }
        *(float4*)&Cpart[(tid >> 4) * 64 + (tid & 15) * 4] = cs;
        __syncthreads();

        if (tid < 64) {
            float s = 0.f;
#pragma unroll
            for (int p2 = 0; p2 < 16; p2++) s += Cpart[p2 * 64 + tid];
            Csum[tid] = s;
        }

        float s[4][4] = {};
        const float* Ka = Ks + (wm * 16 + grp) * QP;
#pragma unroll
        for (int ks = 0; ks < 8; ks++) {
            const int kb = ks * 8;
            uint32_t a[4];
            a[0] = __float_as_uint(Ka[kb + tg]);
            a[1] = __float_as_uint(Ka[8 * QP + kb + tg]);
            a[2] = __float_as_uint(Ka[kb + tg + 4]);
            a[3] = __float_as_uint(Ka[8 * QP + kb + tg + 4]);
#pragma unroll
            for (int nf = 0; nf < 4; nf++) {
                const float* Qb = Qs + (wn * 32 + nf * 8 + grp) * QP + kb + tg;
                uint32_t bb[2] = { __float_as_uint(Qb[0]), __float_as_uint(Qb[4]) };
                MMA_TF32(s[nf], a, bb);
            }
        }

        const int kg0 = kt * 64 + wm * 16 + grp;
        const int kloc = wm * 16 + grp;
#pragma unroll
        for (int nf = 0; nf < 4; nf++) {
            const int qg0  = qt * 64 + wn * 32 + nf * 8 + 2 * tg;
            const int qloc = wn * 32 + nf * 8 + 2 * tg;
            float d0, d1, d2, d3;
            {
                float x = s[nf][0] * (1.f / 4096.f);
                d0 = (kg0 <= qg0)     ? x * (1.f + x * (0.5f + x * (1.f / 6.f))) : -1.f;
                x = s[nf][1] * (1.f / 4096.f);
                d1 = (kg0 <= qg0 + 1) ? x * (1.f + x * (0.5f + x * (1.f / 6.f))) : -1.f;
                x = s[nf][2] * (1.f / 4096.f);
                d2 = (kg0 + 8 <= qg0)     ? x * (1.f + x * (0.5f + x * (1.f / 6.f))) : -1.f;
                x = s[nf][3] * (1.f / 4096.f);
                d3 = (kg0 + 8 <= qg0 + 1) ? x * (1.f + x * (0.5f + x * (1.f / 6.f))) : -1.f;
            }
            dsum[nf][0] += d0 + d2;
            dsum[nf][1] += d1 + d3;
            Dh[qloc * QP + kloc]           = tf32f(d0);
            Dh[(qloc + 1) * QP + kloc]     = tf32f(d1);
            Dh[qloc * QP + kloc + 8]       = tf32f(d2);
            Dh[(qloc + 1) * QP + kloc + 8] = tf32f(d3);
        }
        __syncthreads();

        const float* Da = Dh + (wm * 16 + grp) * QP;
        const bool diag = (kt == qt);
#pragma unroll
        for (int ks = 0; ks < 8; ks++) {
            const int kb = ks * 8;
            uint32_t a[4];
            a[0] = __float_as_uint(Da[kb + tg]);
            a[1] = __float_as_uint(Da[8 * QP + kb + tg]);
            a[2] = __float_as_uint(Da[kb + tg + 4]);
            a[3] = __float_as_uint(Da[8 * QP + kb + tg + 4]);
#pragma unroll
            for (int nf = 0; nf < 4; nf++) {
                const float* Vb = Vh + (kb + tg) * VP + wn * 32 + nf * 8 + grp;
                uint32_t bh2[2] = { __float_as_uint(Vb[0]), __float_as_uint(Vb[4 * VP]) };
                MMA_TF32(acc[nf], a, bh2);
            }
            if (diag) {
#pragma unroll
                for (int nf = 0; nf < 4; nf++) {
                    const float* Vb = Vl + (kb + tg) * VP + wn * 32 + nf * 8 + grp;
                    uint32_t bl2[2] = { __float_as_uint(Vb[0]), __float_as_uint(Vb[4 * VP]) };
                    MMA_TF32(acc[nf], a, bl2);
                }
            }
        }

#pragma unroll
        for (int nf = 0; nf < 4; nf++) {
            const float c0 = Csum[wn * 32 + nf * 8 + 2 * tg];
            const float c1 = Csum[wn * 32 + nf * 8 + 2 * tg + 1];
            acc[nf][0] += c0; acc[nf][1] += c1;
            acc[nf][2] += c0; acc[nf][3] += c1;
        }
    }

#pragma unroll
    for (int off = 16; off >= 4; off >>= 1)
#pragma unroll
        for (int nf = 0; nf < 4; nf++) {
            dsum[nf][0] += __shfl_xor_sync(0xffffffffu, dsum[nf][0], off);
            dsum[nf][1] += __shfl_xor_sync(0xffffffffu, dsum[nf][1], off);
        }
    if (grp == 0) {
#pragma unroll
        for (int nf = 0; nf < 4; nf++) {
            Lred[wm * 64 + wn * 32 + nf * 8 + 2 * tg]     = dsum[nf][0];
            Lred[wm * 64 + wn * 32 + nf * 8 + 2 * tg + 1] = dsum[nf][1];
        }
    }
    __syncthreads();

    const float nk = 64.0f * (float)(qt + 1);
    const int r0 = wm * 16 + grp, r1 = r0 + 8;
    float l0 = nk, l1 = nk;
#pragma unroll
    for (int w = 0; w < 4; w++) {
        l0 += Lred[w * 64 + r0];
        l1 += Lred[w * 64 + r1];
    }
    const float inv0 = 1.0f / l0, inv1 = 1.0f / l1;
#pragma unroll
    for (int nf = 0; nf < 4; nf++) {
        const int dcol = wn * 32 + nf * 8 + 2 * tg;
        float2 w0, w1;
        w0.x = acc[nf][0] * inv0; w0.y = acc[nf][1] * inv0;
        w1.x = acc[nf][2] * inv1; w1.y = acc[nf][3] * inv1;
        *(float2*)&ctx[base + (size_t)(qt * 64 + r0) * D_ + dcol] = w0;
        *(float2*)&ctx[base + (size_t)(qt * 64 + r1) * D_ + dcol] = w1;
    }
}

// ---------------------------------------------------------------------------
// Launch
// ---------------------------------------------------------------------------
extern "C" void kernel_launch(void* const* d_in, const int* in_sizes, int n_in,
                              void* d_out, int out_size) {
    const float* x  = (const float*)d_in[0];
    const float* Wq = (const float*)d_in[1];
    const float* Wk = (const float*)d_in[2];
    const float* Wv = (const float*)d_in[3];
    const float* Wo = (const float*)d_in[4];
    const float* bo = (const float*)d_in[5];
    float* out = (float*)d_out;

    float *pq, *pk, *pv, *pc;
    cudaGetSymbolAddress((void**)&pq, g_q);
    cudaGetSymbolAddress((void**)&pk, g_k);
    cudaGetSymbolAddress((void**)&pv, g_v);
    cudaGetSymbolAddress((void**)&pc, g_c);
    __nv_bfloat16 *pxh, *pxl, *pch, *pcl, *pwh, *pwl;
    cudaGetSymbolAddress((void**)&pxh, g_xh);
    cudaGetSymbolAddress((void**)&pxl, g_xl);
    cudaGetSymbolAddress((void**)&pch, g_ch);
    cudaGetSymbolAddress((void**)&pcl, g_cl);
    cudaGetSymbolAddress((void**)&pwh, g_wh);
    cudaGetSymbolAddress((void**)&pwl, g_wl);

    const int gemm_smem = 2 * STAGE * (int)sizeof(__nv_bfloat16);  // 81920 B
    cudaFuncSetAttribute(gemm_bf16x3, cudaFuncAttributeMaxDynamicSharedMemorySize,
                         gemm_smem);
    const int attn_smem = (3 * 64 * QP + 2 * 64 * VP + 16 * 64 + 64 + 4 * 64) *
                          (int)sizeof(float);                       // 94464 B
    cudaFuncSetAttribute(attn_mma, cudaFuncAttributeMaxDynamicSharedMemorySize,
                         attn_smem);

    // Prep: split x, transpose+split the 4 weights
    fsplit<<<M_ * D_ / 4 / 256, 256>>>(x, pxh, pxl);
    wsplit_t<<<dim3(32, 32, 4), 256>>>(Wq, Wk, Wv, Wo, pwh, pwl);

    dim3 ggemm(D_ / 128, M_ / 128);   // (8, 64)
    gemm_bf16x3<<<ggemm, 256, gemm_smem>>>(pxh, pxl, pwh + 0 * D_ * D_,
                                           pwl + 0 * D_ * D_, nullptr, pq);
    gemm_bf16x3<<<ggemm, 256, gemm_smem>>>(pxh, pxl, pwh + 1 * D_ * D_,
                                           pwl + 1 * D_ * D_, nullptr, pk);
    gemm_bf16x3<<<ggemm, 256, gemm_smem>>>(pxh, pxl, pwh + 2 * D_ * D_,
                                           pwl + 2 * D_ * D_, nullptr, pv);

    dim3 gattn(S_ / 64, H_, B_);      // (32, 16, 4)
    attn_mma<<<gattn, 256, attn_smem>>>(pq, pk, pv, pc);

    fsplit<<<M_ * D_ / 4 / 256, 256>>>(pc, pch, pcl);
    gemm_bf16x3<<<ggemm, 256, gemm_smem>>>(pch, pcl, pwh + 3 * D_ * D_,
                                           pwl + 3 * D_ * D_, bo, out);
}

// round 10
// speedup vs baseline: 2.6577x; 1.0599x over previous
#include <cuda_runtime.h>
#include <cuda_bf16.h>
#include <cstdint>

// Problem constants
#define B_  4
#define S_  2048
#define D_  1024
#define H_  16
#define HD_ 64
#define M_  (B_ * S_)   // 8192 rows

// Scratch (allocation-free rule: __device__ globals)
__device__ float g_q[M_ * D_];
__device__ float g_k[M_ * D_];
__device__ float g_v[M_ * D_];
__device__ float g_c[M_ * D_];
// bf16x3 pre-split operands
__device__ __nv_bfloat16 g_xh[M_ * D_], g_xl[M_ * D_];    // x hi/lo [M][K]
__device__ __nv_bfloat16 g_ch[M_ * D_], g_cl[M_ * D_];    // ctx hi/lo [M][K]
__device__ __nv_bfloat16 g_wh[4 * D_ * D_];               // W^T hi [N][K] x4
__device__ __nv_bfloat16 g_wl[4 * D_ * D_];               // W^T lo

// ---------------------------------------------------------------------------
// cp.async helpers
// ---------------------------------------------------------------------------
__device__ __forceinline__ void cp_async16(void* smem, const void* gmem) {
    uint32_t s = (uint32_t)__cvta_generic_to_shared(smem);
    asm volatile("cp.async.cg.shared.global [%0], [%1], 16;\n" :: "r"(s), "l"(gmem));
}
__device__ __forceinline__ void cp_commit() {
    asm volatile("cp.async.commit_group;\n");
}
template <int N>
__device__ __forceinline__ void cp_wait() {
    asm volatile("cp.async.wait_group %0;\n" :: "n"(N));
}

#define MMA_TF32(c, a, b)                                                     \
    asm volatile(                                                             \
        "mma.sync.aligned.m16n8k8.row.col.f32.tf32.tf32.f32 "                 \
        "{%0,%1,%2,%3},{%4,%5,%6,%7},{%8,%9},{%0,%1,%2,%3};"                  \
        : "+f"(c[0]), "+f"(c[1]), "+f"(c[2]), "+f"(c[3])                      \
        : "r"(a[0]), "r"(a[1]), "r"(a[2]), "r"(a[3]), "r"(b[0]), "r"(b[1]))

#define MMA_BF16(c, a, b)                                                     \
    asm volatile(                                                             \
        "mma.sync.aligned.m16n8k16.row.col.f32.bf16.bf16.f32 "                \
        "{%0,%1,%2,%3},{%4,%5,%6,%7},{%8,%9},{%0,%1,%2,%3};"                  \
        : "+f"(c[0]), "+f"(c[1]), "+f"(c[2]), "+f"(c[3])                      \
        : "r"(a[0]), "r"(a[1]), "r"(a[2]), "r"(a[3]), "r"(b[0]), "r"(b[1]))

// 3xTF32 split (attention V path)
__device__ __forceinline__ void split_tf32(float x, uint32_t& hi, uint32_t& lo) {
    asm("cvt.rna.tf32.f32 %0, %1;" : "=r"(hi) : "f"(x));
    float r = x - __uint_as_float(hi);
    asm("cvt.rna.tf32.f32 %0, %1;" : "=r"(lo) : "f"(r));
}
__device__ __forceinline__ float tf32f(float x) {
    uint32_t u;
    asm("cvt.rna.tf32.f32 %0, %1;" : "=r"(u) : "f"(x));
    return __uint_as_float(u);
}
__device__ __forceinline__ void split_bf16(float x, __nv_bfloat16& h, __nv_bfloat16& l) {
    h = __float2bfloat16_rn(x);
    l = __float2bfloat16_rn(x - __bfloat162float(h));
}

// ---------------------------------------------------------------------------
// Prep: elementwise fp32 -> bf16 hi/lo split (for x and ctx, [M][K] layout).
// ---------------------------------------------------------------------------
__global__ __launch_bounds__(256) void fsplit(const float* __restrict__ src,
                                              __nv_bfloat16* __restrict__ h,
                                              __nv_bfloat16* __restrict__ l) {
    const int i = blockIdx.x * 256 + threadIdx.x;   // one float4 per thread
    float4 v = ((const float4*)src)[i];
    __nv_bfloat16 h0, h1, h2, h3, l0, l1, l2, l3;
    split_bf16(v.x, h0, l0);
    split_bf16(v.y, h1, l1);
    split_bf16(v.z, h2, l2);
    split_bf16(v.w, h3, l3);
    __nv_bfloat162* hp = (__nv_bfloat162*)h;
    __nv_bfloat162* lp = (__nv_bfloat162*)l;
    hp[2 * i]     = __nv_bfloat162{h0, h1};
    hp[2 * i + 1] = __nv_bfloat162{h2, h3};
    lp[2 * i]     = __nv_bfloat162{l0, l1};
    lp[2 * i + 1] = __nv_bfloat162{l2, l3};
}

// ---------------------------------------------------------------------------
// Prep: W [K][N] -> W^T hi/lo bf16 [N][K], 32x32 smem tile transpose.
// blockIdx.z selects which of the 4 weights.
// ---------------------------------------------------------------------------
__global__ __launch_bounds__(256) void wsplit_t(const float* __restrict__ W0,
                                                const float* __restrict__ W1,
                                                const float* __restrict__ W2,
                                                const float* __restrict__ W3,
                                                __nv_bfloat16* __restrict__ dh,
                                                __nv_bfloat16* __restrict__ dl) {
    __shared__ float t[32][33];
    const float* W = (blockIdx.z == 0) ? W0 : (blockIdx.z == 1) ? W1
                   : (blockIdx.z == 2) ? W2 : W3;
    dh += (size_t)blockIdx.z * D_ * D_;
    dl += (size_t)blockIdx.z * D_ * D_;
    const int kx = blockIdx.x * 32, ny = blockIdx.y * 32;
    const int tx = threadIdx.x & 31, ty = threadIdx.x >> 5;   // 32 x 8
#pragma unroll
    for (int r = 0; r < 4; r++) {
        const int row = ty + r * 8;
        t[row][tx] = W[(size_t)(kx + row) * D_ + ny + tx];    // t[k_loc][n_loc]
    }
    __syncthreads();
#pragma unroll
    for (int r = 0; r < 4; r++) {
        const int row = ty + r * 8;                            // n_loc
        __nv_bfloat16 h, l;
        split_bf16(t[tx][row], h, l);
        dh[(size_t)(ny + row) * D_ + kx + tx] = h;
        dl[(size_t)(ny + row) * D_ + kx + tx] = l;
    }
}

// ---------------------------------------------------------------------------
// bf16x3 tensor-core GEMM, fused over up to 3 weight matrices.
// C_sel[M,N] = A[M,K] @ W_sel[K,N] (+bias), sel = blockIdx.x >> 3.
// 128x128 CTA tile, K-chunk 32, 8 warps (4M x 2N), m16n8k16 fragments,
// cp.async double-buffered. __launch_bounds__(256,2): 2 CTAs/SM co-residency
// (64K regs + 160KB smem per SM) so one CTA's MMAs fill the other's
// sync/load bubbles. Smem pitch 40 bf16 -> conflict-free fragment LDS.
// ---------------------------------------------------------------------------
#define GP 40                     // smem pitch in bf16
#define PLANE (128 * GP)          // 5120 bf16 per plane
#define STAGE (4 * PLANE)         // Ah, Al, Bh, Bl

__global__ __launch_bounds__(256, 2) void gemm_bf16x3(
    const __nv_bfloat16* __restrict__ Ah, const __nv_bfloat16* __restrict__ Al,
    const __nv_bfloat16* __restrict__ BhBase,
    const __nv_bfloat16* __restrict__ BlBase,
    const float* __restrict__ bias,
    float* __restrict__ C0, float* __restrict__ C1, float* __restrict__ C2) {
    const int K = D_, N = D_;
    extern __shared__ __nv_bfloat16 smb[];

    const int sel = blockIdx.x >> 3;
    const int bx = blockIdx.x & 7;
    const int by = blockIdx.y;
    const __nv_bfloat16* Bh = BhBase + (size_t)sel * D_ * D_;
    const __nv_bfloat16* Bl = BlBase + (size_t)sel * D_ * D_;
    float* C = (sel == 0) ? C0 : (sel == 1) ? C1 : C2;

    const int tid = threadIdx.x;
    const int wid = tid >> 5, lane = tid & 31;
    const int grp = lane >> 2, tg = lane & 3;
    const int wm = wid & 3;       // 32 M-rows per warp group
    const int wn = wid >> 2;      // 64 N-cols per warp group

    float acc[2][8][4] = {};

    const __nv_bfloat16* srcA_h = Ah + (size_t)(by * 128) * K;
    const __nv_bfloat16* srcA_l = Al + (size_t)(by * 128) * K;
    const __nv_bfloat16* srcB_h = Bh + (size_t)(bx * 128) * K;
    const __nv_bfloat16* srcB_l = Bl + (size_t)(bx * 128) * K;

    auto load_stage = [&](int stage, int k0) {
        __nv_bfloat16* s = smb + stage * STAGE;
        const __nv_bfloat16* srcs[4] = {srcA_h + k0, srcA_l + k0,
                                        srcB_h + k0, srcB_l + k0};
#pragma unroll
        for (int plane = 0; plane < 4; plane++) {
#pragma unroll
            for (int half = 0; half < 2; half++) {
                const int idx = tid + half * 256;      // 512 chunks of 16B
                const int row = idx >> 2, c = idx & 3; // 4 chunks per 64B row
                cp_async16(s + plane * PLANE + row * GP + c * 8,
                           srcs[plane] + (size_t)row * K + c * 8);
            }
        }
    };

    auto compute = [&](int stage) {
        const uint32_t* b32 = (const uint32_t*)(smb + stage * STAGE);
        const uint32_t* pAh = b32 + (wm * 32 + grp) * 20;
        const uint32_t* pAl = pAh + PLANE / 2;
        const uint32_t* pBh = b32 + 2 * (PLANE / 2) + (wn * 64 + grp) * 20;
        const uint32_t* pBl = pBh + PLANE / 2;
#pragma unroll
        for (int ks = 0; ks < 2; ks++) {
            const int k32 = ks * 8;                    // u32 offset (16 bf16)
            uint32_t ah[2][4], al[2][4];
#pragma unroll
            for (int mf = 0; mf < 2; mf++) {
                const uint32_t* p = pAh + mf * 16 * 20 + k32;
                ah[mf][0] = p[tg];
                ah[mf][1] = p[160 + tg];
                ah[mf][2] = p[tg + 4];
                ah[mf][3] = p[160 + tg + 4];
                const uint32_t* q2 = pAl + mf * 16 * 20 + k32;
                al[mf][0] = q2[tg];
                al[mf][1] = q2[160 + tg];
                al[mf][2] = q2[tg + 4];
                al[mf][3] = q2[160 + tg + 4];
            }
            uint32_t bh[8][2], bl[8][2];
#pragma unroll
            for (int nf = 0; nf < 8; nf++) {
                const uint32_t* p = pBh + nf * 160 + k32;
                bh[nf][0] = p[tg];
                bh[nf][1] = p[tg + 4];
                const uint32_t* q2 = pBl + nf * 160 + k32;
                bl[nf][0] = q2[tg];
                bl[nf][1] = q2[tg + 4];
            }
#pragma unroll
            for (int mf = 0; mf < 2; mf++)
#pragma unroll
                for (int nf = 0; nf < 8; nf++) {
                    MMA_BF16(acc[mf][nf], ah[mf], bh[nf]);
                    MMA_BF16(acc[mf][nf], al[mf], bh[nf]);
                    MMA_BF16(acc[mf][nf], ah[mf], bl[nf]);
                }
        }
    };

    load_stage(0, 0);
    cp_commit();

    const int KT = K / 32;
    int stage = 0;
    for (int kt = 0; kt < KT; kt++) {
        if (kt + 1 < KT) {
            load_stage(stage ^ 1, (kt + 1) * 32);
            cp_commit();
            cp_wait<1>();
        } else {
            cp_wait<0>();
        }
        __syncthreads();
        compute(stage);
        stage ^= 1;
        __syncthreads();
    }

#pragma unroll
    for (int mf = 0; mf < 2; mf++) {
#pragma unroll
        for (int nf = 0; nf < 8; nf++) {
            const int row = by * 128 + wm * 32 + mf * 16 + grp;
            const int col = bx * 128 + wn * 64 + nf * 8 + 2 * tg;
            float b0 = 0.f, b1 = 0.f;
            if (bias) { b0 = bias[col]; b1 = bias[col + 1]; }
            C[(size_t)row * N + col]           = acc[mf][nf][0] + b0;
            C[(size_t)row * N + col + 1]       = acc[mf][nf][1] + b1;
            C[(size_t)(row + 8) * N + col]     = acc[mf][nf][2] + b0;
            C[(size_t)(row + 8) * N + col + 1] = acc[mf][nf][3] + b1;
        }
    }
}

// ---------------------------------------------------------------------------
// Tensor-core causal attention via the P = 1 + D decomposition (unchanged
// from the passing round-8/9 kernel).
// ---------------------------------------------------------------------------
#define QP 68
#define VP 72

__global__ __launch_bounds__(256) void attn_mma(const float* __restrict__ q,
                                                const float* __restrict__ k,
                                                const float* __restrict__ v,
                                                float* __restrict__ ctx) {
    extern __shared__ float sm[];
    float* Qs    = sm;                 // [64][QP]  tf32 Q[qtok][d]   (B operand)
    float* Ks    = Qs + 64 * QP;       // [64][QP]  tf32 K[ktok][d]   (A operand)
    float* Dh    = Ks + 64 * QP;       // [64][QP]  tf32 D[qtok][ktok](A operand)
    float* Vh    = Dh + 64 * QP;       // [64][VP]  tf32 V hi [ktok][d] (B)
    float* Vl    = Vh + 64 * VP;       // [64][VP]  tf32 V lo
    float* Cpart = Vl + 64 * VP;       // [16][64]  colsum partials
    float* Csum  = Cpart + 16 * 64;    // [64]
    float* Lred  = Csum + 64;          // [4][64]   dsum partials per k-warp

    const int tid = threadIdx.x;
    const int wid = tid >> 5, lane = tid & 31;
    const int grp = lane >> 2, tg = lane & 3;
    const int wm = wid & 3;
    const int wn = wid >> 2;
    const int qt = blockIdx.x, h = blockIdx.y, b = blockIdx.z;

    const size_t base = ((size_t)b * S_) * D_ + (size_t)h * HD_;

    for (int t = tid; t < 64 * 16; t += 256) {
        const int row = t >> 4, dc = (t & 15) * 4;
        float4 vq = *(const float4*)&q[base + (size_t)(qt * 64 + row) * D_ + dc];
        float4 qc;
        qc.x = tf32f(vq.x); qc.y = tf32f(vq.y);
        qc.z = tf32f(vq.z); qc.w = tf32f(vq.w);
        *(float4*)&Qs[row * QP + dc] = qc;
    }

    float acc[4][4]  = {};
    float dsum[4][2] = {};

    for (int kt = 0; kt <= qt; kt++) {
        __syncthreads();

        float4 cs = {0.f, 0.f, 0.f, 0.f};
#pragma unroll
        for (int it = 0; it < 4; it++) {
            const int idx = tid + it * 256;
            const int row = idx >> 4, dc = (idx & 15) * 4;
            const size_t goff = base + (size_t)(kt * 64 + row) * D_ + dc;
            float4 kv = *(const float4*)&k[goff];
            float4 kc;
            kc.x = tf32f(kv.x); kc.y = tf32f(kv.y);
            kc.z = tf32f(kv.z); kc.w = tf32f(kv.w);
            *(float4*)&Ks[row * QP + dc] = kc;
            float4 vv = *(const float4*)&v[goff];
            cs.x += vv.x; cs.y += vv.y; cs.z += vv.z; cs.w += vv.w;
            float4 vhi, vlo;
            uint32_t hu, lu;
            split_tf32(vv.x, hu, lu); vhi.x = __uint_as_float(hu); vlo.x = __uint_as_float(lu);
            split_tf32(vv.y, hu, lu); vhi.y = __uint_as_float(hu); vlo.y = __uint_as_float(lu);
            split_tf32(vv.z, hu, lu); vhi.z = __uint_as_float(hu); vlo.z = __uint_as_float(lu);
            split_tf32(vv.w, hu, lu); vhi.w = __uint_as_float(hu); vlo.w = __uint_as_float(lu);
            *(float4*)&Vh[row * VP + dc] = vhi;
            *(float4*)&Vl[row * VP + dc] = vlo;
        }
        *(float4*)&Cpart[(tid >> 4) * 64 + (tid & 15) * 4] = cs;
        __syncthreads();

        if (tid < 64) {
            float s = 0.f;
#pragma unroll
            for (int p2 = 0; p2 < 16; p2++) s += Cpart[p2 * 64 + tid];
            Csum[tid] = s;
        }

        float s[4][4] = {};
        const float* Ka = Ks + (wm * 16 + grp) * QP;
#pragma unroll
        for (int ks = 0; ks < 8; ks++) {
            const int kb = ks * 8;
            uint32_t a[4];
            a[0] = __float_as_uint(Ka[kb + tg]);
            a[1] = __float_as_uint(Ka[8 * QP + kb + tg]);
            a[2] = __float_as_uint(Ka[kb + tg + 4]);
            a[3] = __float_as_uint(Ka[8 * QP + kb + tg + 4]);
#pragma unroll
            for (int nf = 0; nf < 4; nf++) {
                const float* Qb = Qs + (wn * 32 + nf * 8 + grp) * QP + kb + tg;
                uint32_t bb[2] = { __float_as_uint(Qb[0]), __float_as_uint(Qb[4]) };
                MMA_TF32(s[nf], a, bb);
            }
        }

        const int kg0 = kt * 64 + wm * 16 + grp;
        const int kloc = wm * 16 + grp;
#pragma unroll
        for (int nf = 0; nf < 4; nf++) {
            const int qg0  = qt * 64 + wn * 32 + nf * 8 + 2 * tg;
            const int qloc = wn * 32 + nf * 8 + 2 * tg;
            float d0, d1, d2, d3;
            {
                float x = s[nf][0] * (1.f / 4096.f);
                d0 = (kg0 <= qg0)     ? x * (1.f + x * (0.5f + x * (1.f / 6.f))) : -1.f;
                x = s[nf][1] * (1.f / 4096.f);
                d1 = (kg0 <= qg0 + 1) ? x * (1.f + x * (0.5f + x * (1.f / 6.f))) : -1.f;
                x = s[nf][2] * (1.f / 4096.f);
                d2 = (kg0 + 8 <= qg0)     ? x * (1.f + x * (0.5f + x * (1.f / 6.f))) : -1.f;
                x = s[nf][3] * (1.f / 4096.f);
                d3 = (kg0 + 8 <= qg0 + 1) ? x * (1.f + x * (0.5f + x * (1.f / 6.f))) : -1.f;
            }
            dsum[nf][0] += d0 + d2;
            dsum[nf][1] += d1 + d3;
            Dh[qloc * QP + kloc]           = tf32f(d0);
            Dh[(qloc + 1) * QP + kloc]     = tf32f(d1);
            Dh[qloc * QP + kloc + 8]       = tf32f(d2);
            Dh[(qloc + 1) * QP + kloc + 8] = tf32f(d3);
        }
        __syncthreads();

        const float* Da = Dh + (wm * 16 + grp) * QP;
        const bool diag = (kt == qt);
#pragma unroll
        for (int ks = 0; ks < 8; ks++) {
            const int kb = ks * 8;
            uint32_t a[4];
            a[0] = __float_as_uint(Da[kb + tg]);
            a[1] = __float_as_uint(Da[8 * QP + kb + tg]);
            a[2] = __float_as_uint(Da[kb + tg + 4]);
            a[3] = __float_as_uint(Da[8 * QP + kb + tg + 4]);
#pragma unroll
            for (int nf = 0; nf < 4; nf++) {
                const float* Vb = Vh + (kb + tg) * VP + wn * 32 + nf * 8 + grp;
                uint32_t bh2[2] = { __float_as_uint(Vb[0]), __float_as_uint(Vb[4 * VP]) };
                MMA_TF32(acc[nf], a, bh2);
            }
            if (diag) {
#pragma unroll
                for (int nf = 0; nf < 4; nf++) {
                    const float* Vb = Vl + (kb + tg) * VP + wn * 32 + nf * 8 + grp;
                    uint32_t bl2[2] = { __float_as_uint(Vb[0]), __float_as_uint(Vb[4 * VP]) };
                    MMA_TF32(acc[nf], a, bl2);
                }
            }
        }

#pragma unroll
        for (int nf = 0; nf < 4; nf++) {
            const float c0 = Csum[wn * 32 + nf * 8 + 2 * tg];
            const float c1 = Csum[wn * 32 + nf * 8 + 2 * tg + 1];
            acc[nf][0] += c0; acc[nf][1] += c1;
            acc[nf][2] += c0; acc[nf][3] += c1;
        }
    }

#pragma unroll
    for (int off = 16; off >= 4; off >>= 1)
#pragma unroll
        for (int nf = 0; nf < 4; nf++) {
            dsum[nf][0] += __shfl_xor_sync(0xffffffffu, dsum[nf][0], off);
            dsum[nf][1] += __shfl_xor_sync(0xffffffffu, dsum[nf][1], off);
        }
    if (grp == 0) {
#pragma unroll
        for (int nf = 0; nf < 4; nf++) {
            Lred[wm * 64 + wn * 32 + nf * 8 + 2 * tg]     = dsum[nf][0];
            Lred[wm * 64 + wn * 32 + nf * 8 + 2 * tg + 1] = dsum[nf][1];
        }
    }
    __syncthreads();

    const float nk = 64.0f * (float)(qt + 1);
    const int r0 = wm * 16 + grp, r1 = r0 + 8;
    float l0 = nk, l1 = nk;
#pragma unroll
    for (int w = 0; w < 4; w++) {
        l0 += Lred[w * 64 + r0];
        l1 += Lred[w * 64 + r1];
    }
    const float inv0 = 1.0f / l0, inv1 = 1.0f / l1;
#pragma unroll
    for (int nf = 0; nf < 4; nf++) {
        const int dcol = wn * 32 + nf * 8 + 2 * tg;
        float2 w0, w1;
        w0.x = acc[nf][0] * inv0; w0.y = acc[nf][1] * inv0;
        w1.x = acc[nf][2] * inv1; w1.y = acc[nf][3] * inv1;
        *(float2*)&ctx[base + (size_t)(qt * 64 + r0) * D_ + dcol] = w0;
        *(float2*)&ctx[base + (size_t)(qt * 64 + r1) * D_ + dcol] = w1;
    }
}

// ---------------------------------------------------------------------------
// Launch
// ---------------------------------------------------------------------------
extern "C" void kernel_launch(void* const* d_in, const int* in_sizes, int n_in,
                              void* d_out, int out_size) {
    const float* x  = (const float*)d_in[0];
    const float* Wq = (const float*)d_in[1];
    const float* Wk = (const float*)d_in[2];
    const float* Wv = (const float*)d_in[3];
    const float* Wo = (const float*)d_in[4];
    const float* bo = (const float*)d_in[5];
    float* out = (float*)d_out;

    float *pq, *pk, *pv, *pc;
    cudaGetSymbolAddress((void**)&pq, g_q);
    cudaGetSymbolAddress((void**)&pk, g_k);
    cudaGetSymbolAddress((void**)&pv, g_v);
    cudaGetSymbolAddress((void**)&pc, g_c);
    __nv_bfloat16 *pxh, *pxl, *pch, *pcl, *pwh, *pwl;
    cudaGetSymbolAddress((void**)&pxh, g_xh);
    cudaGetSymbolAddress((void**)&pxl, g_xl);
    cudaGetSymbolAddress((void**)&pch, g_ch);
    cudaGetSymbolAddress((void**)&pcl, g_cl);
    cudaGetSymbolAddress((void**)&pwh, g_wh);
    cudaGetSymbolAddress((void**)&pwl, g_wl);

    const int gemm_smem = 2 * STAGE * (int)sizeof(__nv_bfloat16);  // 81920 B
    cudaFuncSetAttribute(gemm_bf16x3, cudaFuncAttributeMaxDynamicSharedMemorySize,
                         gemm_smem);
    const int attn_smem = (3 * 64 * QP + 2 * 64 * VP + 16 * 64 + 64 + 4 * 64) *
                          (int)sizeof(float);                       // 94464 B
    cudaFuncSetAttribute(attn_mma, cudaFuncAttributeMaxDynamicSharedMemorySize,
                         attn_smem);

    // Prep: split x, transpose+split the 4 weights
    fsplit<<<M_ * D_ / 4 / 256, 256>>>(x, pxh, pxl);
    wsplit_t<<<dim3(32, 32, 4), 256>>>(Wq, Wk, Wv, Wo, pwh, pwl);

    // Fused Q/K/V projection: sel = blockIdx.x >> 3 picks weight + output
    dim3 gqkv(3 * D_ / 128, M_ / 128);   // (24, 64)
    gemm_bf16x3<<<gqkv, 256, gemm_smem>>>(pxh, pxl, pwh, pwl, nullptr,
                                          pq, pk, pv);

    dim3 gattn(S_ / 64, H_, B_);         // (32, 16, 4)
    attn_mma<<<gattn, 256, attn_smem>>>(pq, pk, pv, pc);

    fsplit<<<M_ * D_ / 4 / 256, 256>>>(pc, pch, pcl);
    dim3 gout(D_ / 128, M_ / 128);       // (8, 64)
    gemm_bf16x3<<<gout, 256, gemm_smem>>>(pch, pcl, pwh + 3 * (size_t)D_ * D_,
                                          pwl + 3 * (size_t)D_ * D_, bo,
                                          out, out, out);
}

// round 11
// speedup vs baseline: 2.7891x; 1.0494x over previous
#include <cuda_runtime.h>
#include <cuda_bf16.h>
#include <cstdint>

// Problem constants
#define B_  4
#define S_  2048
#define D_  1024
#define H_  16
#define HD_ 64
#define M_  (B_ * S_)   // 8192 rows

// Scratch (allocation-free rule: __device__ globals)
__device__ float g_q[M_ * D_];      // tf32-rounded Q
__device__ float g_k[M_ * D_];      // tf32-rounded K
__device__ float g_v[M_ * D_];      // V hi (tf32 part)
__device__ float g_vl[M_ * D_];     // V lo (residual)
__device__ float g_c[M_ * D_];      // attention output ctx
__device__ float g_cs[B_ * H_ * 32 * 64];   // per-(b,h) prefix tile colsums of V
// bf16x3 pre-split operands
__device__ __nv_bfloat16 g_xh[M_ * D_], g_xl[M_ * D_];    // x hi/lo [M][K]
__device__ __nv_bfloat16 g_ch[M_ * D_], g_cl[M_ * D_];    // ctx hi/lo [M][K]
__device__ __nv_bfloat16 g_wh[4 * D_ * D_];               // W^T hi [N][K] x4
__device__ __nv_bfloat16 g_wl[4 * D_ * D_];               // W^T lo

// ---------------------------------------------------------------------------
// cp.async helpers
// ---------------------------------------------------------------------------
__device__ __forceinline__ void cp_async16(void* smem, const void* gmem) {
    uint32_t s = (uint32_t)__cvta_generic_to_shared(smem);
    asm volatile("cp.async.cg.shared.global [%0], [%1], 16;\n" :: "r"(s), "l"(gmem));
}
__device__ __forceinline__ void cp_commit() {
    asm volatile("cp.async.commit_group;\n");
}
template <int N>
__device__ __forceinline__ void cp_wait() {
    asm volatile("cp.async.wait_group %0;\n" :: "n"(N));
}

#define MMA_TF32(c, a, b)                                                     \
    asm volatile(                                                             \
        "mma.sync.aligned.m16n8k8.row.col.f32.tf32.tf32.f32 "                 \
        "{%0,%1,%2,%3},{%4,%5,%6,%7},{%8,%9},{%0,%1,%2,%3};"                  \
        : "+f"(c[0]), "+f"(c[1]), "+f"(c[2]), "+f"(c[3])                      \
        : "r"(a[0]), "r"(a[1]), "r"(a[2]), "r"(a[3]), "r"(b[0]), "r"(b[1]))

#define MMA_BF16(c, a, b)                                                     \
    asm volatile(                                                             \
        "mma.sync.aligned.m16n8k16.row.col.f32.bf16.bf16.f32 "                \
        "{%0,%1,%2,%3},{%4,%5,%6,%7},{%8,%9},{%0,%1,%2,%3};"                  \
        : "+f"(c[0]), "+f"(c[1]), "+f"(c[2]), "+f"(c[3])                      \
        : "r"(a[0]), "r"(a[1]), "r"(a[2]), "r"(a[3]), "r"(b[0]), "r"(b[1]))

__device__ __forceinline__ void split_tf32(float x, uint32_t& hi, uint32_t& lo) {
    asm("cvt.rna.tf32.f32 %0, %1;" : "=r"(hi) : "f"(x));
    float r = x - __uint_as_float(hi);
    asm("cvt.rna.tf32.f32 %0, %1;" : "=r"(lo) : "f"(r));
}
__device__ __forceinline__ float tf32f(float x) {
    uint32_t u;
    asm("cvt.rna.tf32.f32 %0, %1;" : "=r"(u) : "f"(x));
    return __uint_as_float(u);
}
__device__ __forceinline__ void split_bf16(float x, __nv_bfloat16& h, __nv_bfloat16& l) {
    h = __float2bfloat16_rn(x);
    l = __float2bfloat16_rn(x - __bfloat162float(h));
}

// ---------------------------------------------------------------------------
// Prep: elementwise fp32 -> bf16 hi/lo split (for x and ctx).
// ---------------------------------------------------------------------------
__global__ __launch_bounds__(256) void fsplit(const float* __restrict__ src,
                                              __nv_bfloat16* __restrict__ h,
                                              __nv_bfloat16* __restrict__ l) {
    const int i = blockIdx.x * 256 + threadIdx.x;   // one float4 per thread
    float4 v = ((const float4*)src)[i];
    __nv_bfloat16 h0, h1, h2, h3, l0, l1, l2, l3;
    split_bf16(v.x, h0, l0);
    split_bf16(v.y, h1, l1);
    split_bf16(v.z, h2, l2);
    split_bf16(v.w, h3, l3);
    __nv_bfloat162* hp = (__nv_bfloat162*)h;
    __nv_bfloat162* lp = (__nv_bfloat162*)l;
    hp[2 * i]     = __nv_bfloat162{h0, h1};
    hp[2 * i + 1] = __nv_bfloat162{h2, h3};
    lp[2 * i]     = __nv_bfloat162{l0, l1};
    lp[2 * i + 1] = __nv_bfloat162{l2, l3};
}

// ---------------------------------------------------------------------------
// Prep: W [K][N] -> W^T hi/lo bf16 [N][K], 32x32 smem tile transpose.
// ---------------------------------------------------------------------------
__global__ __launch_bounds__(256) void wsplit_t(const float* __restrict__ W0,
                                                const float* __restrict__ W1,
                                                const float* __restrict__ W2,
                                                const float* __restrict__ W3,
                                                __nv_bfloat16* __restrict__ dh,
                                                __nv_bfloat16* __restrict__ dl) {
    __shared__ float t[32][33];
    const float* W = (blockIdx.z == 0) ? W0 : (blockIdx.z == 1) ? W1
                   : (blockIdx.z == 2) ? W2 : W3;
    dh += (size_t)blockIdx.z * D_ * D_;
    dl += (size_t)blockIdx.z * D_ * D_;
    const int kx = blockIdx.x * 32, ny = blockIdx.y * 32;
    const int tx = threadIdx.x & 31, ty = threadIdx.x >> 5;   // 32 x 8
#pragma unroll
    for (int r = 0; r < 4; r++) {
        const int row = ty + r * 8;
        t[row][tx] = W[(size_t)(kx + row) * D_ + ny + tx];
    }
    __syncthreads();
#pragma unroll
    for (int r = 0; r < 4; r++) {
        const int row = ty + r * 8;                            // n_loc
        __nv_bfloat16 h, l;
        split_bf16(t[tx][row], h, l);
        dh[(size_t)(ny + row) * D_ + kx + tx] = h;
        dl[(size_t)(ny + row) * D_ + kx + tx] = l;
    }
}

// ---------------------------------------------------------------------------
// Prep: per-tile column sums of V (hi+lo), then prefix over tiles.
// ---------------------------------------------------------------------------
__global__ __launch_bounds__(64) void vtilesum(const float* __restrict__ vh,
                                               const float* __restrict__ vl,
                                               float* __restrict__ cs) {
    const int t = blockIdx.x, h = blockIdx.y, b = blockIdx.z, d = threadIdx.x;
    const size_t base = ((size_t)b * S_ + t * 64) * D_ + (size_t)h * HD_ + d;
    float s = 0.f;
#pragma unroll 8
    for (int r = 0; r < 64; r++)
        s += vh[base + (size_t)r * D_] + vl[base + (size_t)r * D_];
    cs[(((size_t)b * H_ + h) * 32 + t) * 64 + d] = s;
}
__global__ __launch_bounds__(64) void vprefix(float* __restrict__ cs) {
    const int h = blockIdx.x, b = blockIdx.y, d = threadIdx.x;
    float s = 0.f;
    for (int t = 0; t < 32; t++) {
        const size_t off = (((size_t)b * H_ + h) * 32 + t) * 64 + d;
        s += cs[off];
        cs[off] = s;
    }
}

// ---------------------------------------------------------------------------
// bf16x3 tensor-core GEMM, fused over up to 3 weight matrices.
// qkv_mode=1: sel 0/1 outputs tf32-rounded (q,k); sel 2 outputs tf32 hi/lo
// split (v -> C, Cvl). qkv_mode=0: plain fp32 + bias.
// ---------------------------------------------------------------------------
#define GP 40                     // smem pitch in bf16
#define PLANE (128 * GP)          // 5120 bf16 per plane
#define STAGE (4 * PLANE)         // Ah, Al, Bh, Bl

__global__ __launch_bounds__(256, 2) void gemm_bf16x3(
    const __nv_bfloat16* __restrict__ Ah, const __nv_bfloat16* __restrict__ Al,
    const __nv_bfloat16* __restrict__ BhBase,
    const __nv_bfloat16* __restrict__ BlBase,
    const float* __restrict__ bias,
    float* __restrict__ C0, float* __restrict__ C1, float* __restrict__ C2,
    float* __restrict__ Cvl, int qkv_mode) {
    const int K = D_, N = D_;
    extern __shared__ __nv_bfloat16 smb[];

    const int sel = blockIdx.x >> 3;
    const int bx = blockIdx.x & 7;
    const int by = blockIdx.y;
    const __nv_bfloat16* Bh = BhBase + (size_t)sel * D_ * D_;
    const __nv_bfloat16* Bl = BlBase + (size_t)sel * D_ * D_;
    float* C = (sel == 0) ? C0 : (sel == 1) ? C1 : C2;

    const int tid = threadIdx.x;
    const int wid = tid >> 5, lane = tid & 31;
    const int grp = lane >> 2, tg = lane & 3;
    const int wm = wid & 3;
    const int wn = wid >> 2;

    float acc[2][8][4] = {};

    const __nv_bfloat16* srcA_h = Ah + (size_t)(by * 128) * K;
    const __nv_bfloat16* srcA_l = Al + (size_t)(by * 128) * K;
    const __nv_bfloat16* srcB_h = Bh + (size_t)(bx * 128) * K;
    const __nv_bfloat16* srcB_l = Bl + (size_t)(bx * 128) * K;

    auto load_stage = [&](int stage, int k0) {
        __nv_bfloat16* s = smb + stage * STAGE;
        const __nv_bfloat16* srcs[4] = {srcA_h + k0, srcA_l + k0,
                                        srcB_h + k0, srcB_l + k0};
#pragma unroll
        for (int plane = 0; plane < 4; plane++) {
#pragma unroll
            for (int half = 0; half < 2; half++) {
                const int idx = tid + half * 256;
                const int row = idx >> 2, c = idx & 3;
                cp_async16(s + plane * PLANE + row * GP + c * 8,
                           srcs[plane] + (size_t)row * K + c * 8);
            }
        }
    };

    auto compute = [&](int stage) {
        const uint32_t* b32 = (const uint32_t*)(smb + stage * STAGE);
        const uint32_t* pAh = b32 + (wm * 32 + grp) * 20;
        const uint32_t* pAl = pAh + PLANE / 2;
        const uint32_t* pBh = b32 + 2 * (PLANE / 2) + (wn * 64 + grp) * 20;
        const uint32_t* pBl = pBh + PLANE / 2;
#pragma unroll
        for (int ks = 0; ks < 2; ks++) {
            const int k32 = ks * 8;
            uint32_t ah[2][4], al[2][4];
#pragma unroll
            for (int mf = 0; mf < 2; mf++) {
                const uint32_t* p = pAh + mf * 16 * 20 + k32;
                ah[mf][0] = p[tg];
                ah[mf][1] = p[160 + tg];
                ah[mf][2] = p[tg + 4];
                ah[mf][3] = p[160 + tg + 4];
                const uint32_t* q2 = pAl + mf * 16 * 20 + k32;
                al[mf][0] = q2[tg];
                al[mf][1] = q2[160 + tg];
                al[mf][2] = q2[tg + 4];
                al[mf][3] = q2[160 + tg + 4];
            }
            uint32_t bh[8][2], bl[8][2];
#pragma unroll
            for (int nf = 0; nf < 8; nf++) {
                const uint32_t* p = pBh + nf * 160 + k32;
                bh[nf][0] = p[tg];
                bh[nf][1] = p[tg + 4];
                const uint32_t* q2 = pBl + nf * 160 + k32;
                bl[nf][0] = q2[tg];
                bl[nf][1] = q2[tg + 4];
            }
#pragma unroll
            for (int mf = 0; mf < 2; mf++)
#pragma unroll
                for (int nf = 0; nf < 8; nf++) {
                    MMA_BF16(acc[mf][nf], ah[mf], bh[nf]);
                    MMA_BF16(acc[mf][nf], al[mf], bh[nf]);
                    MMA_BF16(acc[mf][nf], ah[mf], bl[nf]);
                }
        }
    };

    load_stage(0, 0);
    cp_commit();

    const int KT = K / 32;
    int stage = 0;
    for (int kt = 0; kt < KT; kt++) {
        if (kt + 1 < KT) {
            load_stage(stage ^ 1, (kt + 1) * 32);
            cp_commit();
            cp_wait<1>();
        } else {
            cp_wait<0>();
        }
        __syncthreads();
        compute(stage);
        stage ^= 1;
        __syncthreads();
    }

#pragma unroll
    for (int mf = 0; mf < 2; mf++) {
#pragma unroll
        for (int nf = 0; nf < 8; nf++) {
            const int row = by * 128 + wm * 32 + mf * 16 + grp;
            const int col = bx * 128 + wn * 64 + nf * 8 + 2 * tg;
            const size_t o00 = (size_t)row * N + col;
            const size_t o10 = (size_t)(row + 8) * N + col;
            if (qkv_mode) {
                if (sel < 2) {
                    C[o00]     = tf32f(acc[mf][nf][0]);
                    C[o00 + 1] = tf32f(acc[mf][nf][1]);
                    C[o10]     = tf32f(acc[mf][nf][2]);
                    C[o10 + 1] = tf32f(acc[mf][nf][3]);
                } else {
                    uint32_t hu, lu;
                    split_tf32(acc[mf][nf][0], hu, lu);
                    C[o00] = __uint_as_float(hu);  Cvl[o00] = __uint_as_float(lu);
                    split_tf32(acc[mf][nf][1], hu, lu);
                    C[o00 + 1] = __uint_as_float(hu); Cvl[o00 + 1] = __uint_as_float(lu);
                    split_tf32(acc[mf][nf][2], hu, lu);
                    C[o10] = __uint_as_float(hu);  Cvl[o10] = __uint_as_float(lu);
                    split_tf32(acc[mf][nf][3], hu, lu);
                    C[o10 + 1] = __uint_as_float(hu); Cvl[o10 + 1] = __uint_as_float(lu);
                }
            } else {
                const float b0 = bias ? bias[col] : 0.f;
                const float b1 = bias ? bias[col + 1] : 0.f;
                C[o00]     = acc[mf][nf][0] + b0;
                C[o00 + 1] = acc[mf][nf][1] + b1;
                C[o10]     = acc[mf][nf][2] + b0;
                C[o10 + 1] = acc[mf][nf][3] + b1;
            }
        }
    }
}

// ---------------------------------------------------------------------------
// Tensor-core causal attention, P = 1 + D decomposition.
// All operands pre-converted in global memory: q,k tf32-rounded; v split into
// vh/vl. Tile loads are pure cp.async. colsum(V) replaced by precomputed
// prefix sums (added once in the epilogue). Vl tile loaded only for the
// diagonal tile. 90KB smem -> 2 CTAs/SM co-residency.
// ---------------------------------------------------------------------------
#define QP 68
#define VP 72

__global__ __launch_bounds__(256, 2) void attn_mma(
    const float* __restrict__ q, const float* __restrict__ k,
    const float* __restrict__ vh, const float* __restrict__ vl,
    const float* __restrict__ csum, float* __restrict__ ctx) {
    extern __shared__ float sm[];
    float* Qs   = sm;                  // [64][QP]
    float* Ks   = Qs + 64 * QP;        // [64][QP]
    float* Dh   = Ks + 64 * QP;        // [64][QP]
    float* Vhs  = Dh + 64 * QP;        // [64][VP]
    float* Vls  = Vhs + 64 * VP;       // [64][VP] (diag tile only)
    float* Lred = Vls + 64 * VP;       // [4][64]

    const int tid = threadIdx.x;
    const int wid = tid >> 5, lane = tid & 31;
    const int grp = lane >> 2, tg = lane & 3;
    const int wm = wid & 3;            // S^T: k-row group / PV: q-row group
    const int wn = wid >> 2;           // S^T: q-col group / PV: d-col group
    const int qt = blockIdx.x, h = blockIdx.y, b = blockIdx.z;

    const size_t base = ((size_t)b * S_) * D_ + (size_t)h * HD_;

    // Q tile: pure copy (already tf32-rounded in global)
#pragma unroll
    for (int it = 0; it < 4; it++) {
        const int idx = tid + it * 256;
        const int row = idx >> 4, c = idx & 15;
        cp_async16(Qs + row * QP + c * 4,
                   q + base + (size_t)(qt * 64 + row) * D_ + c * 4);
    }

    float acc[4][4]  = {};
    float dsum[4][2] = {};

    for (int kt = 0; kt <= qt; kt++) {
        __syncthreads();   // (A) previous tile fully consumed

        // K + Vh tile loads (pure cp.async); Vl only on diagonal tile
#pragma unroll
        for (int it = 0; it < 4; it++) {
            const int idx = tid + it * 256;
            const int row = idx >> 4, c = idx & 15;
            const size_t goff = base + (size_t)(kt * 64 + row) * D_ + c * 4;
            cp_async16(Ks + row * QP + c * 4, k + goff);
            cp_async16(Vhs + row * VP + c * 4, vh + goff);
        }
        if (kt == qt) {
#pragma unroll
            for (int it = 0; it < 4; it++) {
                const int idx = tid + it * 256;
                const int row = idx >> 4, c = idx & 15;
                cp_async16(Vls + row * VP + c * 4,
                           vl + base + (size_t)(kt * 64 + row) * D_ + c * 4);
            }
        }
        cp_commit();
        cp_wait<0>();
        __syncthreads();   // (B) tiles ready

        // S^T = K @ Q^T  (m = k-token, n = q-token), 1-pass tf32
        float s[4][4] = {};
        const float* Ka = Ks + (wm * 16 + grp) * QP;
#pragma unroll
        for (int ks = 0; ks < 8; ks++) {
            const int kb = ks * 8;
            uint32_t a[4];
            a[0] = __float_as_uint(Ka[kb + tg]);
            a[1] = __float_as_uint(Ka[8 * QP + kb + tg]);
            a[2] = __float_as_uint(Ka[kb + tg + 4]);
            a[3] = __float_as_uint(Ka[8 * QP + kb + tg + 4]);
#pragma unroll
            for (int nf = 0; nf < 4; nf++) {
                const float* Qb = Qs + (wn * 32 + nf * 8 + grp) * QP + kb + tg;
                uint32_t bb[2] = { __float_as_uint(Qb[0]), __float_as_uint(Qb[4]) };
                MMA_TF32(s[nf], a, bb);
            }
        }

        // d = expm1(s/4096); masked (ktok > qtok) -> d = -1. Store D^T.
        const int kg0 = kt * 64 + wm * 16 + grp;
        const int kloc = wm * 16 + grp;
#pragma unroll
        for (int nf = 0; nf < 4; nf++) {
            const int qg0  = qt * 64 + wn * 32 + nf * 8 + 2 * tg;
            const int qloc = wn * 32 + nf * 8 + 2 * tg;
            float d0, d1, d2, d3;
            {
                float x = s[nf][0] * (1.f / 4096.f);
                d0 = (kg0 <= qg0)     ? x * (1.f + x * (0.5f + x * (1.f / 6.f))) : -1.f;
                x = s[nf][1] * (1.f / 4096.f);
                d1 = (kg0 <= qg0 + 1) ? x * (1.f + x * (0.5f + x * (1.f / 6.f))) : -1.f;
                x = s[nf][2] * (1.f / 4096.f);
                d2 = (kg0 + 8 <= qg0)     ? x * (1.f + x * (0.5f + x * (1.f / 6.f))) : -1.f;
                x = s[nf][3] * (1.f / 4096.f);
                d3 = (kg0 + 8 <= qg0 + 1) ? x * (1.f + x * (0.5f + x * (1.f / 6.f))) : -1.f;
            }
            dsum[nf][0] += d0 + d2;
            dsum[nf][1] += d1 + d3;
            Dh[qloc * QP + kloc]           = d0;
            Dh[(qloc + 1) * QP + kloc]     = d1;
            Dh[qloc * QP + kloc + 8]       = d2;
            Dh[(qloc + 1) * QP + kloc + 8] = d3;
        }
        __syncthreads();   // (C) Dh ready

        // acc += D @ V ; diagonal tile adds the (d, v_lo) pass
        const float* Da = Dh + (wm * 16 + grp) * QP;
        const bool diag = (kt == qt);
#pragma unroll
        for (int ks = 0; ks < 8; ks++) {
            const int kb = ks * 8;
            uint32_t a[4];
            a[0] = __float_as_uint(Da[kb + tg]);
            a[1] = __float_as_uint(Da[8 * QP + kb + tg]);
            a[2] = __float_as_uint(Da[kb + tg + 4]);
            a[3] = __float_as_uint(Da[8 * QP + kb + tg + 4]);
#pragma unroll
            for (int nf = 0; nf < 4; nf++) {
                const float* Vb = Vhs + (kb + tg) * VP + wn * 32 + nf * 8 + grp;
                uint32_t bh2[2] = { __float_as_uint(Vb[0]), __float_as_uint(Vb[4 * VP]) };
                MMA_TF32(acc[nf], a, bh2);
            }
            if (diag) {
#pragma unroll
                for (int nf = 0; nf < 4; nf++) {
                    const float* Vb = Vls + (kb + tg) * VP + wn * 32 + nf * 8 + grp;
                    uint32_t bl2[2] = { __float_as_uint(Vb[0]), __float_as_uint(Vb[4 * VP]) };
                    MMA_TF32(acc[nf], a, bl2);
                }
            }
        }
    }

    // Reduce dsum over grp lanes
#pragma unroll
    for (int off = 16; off >= 4; off >>= 1)
#pragma unroll
        for (int nf = 0; nf < 4; nf++) {
            dsum[nf][0] += __shfl_xor_sync(0xffffffffu, dsum[nf][0], off);
            dsum[nf][1] += __shfl_xor_sync(0xffffffffu, dsum[nf][1], off);
        }
    if (grp == 0) {
#pragma unroll
        for (int nf = 0; nf < 4; nf++) {
            Lred[wm * 64 + wn * 32 + nf * 8 + 2 * tg]     = dsum[nf][0];
            Lred[wm * 64 + wn * 32 + nf * 8 + 2 * tg + 1] = dsum[nf][1];
        }
    }
    __syncthreads();

    // Epilogue: O = (acc + prefix_colsum) / l
    const float* Cs = csum + (((size_t)b * H_ + h) * 32 + qt) * 64;
    const float nk = 64.0f * (float)(qt + 1);
    const int r0 = wm * 16 + grp, r1 = r0 + 8;
    float l0 = nk, l1 = nk;
#pragma unroll
    for (int w = 0; w < 4; w++) {
        l0 += Lred[w * 64 + r0];
        l1 += Lred[w * 64 + r1];
    }
    const float inv0 = 1.0f / l0, inv1 = 1.0f / l1;
#pragma unroll
    for (int nf = 0; nf < 4; nf++) {
        const int dcol = wn * 32 + nf * 8 + 2 * tg;
        const float cs0 = Cs[dcol], cs1 = Cs[dcol + 1];
        float2 w0, w1;
        w0.x = (acc[nf][0] + cs0) * inv0;
        w0.y = (acc[nf][1] + cs1) * inv0;
        w1.x = (acc[nf][2] + cs0) * inv1;
        w1.y = (acc[nf][3] + cs1) * inv1;
        *(float2*)&ctx[base + (size_t)(qt * 64 + r0) * D_ + dcol] = w0;
        *(float2*)&ctx[base + (size_t)(qt * 64 + r1) * D_ + dcol] = w1;
    }
}

// ---------------------------------------------------------------------------
// Launch
// ---------------------------------------------------------------------------
extern "C" void kernel_launch(void* const* d_in, const int* in_sizes, int n_in,
                              void* d_out, int out_size) {
    const float* x  = (const float*)d_in[0];
    const float* Wq = (const float*)d_in[1];
    const float* Wk = (const float*)d_in[2];
    const float* Wv = (const float*)d_in[3];
    const float* Wo = (const float*)d_in[4];
    const float* bo = (const float*)d_in[5];
    float* out = (float*)d_out;

    float *pq, *pk, *pv, *pvl, *pc, *pcs;
    cudaGetSymbolAddress((void**)&pq, g_q);
    cudaGetSymbolAddress((void**)&pk, g_k);
    cudaGetSymbolAddress((void**)&pv, g_v);
    cudaGetSymbolAddress((void**)&pvl, g_vl);
    cudaGetSymbolAddress((void**)&pc, g_c);
    cudaGetSymbolAddress((void**)&pcs, g_cs);
    __nv_bfloat16 *pxh, *pxl, *pch, *pcl, *pwh, *pwl;
    cudaGetSymbolAddress((void**)&pxh, g_xh);
    cudaGetSymbolAddress((void**)&pxl, g_xl);
    cudaGetSymbolAddress((void**)&pch, g_ch);
    cudaGetSymbolAddress((void**)&pcl, g_cl);
    cudaGetSymbolAddress((void**)&pwh, g_wh);
    cudaGetSymbolAddress((void**)&pwl, g_wl);

    const int gemm_smem = 2 * STAGE * (int)sizeof(__nv_bfloat16);  // 81920 B
    cudaFuncSetAttribute(gemm_bf16x3, cudaFuncAttributeMaxDynamicSharedMemorySize,
                         gemm_smem);
    const int attn_smem = (3 * 64 * QP + 2 * 64 * VP + 4 * 64) *
                          (int)sizeof(float);                       // 90112 B
    cudaFuncSetAttribute(attn_mma, cudaFuncAttributeMaxDynamicSharedMemorySize,
                         attn_smem);

    // Prep: split x, transpose+split the 4 weights
    fsplit<<<M_ * D_ / 4 / 256, 256>>>(x, pxh, pxl);
    wsplit_t<<<dim3(32, 32, 4), 256>>>(Wq, Wk, Wv, Wo, pwh, pwl);

    // Fused Q/K/V projection; epilogue pre-converts q,k (tf32) and v (hi/lo)
    dim3 gqkv(3 * D_ / 128, M_ / 128);   // (24, 64)
    gemm_bf16x3<<<gqkv, 256, gemm_smem>>>(pxh, pxl, pwh, pwl, nullptr,
                                          pq, pk, pv, pvl, 1);

    // Prefix tile colsums of V
    vtilesum<<<dim3(32, H_, B_), 64>>>(pv, pvl, pcs);
    vprefix<<<dim3(H_, B_), 64>>>(pcs);

    dim3 gattn(S_ / 64, H_, B_);         // (32, 16, 4)
    attn_mma<<<gattn, 256, attn_smem>>>(pq, pk, pv, pvl, pcs, pc);

    fsplit<<<M_ * D_ / 4 / 256, 256>>>(pc, pch, pcl);
    dim3 gout(D_ / 128, M_ / 128);       // (8, 64)
    gemm_bf16x3<<<gout, 256, gemm_smem>>>(pch, pcl, pwh + 3 * (size_t)D_ * D_,
                                          pwl + 3 * (size_t)D_ * D_, bo,
                                          out, out, out, nullptr, 0);
}

// round 12
// speedup vs baseline: 3.0446x; 1.0916x over previous
#include <cuda_runtime.h>
#include <cuda_bf16.h>
#include <cstdint>

// Problem constants
#define B_  4
#define S_  2048
#define D_  1024
#define H_  16
#define HD_ 64
#define M_  (B_ * S_)   // 8192 rows

// Scratch (allocation-free rule: __device__ globals)
__device__ __nv_bfloat16 g_q[M_ * D_];   // bf16 Q
__device__ __nv_bfloat16 g_k[M_ * D_];   // bf16 K
__device__ float g_v[M_ * D_];           // V hi (tf32 part)
__device__ float g_vl[M_ * D_];          // V lo (residual)
__device__ float g_c[M_ * D_];           // attention output ctx
__device__ float g_cs[B_ * H_ * 32 * 64];   // per-(b,h) prefix tile colsums of V
// bf16x3 pre-split operands
__device__ __nv_bfloat16 g_xh[M_ * D_], g_xl[M_ * D_];    // x hi/lo [M][K]
__device__ __nv_bfloat16 g_ch[M_ * D_], g_cl[M_ * D_];    // ctx hi/lo [M][K]
__device__ __nv_bfloat16 g_wh[4 * D_ * D_];               // W^T hi [N][K] x4
__device__ __nv_bfloat16 g_wl[4 * D_ * D_];               // W^T lo

// ---------------------------------------------------------------------------
// cp.async helpers
// ---------------------------------------------------------------------------
__device__ __forceinline__ void cp_async16(void* smem, const void* gmem) {
    uint32_t s = (uint32_t)__cvta_generic_to_shared(smem);
    asm volatile("cp.async.cg.shared.global [%0], [%1], 16;\n" :: "r"(s), "l"(gmem));
}
__device__ __forceinline__ void cp_commit() {
    asm volatile("cp.async.commit_group;\n");
}
template <int N>
__device__ __forceinline__ void cp_wait() {
    asm volatile("cp.async.wait_group %0;\n" :: "n"(N));
}

#define MMA_TF32(c, a, b)                                                     \
    asm volatile(                                                             \
        "mma.sync.aligned.m16n8k8.row.col.f32.tf32.tf32.f32 "                 \
        "{%0,%1,%2,%3},{%4,%5,%6,%7},{%8,%9},{%0,%1,%2,%3};"                  \
        : "+f"(c[0]), "+f"(c[1]), "+f"(c[2]), "+f"(c[3])                      \
        : "r"(a[0]), "r"(a[1]), "r"(a[2]), "r"(a[3]), "r"(b[0]), "r"(b[1]))

#define MMA_BF16(c, a, b)                                                     \
    asm volatile(                                                             \
        "mma.sync.aligned.m16n8k16.row.col.f32.bf16.bf16.f32 "                \
        "{%0,%1,%2,%3},{%4,%5,%6,%7},{%8,%9},{%0,%1,%2,%3};"                  \
        : "+f"(c[0]), "+f"(c[1]), "+f"(c[2]), "+f"(c[3])                      \
        : "r"(a[0]), "r"(a[1]), "r"(a[2]), "r"(a[3]), "r"(b[0]), "r"(b[1]))

__device__ __forceinline__ void split_tf32(float x, uint32_t& hi, uint32_t& lo) {
    asm("cvt.rna.tf32.f32 %0, %1;" : "=r"(hi) : "f"(x));
    float r = x - __uint_as_float(hi);
    asm("cvt.rna.tf32.f32 %0, %1;" : "=r"(lo) : "f"(r));
}
__device__ __forceinline__ void split_bf16(float x, __nv_bfloat16& h, __nv_bfloat16& l) {
    h = __float2bfloat16_rn(x);
    l = __float2bfloat16_rn(x - __bfloat162float(h));
}

// ---------------------------------------------------------------------------
// Prep: elementwise fp32 -> bf16 hi/lo split (for x and ctx).
// ---------------------------------------------------------------------------
__global__ __launch_bounds__(256) void fsplit(const float* __restrict__ src,
                                              __nv_bfloat16* __restrict__ h,
                                              __nv_bfloat16* __restrict__ l) {
    const int i = blockIdx.x * 256 + threadIdx.x;   // one float4 per thread
    float4 v = ((const float4*)src)[i];
    __nv_bfloat16 h0, h1, h2, h3, l0, l1, l2, l3;
    split_bf16(v.x, h0, l0);
    split_bf16(v.y, h1, l1);
    split_bf16(v.z, h2, l2);
    split_bf16(v.w, h3, l3);
    __nv_bfloat162* hp = (__nv_bfloat162*)h;
    __nv_bfloat162* lp = (__nv_bfloat162*)l;
    hp[2 * i]     = __nv_bfloat162{h0, h1};
    hp[2 * i + 1] = __nv_bfloat162{h2, h3};
    lp[2 * i]     = __nv_bfloat162{l0, l1};
    lp[2 * i + 1] = __nv_bfloat162{l2, l3};
}

// ---------------------------------------------------------------------------
// Prep: W [K][N] -> W^T hi/lo bf16 [N][K], 32x32 smem tile transpose.
// ---------------------------------------------------------------------------
__global__ __launch_bounds__(256) void wsplit_t(const float* __restrict__ W0,
                                                const float* __restrict__ W1,
                                                const float* __restrict__ W2,
                                                const float* __restrict__ W3,
                                                __nv_bfloat16* __restrict__ dh,
                                                __nv_bfloat16* __restrict__ dl) {
    __shared__ float t[32][33];
    const float* W = (blockIdx.z == 0) ? W0 : (blockIdx.z == 1) ? W1
                   : (blockIdx.z == 2) ? W2 : W3;
    dh += (size_t)blockIdx.z * D_ * D_;
    dl += (size_t)blockIdx.z * D_ * D_;
    const int kx = blockIdx.x * 32, ny = blockIdx.y * 32;
    const int tx = threadIdx.x & 31, ty = threadIdx.x >> 5;   // 32 x 8
#pragma unroll
    for (int r = 0; r < 4; r++) {
        const int row = ty + r * 8;
        t[row][tx] = W[(size_t)(kx + row) * D_ + ny + tx];
    }
    __syncthreads();
#pragma unroll
    for (int r = 0; r < 4; r++) {
        const int row = ty + r * 8;                            // n_loc
        __nv_bfloat16 h, l;
        split_bf16(t[tx][row], h, l);
        dh[(size_t)(ny + row) * D_ + kx + tx] = h;
        dl[(size_t)(ny + row) * D_ + kx + tx] = l;
    }
}

// ---------------------------------------------------------------------------
// Prep: per-tile column sums of V (hi+lo), then prefix over tiles.
// ---------------------------------------------------------------------------
__global__ __launch_bounds__(64) void vtilesum(const float* __restrict__ vh,
                                               const float* __restrict__ vl,
                                               float* __restrict__ cs) {
    const int t = blockIdx.x, h = blockIdx.y, b = blockIdx.z, d = threadIdx.x;
    const size_t base = ((size_t)b * S_ + t * 64) * D_ + (size_t)h * HD_ + d;
    float s = 0.f;
#pragma unroll 8
    for (int r = 0; r < 64; r++)
        s += vh[base + (size_t)r * D_] + vl[base + (size_t)r * D_];
    cs[(((size_t)b * H_ + h) * 32 + t) * 64 + d] = s;
}
__global__ __launch_bounds__(64) void vprefix(float* __restrict__ cs) {
    const int h = blockIdx.x, b = blockIdx.y, d = threadIdx.x;
    float s = 0.f;
    for (int t = 0; t < 32; t++) {
        const size_t off = (((size_t)b * H_ + h) * 32 + t) * 64 + d;
        s += cs[off];
        cs[off] = s;
    }
}

// ---------------------------------------------------------------------------
// bf16x3 tensor-core GEMM, fused over up to 3 weight matrices.
// qkv_mode=1: sel 0/1 -> bf16 outputs (q,k); sel 2 -> tf32 hi/lo split
// (v -> Vho, Vlo). qkv_mode=0: fp32 + bias -> Cf.
// ---------------------------------------------------------------------------
#define GP 40                     // smem pitch in bf16
#define PLANE (128 * GP)          // 5120 bf16 per plane
#define STAGE (4 * PLANE)         // Ah, Al, Bh, Bl

__global__ __launch_bounds__(256, 2) void gemm_bf16x3(
    const __nv_bfloat16* __restrict__ Ah, const __nv_bfloat16* __restrict__ Al,
    const __nv_bfloat16* __restrict__ BhBase,
    const __nv_bfloat16* __restrict__ BlBase,
    const float* __restrict__ bias, float* __restrict__ Cf,
    __nv_bfloat16* __restrict__ Qo, __nv_bfloat16* __restrict__ Ko,
    float* __restrict__ Vho, float* __restrict__ Vlo, int qkv_mode) {
    const int K = D_, N = D_;
    extern __shared__ __nv_bfloat16 smb[];

    const int sel = blockIdx.x >> 3;
    const int bx = blockIdx.x & 7;
    const int by = blockIdx.y;
    const __nv_bfloat16* Bh = BhBase + (size_t)sel * D_ * D_;
    const __nv_bfloat16* Bl = BlBase + (size_t)sel * D_ * D_;

    const int tid = threadIdx.x;
    const int wid = tid >> 5, lane = tid & 31;
    const int grp = lane >> 2, tg = lane & 3;
    const int wm = wid & 3;
    const int wn = wid >> 2;

    float acc[2][8][4] = {};

    const __nv_bfloat16* srcA_h = Ah + (size_t)(by * 128) * K;
    const __nv_bfloat16* srcA_l = Al + (size_t)(by * 128) * K;
    const __nv_bfloat16* srcB_h = Bh + (size_t)(bx * 128) * K;
    const __nv_bfloat16* srcB_l = Bl + (size_t)(bx * 128) * K;

    auto load_stage = [&](int stage, int k0) {
        __nv_bfloat16* s = smb + stage * STAGE;
        const __nv_bfloat16* srcs[4] = {srcA_h + k0, srcA_l + k0,
                                        srcB_h + k0, srcB_l + k0};
#pragma unroll
        for (int plane = 0; plane < 4; plane++) {
#pragma unroll
            for (int half = 0; half < 2; half++) {
                const int idx = tid + half * 256;
                const int row = idx >> 2, c = idx & 3;
                cp_async16(s + plane * PLANE + row * GP + c * 8,
                           srcs[plane] + (size_t)row * K + c * 8);
            }
        }
    };

    auto compute = [&](int stage) {
        const uint32_t* b32 = (const uint32_t*)(smb + stage * STAGE);
        const uint32_t* pAh = b32 + (wm * 32 + grp) * 20;
        const uint32_t* pAl = pAh + PLANE / 2;
        const uint32_t* pBh = b32 + 2 * (PLANE / 2) + (wn * 64 + grp) * 20;
        const uint32_t* pBl = pBh + PLANE / 2;
#pragma unroll
        for (int ks = 0; ks < 2; ks++) {
            const int k32 = ks * 8;
            uint32_t ah[2][4], al[2][4];
#pragma unroll
            for (int mf = 0; mf < 2; mf++) {
                const uint32_t* p = pAh + mf * 16 * 20 + k32;
                ah[mf][0] = p[tg];
                ah[mf][1] = p[160 + tg];
                ah[mf][2] = p[tg + 4];
                ah[mf][3] = p[160 + tg + 4];
                const uint32_t* q2 = pAl + mf * 16 * 20 + k32;
                al[mf][0] = q2[tg];
                al[mf][1] = q2[160 + tg];
                al[mf][2] = q2[tg + 4];
                al[mf][3] = q2[160 + tg + 4];
            }
            uint32_t bh[8][2], bl[8][2];
#pragma unroll
            for (int nf = 0; nf < 8; nf++) {
                const uint32_t* p = pBh + nf * 160 + k32;
                bh[nf][0] = p[tg];
                bh[nf][1] = p[tg + 4];
                const uint32_t* q2 = pBl + nf * 160 + k32;
                bl[nf][0] = q2[tg];
                bl[nf][1] = q2[tg + 4];
            }
#pragma unroll
            for (int mf = 0; mf < 2; mf++)
#pragma unroll
                for (int nf = 0; nf < 8; nf++) {
                    MMA_BF16(acc[mf][nf], ah[mf], bh[nf]);
                    MMA_BF16(acc[mf][nf], al[mf], bh[nf]);
                    MMA_BF16(acc[mf][nf], ah[mf], bl[nf]);
                }
        }
    };

    load_stage(0, 0);
    cp_commit();

    const int KT = K / 32;
    int stage = 0;
    for (int kt = 0; kt < KT; kt++) {
        if (kt + 1 < KT) {
            load_stage(stage ^ 1, (kt + 1) * 32);
            cp_commit();
            cp_wait<1>();
        } else {
            cp_wait<0>();
        }
        __syncthreads();
        compute(stage);
        stage ^= 1;
        __syncthreads();
    }

#pragma unroll
    for (int mf = 0; mf < 2; mf++) {
#pragma unroll
        for (int nf = 0; nf < 8; nf++) {
            const int row = by * 128 + wm * 32 + mf * 16 + grp;
            const int col = bx * 128 + wn * 64 + nf * 8 + 2 * tg;
            const size_t o00 = (size_t)row * N + col;
            const size_t o10 = (size_t)(row + 8) * N + col;
            if (qkv_mode) {
                if (sel < 2) {
                    __nv_bfloat16* O = sel ? Ko : Qo;
                    *(__nv_bfloat162*)&O[o00] =
                        __floats2bfloat162_rn(acc[mf][nf][0], acc[mf][nf][1]);
                    *(__nv_bfloat162*)&O[o10] =
                        __floats2bfloat162_rn(acc[mf][nf][2], acc[mf][nf][3]);
                } else {
                    uint32_t hu, lu;
                    split_tf32(acc[mf][nf][0], hu, lu);
                    Vho[o00] = __uint_as_float(hu);  Vlo[o00] = __uint_as_float(lu);
                    split_tf32(acc[mf][nf][1], hu, lu);
                    Vho[o00 + 1] = __uint_as_float(hu); Vlo[o00 + 1] = __uint_as_float(lu);
                    split_tf32(acc[mf][nf][2], hu, lu);
                    Vho[o10] = __uint_as_float(hu);  Vlo[o10] = __uint_as_float(lu);
                    split_tf32(acc[mf][nf][3], hu, lu);
                    Vho[o10 + 1] = __uint_as_float(hu); Vlo[o10 + 1] = __uint_as_float(lu);
                }
            } else {
                const float b0 = bias ? bias[col] : 0.f;
                const float b1 = bias ? bias[col + 1] : 0.f;
                Cf[o00]     = acc[mf][nf][0] + b0;
                Cf[o00 + 1] = acc[mf][nf][1] + b1;
                Cf[o10]     = acc[mf][nf][2] + b0;
                Cf[o10 + 1] = acc[mf][nf][3] + b1;
            }
        }
    }
}

// ---------------------------------------------------------------------------
// Tensor-core causal attention, P = 1 + D decomposition.
// q,k bf16 (QK^T via m16n8k16); v pre-split tf32 hi/lo (DV via tf32, lo-pass
// on the diagonal tile). K/Vh double-buffered: prefetch of tile kt+1 issues
// after the top barrier of iter kt and overlaps all of kt's compute.
// colsum(V) precomputed as prefix sums. 99KB smem -> 2 CTAs/SM.
//
// Smem byte layout:
//   Qb   [64][72] bf16   @ 0       (9216)
//   Kb0  [64][72] bf16   @ 9216    (9216)
//   Kb1  [64][72] bf16   @ 18432   (9216)
//   Dh   [64][68] fp32   @ 27648   (17408)
//   Vh0  [64][72] fp32   @ 45056   (18432)
//   Vh1  [64][72] fp32   @ 63488   (18432)
//   Vl   [64][72] fp32   @ 81920   (18432)
//   Lred [4][64]  fp32   @ 100352  (1024)    total 101376 B
// ---------------------------------------------------------------------------
#define QP 68
#define VP 72
#define KPB36 36   // bf16 tile pitch in u32 (72 bf16)

__global__ __launch_bounds__(256, 2) void attn_mma(
    const __nv_bfloat16* __restrict__ q, const __nv_bfloat16* __restrict__ k,
    const float* __restrict__ vh, const float* __restrict__ vl,
    const float* __restrict__ csum, float* __restrict__ ctx) {
    extern __shared__ float sm[];
    char* smc = (char*)sm;
    const uint32_t offK[2] = {9216u, 18432u};
    const uint32_t offV[2] = {45056u, 63488u};
    float* Dh   = (float*)(smc + 27648);
    float* Vls  = (float*)(smc + 81920);
    float* Lred = (float*)(smc + 100352);

    const int tid = threadIdx.x;
    const int wid = tid >> 5, lane = tid & 31;
    const int grp = lane >> 2, tg = lane & 3;
    const int wm = wid & 3;            // S^T: k-row group / PV: q-row group
    const int wn = wid >> 2;           // S^T: q-col group / PV: d-col group
    const int qt = blockIdx.x, h = blockIdx.y, b = blockIdx.z;

    const size_t base = ((size_t)b * S_) * D_ + (size_t)h * HD_;

    auto load_kv = [&](int stage, int kt2) {
        char* Kd = smc + offK[stage];
        char* Vd = smc + offV[stage];
        const __nv_bfloat16* ksrc = k + base + (size_t)(kt2 * 64) * D_;
        const float* vsrc = vh + base + (size_t)(kt2 * 64) * D_;
#pragma unroll
        for (int it = 0; it < 2; it++) {          // K: 512 x 16B
            const int idx = tid + it * 256;
            const int row = idx >> 3, c = idx & 7;
            cp_async16(Kd + row * 144 + c * 16, ksrc + (size_t)row * D_ + c * 8);
        }
#pragma unroll
        for (int it = 0; it < 4; it++) {          // Vh: 1024 x 16B
            const int idx = tid + it * 256;
            const int row = idx >> 4, c = idx & 15;
            cp_async16(Vd + row * 288 + c * 16, vsrc + (size_t)row * D_ + c * 4);
        }
    };
    auto load_vl = [&](int kt2) {
        const float* vsrc = vl + base + (size_t)(kt2 * 64) * D_;
#pragma unroll
        for (int it = 0; it < 4; it++) {
            const int idx = tid + it * 256;
            const int row = idx >> 4, c = idx & 15;
            cp_async16((char*)Vls + row * 288 + c * 16,
                       vsrc + (size_t)row * D_ + c * 4);
        }
    };

    // Preloop: Q tile + first K/Vh tile (+Vl if single-tile row)
    {
        const __nv_bfloat16* qsrc = q + base + (size_t)(qt * 64) * D_;
#pragma unroll
        for (int it = 0; it < 2; it++) {
            const int idx = tid + it * 256;
            const int row = idx >> 3, c = idx & 7;
            cp_async16(smc + row * 144 + c * 16, qsrc + (size_t)row * D_ + c * 8);
        }
    }
    load_kv(0, 0);
    if (qt == 0) load_vl(0);
    cp_commit();

    float acc[4][4]  = {};
    float dsum[4][2] = {};
    int stage = 0;

    for (int kt = 0; kt <= qt; kt++) {
        cp_wait<0>();
        __syncthreads();   // tile ready+visible; prev iter's DV complete

        // Prefetch next tile into the other stage (overlaps all compute below)
        if (kt < qt) {
            load_kv(stage ^ 1, kt + 1);
            if (kt + 1 == qt) load_vl(qt);
            cp_commit();
        }

        // S^T = K @ Q^T  (m = k-token, n = q-token), bf16 m16n8k16
        float s[4][4] = {};
        const uint32_t* Ka = (const uint32_t*)(smc + offK[stage]) +
                             (wm * 16 + grp) * KPB36;
        const uint32_t* Qbase32 = (const uint32_t*)smc;
#pragma unroll
        for (int ks = 0; ks < 4; ks++) {
            const int k32 = ks * 8;
            uint32_t a[4];
            a[0] = Ka[k32 + tg];
            a[1] = Ka[8 * KPB36 + k32 + tg];
            a[2] = Ka[k32 + tg + 4];
            a[3] = Ka[8 * KPB36 + k32 + tg + 4];
#pragma unroll
            for (int nf = 0; nf < 4; nf++) {
                const uint32_t* Qp = Qbase32 +
                    (wn * 32 + nf * 8 + grp) * KPB36 + k32 + tg;
                uint32_t bb[2] = { Qp[0], Qp[4] };
                MMA_BF16(s[nf], a, bb);
            }
        }

        // d = expm1(s/4096); masked (ktok > qtok) -> d = -1. Store D^T.
        const int kg0 = kt * 64 + wm * 16 + grp;
        const int kloc = wm * 16 + grp;
#pragma unroll
        for (int nf = 0; nf < 4; nf++) {
            const int qg0  = qt * 64 + wn * 32 + nf * 8 + 2 * tg;
            const int qloc = wn * 32 + nf * 8 + 2 * tg;
            float d0, d1, d2, d3;
            {
                float x = s[nf][0] * (1.f / 4096.f);
                d0 = (kg0 <= qg0)     ? x * (1.f + x * (0.5f + x * (1.f / 6.f))) : -1.f;
                x = s[nf][1] * (1.f / 4096.f);
                d1 = (kg0 <= qg0 + 1) ? x * (1.f + x * (0.5f + x * (1.f / 6.f))) : -1.f;
                x = s[nf][2] * (1.f / 4096.f);
                d2 = (kg0 + 8 <= qg0)     ? x * (1.f + x * (0.5f + x * (1.f / 6.f))) : -1.f;
                x = s[nf][3] * (1.f / 4096.f);
                d3 = (kg0 + 8 <= qg0 + 1) ? x * (1.f + x * (0.5f + x * (1.f / 6.f))) : -1.f;
            }
            dsum[nf][0] += d0 + d2;
            dsum[nf][1] += d1 + d3;
            Dh[qloc * QP + kloc]           = d0;
            Dh[(qloc + 1) * QP + kloc]     = d1;
            Dh[qloc * QP + kloc + 8]       = d2;
            Dh[(qloc + 1) * QP + kloc + 8] = d3;
        }
        __syncthreads();   // Dh visible

        // acc += D @ V (tf32); diagonal tile adds the (d, v_lo) pass
        const float* Da = Dh + (wm * 16 + grp) * QP;
        const float* Vhs = (const float*)(smc + offV[stage]);
        const bool diag = (kt == qt);
#pragma unroll
        for (int ks = 0; ks < 8; ks++) {
            const int kb = ks * 8;
            uint32_t a[4];
            a[0] = __float_as_uint(Da[kb + tg]);
            a[1] = __float_as_uint(Da[8 * QP + kb + tg]);
            a[2] = __float_as_uint(Da[kb + tg + 4]);
            a[3] = __float_as_uint(Da[8 * QP + kb + tg + 4]);
#pragma unroll
            for (int nf = 0; nf < 4; nf++) {
                const float* Vb = Vhs + (kb + tg) * VP + wn * 32 + nf * 8 + grp;
                uint32_t bh2[2] = { __float_as_uint(Vb[0]), __float_as_uint(Vb[4 * VP]) };
                MMA_TF32(acc[nf], a, bh2);
            }
            if (diag) {
#pragma unroll
                for (int nf = 0; nf < 4; nf++) {
                    const float* Vb = Vls + (kb + tg) * VP + wn * 32 + nf * 8 + grp;
                    uint32_t bl2[2] = { __float_as_uint(Vb[0]), __float_as_uint(Vb[4 * VP]) };
                    MMA_TF32(acc[nf], a, bl2);
                }
            }
        }
        stage ^= 1;
    }

    // Reduce dsum over grp lanes
#pragma unroll
    for (int off = 16; off >= 4; off >>= 1)
#pragma unroll
        for (int nf = 0; nf < 4; nf++) {
            dsum[nf][0] += __shfl_xor_sync(0xffffffffu, dsum[nf][0], off);
            dsum[nf][1] += __shfl_xor_sync(0xffffffffu, dsum[nf][1], off);
        }
    if (grp == 0) {
#pragma unroll
        for (int nf = 0; nf < 4; nf++) {
            Lred[wm * 64 + wn * 32 + nf * 8 + 2 * tg]     = dsum[nf][0];
            Lred[wm * 64 + wn * 32 + nf * 8 + 2 * tg + 1] = dsum[nf][1];
        }
    }
    __syncthreads();

    // Epilogue: O = (acc + prefix_colsum) / l
    const float* Cs = csum + (((size_t)b * H_ + h) * 32 + qt) * 64;
    const float nk = 64.0f * (float)(qt + 1);
    const int r0 = wm * 16 + grp, r1 = r0 + 8;
    float l0 = nk, l1 = nk;
#pragma unroll
    for (int w = 0; w < 4; w++) {
        l0 += Lred[w * 64 + r0];
        l1 += Lred[w * 64 + r1];
    }
    const float inv0 = 1.0f / l0, inv1 = 1.0f / l1;
#pragma unroll
    for (int nf = 0; nf < 4; nf++) {
        const int dcol = wn * 32 + nf * 8 + 2 * tg;
        const float cs0 = Cs[dcol], cs1 = Cs[dcol + 1];
        float2 w0, w1;
        w0.x = (acc[nf][0] + cs0) * inv0;
        w0.y = (acc[nf][1] + cs1) * inv0;
        w1.x = (acc[nf][2] + cs0) * inv1;
        w1.y = (acc[nf][3] + cs1) * inv1;
        *(float2*)&ctx[base + (size_t)(qt * 64 + r0) * D_ + dcol] = w0;
        *(float2*)&ctx[base + (size_t)(qt * 64 + r1) * D_ + dcol] = w1;
    }
}

// ---------------------------------------------------------------------------
// Launch
// ---------------------------------------------------------------------------
extern "C" void kernel_launch(void* const* d_in, const int* in_sizes, int n_in,
                              void* d_out, int out_size) {
    const float* x  = (const float*)d_in[0];
    const float* Wq = (const float*)d_in[1];
    const float* Wk = (const float*)d_in[2];
    const float* Wv = (const float*)d_in[3];
    const float* Wo = (const float*)d_in[4];
    const float* bo = (const float*)d_in[5];
    float* out = (float*)d_out;

    __nv_bfloat16 *pq, *pk;
    float *pv, *pvl, *pc, *pcs;
    cudaGetSymbolAddress((void**)&pq, g_q);
    cudaGetSymbolAddress((void**)&pk, g_k);
    cudaGetSymbolAddress((void**)&pv, g_v);
    cudaGetSymbolAddress((void**)&pvl, g_vl);
    cudaGetSymbolAddress((void**)&pc, g_c);
    cudaGetSymbolAddress((void**)&pcs, g_cs);
    __nv_bfloat16 *pxh, *pxl, *pch, *pcl, *pwh, *pwl;
    cudaGetSymbolAddress((void**)&pxh, g_xh);
    cudaGetSymbolAddress((void**)&pxl, g_xl);
    cudaGetSymbolAddress((void**)&pch, g_ch);
    cudaGetSymbolAddress((void**)&pcl, g_cl);
    cudaGetSymbolAddress((void**)&pwh, g_wh);
    cudaGetSymbolAddress((void**)&pwl, g_wl);

    const int gemm_smem = 2 * STAGE * (int)sizeof(__nv_bfloat16);  // 81920 B
    cudaFuncSetAttribute(gemm_bf16x3, cudaFuncAttributeMaxDynamicSharedMemorySize,
                         gemm_smem);
    const int attn_smem = 101376;
    cudaFuncSetAttribute(attn_mma, cudaFuncAttributeMaxDynamicSharedMemorySize,
                         attn_smem);

    // Prep: split x, transpose+split the 4 weights
    fsplit<<<M_ * D_ / 4 / 256, 256>>>(x, pxh, pxl);
    wsplit_t<<<dim3(32, 32, 4), 256>>>(Wq, Wk, Wv, Wo, pwh, pwl);

    // Fused Q/K/V projection; epilogue emits q,k bf16 and v tf32 hi/lo
    dim3 gqkv(3 * D_ / 128, M_ / 128);   // (24, 64)
    gemm_bf16x3<<<gqkv, 256, gemm_smem>>>(pxh, pxl, pwh, pwl, nullptr, nullptr,
                                          pq, pk, pv, pvl, 1);

    // Prefix tile colsums of V
    vtilesum<<<dim3(32, H_, B_), 64>>>(pv, pvl, pcs);
    vprefix<<<dim3(H_, B_), 64>>>(pcs);

    dim3 gattn(S_ / 64, H_, B_);         // (32, 16, 4)
    attn_mma<<<gattn, 256, attn_smem>>>(pq, pk, pv, pvl, pcs, pc);

    fsplit<<<M_ * D_ / 4 / 256, 256>>>(pc, pch, pcl);
    dim3 gout(D_ / 128, M_ / 128);       // (8, 64)
    gemm_bf16x3<<<gout, 256, gemm_smem>>>(pch, pcl, pwh + 3 * (size_t)D_ * D_,
                                          pwl + 3 * (size_t)D_ * D_, bo, out,
                                          nullptr, nullptr, nullptr, nullptr, 0);
}

// round 14
// speedup vs baseline: 3.0457x; 1.0004x over previous
#include <cuda_runtime.h>
#include <cuda_bf16.h>
#include <cstdint>

// Problem constants
#define B_  4
#define S_  2048
#define D_  1024
#define H_  16
#define HD_ 64
#define M_  (B_ * S_)   // 8192 rows

// Scratch (allocation-free rule: __device__ globals)
__device__ __nv_bfloat16 g_q[M_ * D_];   // bf16 Q
__device__ __nv_bfloat16 g_k[M_ * D_];   // bf16 K
__device__ float g_v[M_ * D_];           // V hi (tf32 part)
__device__ float g_vl[M_ * D_];          // V lo (residual)
__device__ float g_cs[B_ * H_ * 32 * 64];   // per-(b,h) prefix tile colsums of V
__device__ __nv_bfloat16 g_xh[M_ * D_], g_xl[M_ * D_];    // x hi/lo [M][K]
__device__ __nv_bfloat16 g_ch[M_ * D_], g_cl[M_ * D_];    // ctx hi/lo [M][K]
__device__ __nv_bfloat16 g_wh[4 * D_ * D_];               // W^T hi [N][K] x4
__device__ __nv_bfloat16 g_wl[4 * D_ * D_];               // W^T lo

// ---------------------------------------------------------------------------
// cp.async helpers
// ---------------------------------------------------------------------------
__device__ __forceinline__ void cp_async16(void* smem, const void* gmem) {
    uint32_t s = (uint32_t)__cvta_generic_to_shared(smem);
    asm volatile("cp.async.cg.shared.global [%0], [%1], 16;\n" :: "r"(s), "l"(gmem));
}
__device__ __forceinline__ void cp_commit() {
    asm volatile("cp.async.commit_group;\n");
}
template <int N>
__device__ __forceinline__ void cp_wait() {
    asm volatile("cp.async.wait_group %0;\n" :: "n"(N));
}

#define MMA_TF32(c, a, b)                                                     \
    asm volatile(                                                             \
        "mma.sync.aligned.m16n8k8.row.col.f32.tf32.tf32.f32 "                 \
        "{%0,%1,%2,%3},{%4,%5,%6,%7},{%8,%9},{%0,%1,%2,%3};"                  \
        : "+f"(c[0]), "+f"(c[1]), "+f"(c[2]), "+f"(c[3])                      \
        : "r"(a[0]), "r"(a[1]), "r"(a[2]), "r"(a[3]), "r"(b[0]), "r"(b[1]))

#define MMA_BF16(c, a, b)                                                     \
    asm volatile(                                                             \
        "mma.sync.aligned.m16n8k16.row.col.f32.bf16.bf16.f32 "                \
        "{%0,%1,%2,%3},{%4,%5,%6,%7},{%8,%9},{%0,%1,%2,%3};"                  \
        : "+f"(c[0]), "+f"(c[1]), "+f"(c[2]), "+f"(c[3])                      \
        : "r"(a[0]), "r"(a[1]), "r"(a[2]), "r"(a[3]), "r"(b[0]), "r"(b[1]))

__device__ __forceinline__ void split_tf32(float x, uint32_t& hi, uint32_t& lo) {
    asm("cvt.rna.tf32.f32 %0, %1;" : "=r"(hi) : "f"(x));
    float r = x - __uint_as_float(hi);
    asm("cvt.rna.tf32.f32 %0, %1;" : "=r"(lo) : "f"(r));
}
__device__ __forceinline__ void split_bf16(float x, __nv_bfloat16& h, __nv_bfloat16& l) {
    h = __float2bfloat16_rn(x);
    l = __float2bfloat16_rn(x - __bfloat162float(h));
}

// ---------------------------------------------------------------------------
// Prep: elementwise fp32 -> bf16 hi/lo split (x only now).
// ---------------------------------------------------------------------------
__global__ __launch_bounds__(256) void fsplit(const float* __restrict__ src,
                                              __nv_bfloat16* __restrict__ h,
                                              __nv_bfloat16* __restrict__ l) {
    const int i = blockIdx.x * 256 + threadIdx.x;
    float4 v = ((const float4*)src)[i];
    __nv_bfloat16 h0, h1, h2, h3, l0, l1, l2, l3;
    split_bf16(v.x, h0, l0);
    split_bf16(v.y, h1, l1);
    split_bf16(v.z, h2, l2);
    split_bf16(v.w, h3, l3);
    __nv_bfloat162* hp = (__nv_bfloat162*)h;
    __nv_bfloat162* lp = (__nv_bfloat162*)l;
    hp[2 * i]     = __nv_bfloat162{h0, h1};
    hp[2 * i + 1] = __nv_bfloat162{h2, h3};
    lp[2 * i]     = __nv_bfloat162{l0, l1};
    lp[2 * i + 1] = __nv_bfloat162{l2, l3};
}

// ---------------------------------------------------------------------------
// Prep: W [K][N] -> W^T hi/lo bf16 [N][K], 32x32 smem tile transpose.
// ---------------------------------------------------------------------------
__global__ __launch_bounds__(256) void wsplit_t(const float* __restrict__ W0,
                                                const float* __restrict__ W1,
                                                const float* __restrict__ W2,
                                                const float* __restrict__ W3,
                                                __nv_bfloat16* __restrict__ dh,
                                                __nv_bfloat16* __restrict__ dl) {
    __shared__ float t[32][33];
    const float* W = (blockIdx.z == 0) ? W0 : (blockIdx.z == 1) ? W1
                   : (blockIdx.z == 2) ? W2 : W3;
    dh += (size_t)blockIdx.z * D_ * D_;
    dl += (size_t)blockIdx.z * D_ * D_;
    const int kx = blockIdx.x * 32, ny = blockIdx.y * 32;
    const int tx = threadIdx.x & 31, ty = threadIdx.x >> 5;
#pragma unroll
    for (int r = 0; r < 4; r++) {
        const int row = ty + r * 8;
        t[row][tx] = W[(size_t)(kx + row) * D_ + ny + tx];
    }
    __syncthreads();
#pragma unroll
    for (int r = 0; r < 4; r++) {
        const int row = ty + r * 8;
        __nv_bfloat16 h, l;
        split_bf16(t[tx][row], h, l);
        dh[(size_t)(ny + row) * D_ + kx + tx] = h;
        dl[(size_t)(ny + row) * D_ + kx + tx] = l;
    }
}

// ---------------------------------------------------------------------------
// Prep: per-tile column sums of V (hi+lo), then prefix over tiles.
// ---------------------------------------------------------------------------
__global__ __launch_bounds__(64) void vtilesum(const float* __restrict__ vh,
                                               const float* __restrict__ vl,
                                               float* __restrict__ cs) {
    const int t = blockIdx.x, h = blockIdx.y, b = blockIdx.z, d = threadIdx.x;
    const size_t base = ((size_t)b * S_ + t * 64) * D_ + (size_t)h * HD_ + d;
    float s = 0.f;
#pragma unroll 8
    for (int r = 0; r < 64; r++)
        s += vh[base + (size_t)r * D_] + vl[base + (size_t)r * D_];
    cs[(((size_t)b * H_ + h) * 32 + t) * 64 + d] = s;
}
__global__ __launch_bounds__(64) void vprefix(float* __restrict__ cs) {
    const int h = blockIdx.x, b = blockIdx.y, d = threadIdx.x;
    float s = 0.f;
    for (int t = 0; t < 32; t++) {
        const size_t off = (((size_t)b * H_ + h) * 32 + t) * 64 + d;
        s += cs[off];
        cs[off] = s;
    }
}

// ---------------------------------------------------------------------------
// bf16x3 tensor-core GEMM (mma.sync; tcgen05 rejected by this bench's
// compute_103 PTX stage). Fused over up to 3 weights, sel = blockIdx.x>>3.
// Single-sync pipelined mainloop: per chunk  wait<0> -> sync ->
// prefetch(next -> stage^1) -> compute(stage). The prefetch overwrites
// stage^1, last read in iter kt-1, which all warps finished before this
// iteration's barrier -> one barrier per chunk, loads overlap MMA issue.
// 2 CTAs/SM co-residency.
// ---------------------------------------------------------------------------
#define GP 40                     // smem pitch in bf16
#define PLANE (128 * GP)          // 5120 bf16 per plane
#define STAGE (4 * PLANE)         // Ah, Al, Bh, Bl

__global__ __launch_bounds__(256, 2) void gemm_bf16x3(
    const __nv_bfloat16* __restrict__ Ah, const __nv_bfloat16* __restrict__ Al,
    const __nv_bfloat16* __restrict__ BhBase,
    const __nv_bfloat16* __restrict__ BlBase,
    const float* __restrict__ bias, float* __restrict__ Cf,
    __nv_bfloat16* __restrict__ Qo, __nv_bfloat16* __restrict__ Ko,
    float* __restrict__ Vho, float* __restrict__ Vlo, int qkv_mode) {
    const int K = D_, N = D_;
    extern __shared__ __nv_bfloat16 smb[];

    const int sel = blockIdx.x >> 3;
    const int bx = blockIdx.x & 7;
    const int by = blockIdx.y;
    const __nv_bfloat16* Bh = BhBase + (size_t)sel * D_ * D_;
    const __nv_bfloat16* Bl = BlBase + (size_t)sel * D_ * D_;

    const int tid = threadIdx.x;
    const int wid = tid >> 5, lane = tid & 31;
    const int grp = lane >> 2, tg = lane & 3;
    const int wm = wid & 3;
    const int wn = wid >> 2;

    float acc[2][8][4] = {};

    const __nv_bfloat16* srcA_h = Ah + (size_t)(by * 128) * K;
    const __nv_bfloat16* srcA_l = Al + (size_t)(by * 128) * K;
    const __nv_bfloat16* srcB_h = Bh + (size_t)(bx * 128) * K;
    const __nv_bfloat16* srcB_l = Bl + (size_t)(bx * 128) * K;

    auto load_stage = [&](int stage, int k0) {
        __nv_bfloat16* s = smb + stage * STAGE;
        const __nv_bfloat16* srcs[4] = {srcA_h + k0, srcA_l + k0,
                                        srcB_h + k0, srcB_l + k0};
#pragma unroll
        for (int plane = 0; plane < 4; plane++) {
#pragma unroll
            for (int half = 0; half < 2; half++) {
                const int idx = tid + half * 256;
                const int row = idx >> 2, c = idx & 3;
                cp_async16(s + plane * PLANE + row * GP + c * 8,
                           srcs[plane] + (size_t)row * K + c * 8);
            }
        }
    };

    auto compute = [&](int stage) {
        const uint32_t* b32 = (const uint32_t*)(smb + stage * STAGE);
        const uint32_t* pAh = b32 + (wm * 32 + grp) * 20;
        const uint32_t* pAl = pAh + PLANE / 2;
        const uint32_t* pBh = b32 + 2 * (PLANE / 2) + (wn * 64 + grp) * 20;
        const uint32_t* pBl = pBh + PLANE / 2;
#pragma unroll
        for (int ks = 0; ks < 2; ks++) {
            const int k32 = ks * 8;
            uint32_t ah[2][4], al[2][4];
#pragma unroll
            for (int mf = 0; mf < 2; mf++) {
                const uint32_t* p = pAh + mf * 16 * 20 + k32;
                ah[mf][0] = p[tg];
                ah[mf][1] = p[160 + tg];
                ah[mf][2] = p[tg + 4];
                ah[mf][3] = p[160 + tg + 4];
                const uint32_t* q2 = pAl + mf * 16 * 20 + k32;
                al[mf][0] = q2[tg];
                al[mf][1] = q2[160 + tg];
                al[mf][2] = q2[tg + 4];
                al[mf][3] = q2[160 + tg + 4];
            }
            uint32_t bh[8][2], bl[8][2];
#pragma unroll
            for (int nf = 0; nf < 8; nf++) {
                const uint32_t* p = pBh + nf * 160 + k32;
                bh[nf][0] = p[tg];
                bh[nf][1] = p[tg + 4];
                const uint32_t* q2 = pBl + nf * 160 + k32;
                bl[nf][0] = q2[tg];
                bl[nf][1] = q2[tg + 4];
            }
#pragma unroll
            for (int mf = 0; mf < 2; mf++)
#pragma unroll
                for (int nf = 0; nf < 8; nf++) {
                    MMA_BF16(acc[mf][nf], ah[mf], bh[nf]);
                    MMA_BF16(acc[mf][nf], al[mf], bh[nf]);
                    MMA_BF16(acc[mf][nf], ah[mf], bl[nf]);
                }
        }
    };

    load_stage(0, 0);
    cp_commit();

    const int KT = K / 32;   // 32 chunks
    int stage = 0;
    for (int kt = 0; kt < KT; kt++) {
        cp_wait<0>();
        __syncthreads();     // chunk kt resident; all warps done with stage^1
        if (kt + 1 < KT) {
            load_stage(stage ^ 1, (kt + 1) * 32);
            cp_commit();
        }
        compute(stage);
        stage ^= 1;
    }

#pragma unroll
    for (int mf = 0; mf < 2; mf++) {
#pragma unroll
        for (int nf = 0; nf < 8; nf++) {
            const int row = by * 128 + wm * 32 + mf * 16 + grp;
            const int col = bx * 128 + wn * 64 + nf * 8 + 2 * tg;
            const size_t o00 = (size_t)row * N + col;
            const size_t o10 = (size_t)(row + 8) * N + col;
            if (qkv_mode) {
                if (sel < 2) {
                    __nv_bfloat16* O = sel ? Ko : Qo;
                    *(__nv_bfloat162*)&O[o00] =
                        __floats2bfloat162_rn(acc[mf][nf][0], acc[mf][nf][1]);
                    *(__nv_bfloat162*)&O[o10] =
                        __floats2bfloat162_rn(acc[mf][nf][2], acc[mf][nf][3]);
                } else {
                    uint32_t hu, lu;
                    split_tf32(acc[mf][nf][0], hu, lu);
                    Vho[o00] = __uint_as_float(hu);  Vlo[o00] = __uint_as_float(lu);
                    split_tf32(acc[mf][nf][1], hu, lu);
                    Vho[o00 + 1] = __uint_as_float(hu); Vlo[o00 + 1] = __uint_as_float(lu);
                    split_tf32(acc[mf][nf][2], hu, lu);
                    Vho[o10] = __uint_as_float(hu);  Vlo[o10] = __uint_as_float(lu);
                    split_tf32(acc[mf][nf][3], hu, lu);
                    Vho[o10 + 1] = __uint_as_float(hu); Vlo[o10 + 1] = __uint_as_float(lu);
                }
            } else {
                const float b0 = bias ? bias[col] : 0.f;
                const float b1 = bias ? bias[col + 1] : 0.f;
                Cf[o00]     = acc[mf][nf][0] + b0;
                Cf[o00 + 1] = acc[mf][nf][1] + b1;
                Cf[o10]     = acc[mf][nf][2] + b0;
                Cf[o10 + 1] = acc[mf][nf][3] + b1;
            }
        }
    }
}

// ---------------------------------------------------------------------------
// Tensor-core causal attention, P = 1 + D decomposition (round-12 loop) with
// heavy-first CTA scheduling and bf16 hi/lo epilogue output (feeds out-GEMM
// directly, no fsplit pass).
// ---------------------------------------------------------------------------
#define QP 68
#define VP 72
#define KPB36 36   // bf16 tile pitch in u32 (72 bf16)

__global__ __launch_bounds__(256, 2) void attn_mma(
    const __nv_bfloat16* __restrict__ q, const __nv_bfloat16* __restrict__ k,
    const float* __restrict__ vh, const float* __restrict__ vl,
    const float* __restrict__ csum,
    __nv_bfloat16* __restrict__ ch, __nv_bfloat16* __restrict__ cl) {
    extern __shared__ float sm[];
    char* smc = (char*)sm;
    const uint32_t offK[2] = {9216u, 18432u};
    const uint32_t offV[2] = {45056u, 63488u};
    float* Dh   = (float*)(smc + 27648);
    float* Vls  = (float*)(smc + 81920);
    float* Lred = (float*)(smc + 100352);

    const int tid = threadIdx.x;
    const int wid = tid >> 5, lane = tid & 31;
    const int grp = lane >> 2, tg = lane & 3;
    const int wm = wid & 3;
    const int wn = wid >> 2;
    const int qt = (int)gridDim.x - 1 - (int)blockIdx.x;   // heavy CTAs first
    const int h = blockIdx.y, b = blockIdx.z;

    const size_t base = ((size_t)b * S_) * D_ + (size_t)h * HD_;

    auto load_kv = [&](int stage, int kt2) {
        char* Kd = smc + offK[stage];
        char* Vd = smc + offV[stage];
        const __nv_bfloat16* ksrc = k + base + (size_t)(kt2 * 64) * D_;
        const float* vsrc = vh + base + (size_t)(kt2 * 64) * D_;
#pragma unroll
        for (int it = 0; it < 2; it++) {
            const int idx = tid + it * 256;
            const int row = idx >> 3, c = idx & 7;
            cp_async16(Kd + row * 144 + c * 16, ksrc + (size_t)row * D_ + c * 8);
        }
#pragma unroll
        for (int it = 0; it < 4; it++) {
            const int idx = tid + it * 256;
            const int row = idx >> 4, c = idx & 15;
            cp_async16(Vd + row * 288 + c * 16, vsrc + (size_t)row * D_ + c * 4);
        }
    };
    auto load_vl = [&](int kt2) {
        const float* vsrc = vl + base + (size_t)(kt2 * 64) * D_;
#pragma unroll
        for (int it = 0; it < 4; it++) {
            const int idx = tid + it * 256;
            const int row = idx >> 4, c = idx & 15;
            cp_async16((char*)Vls + row * 288 + c * 16,
                       vsrc + (size_t)row * D_ + c * 4);
        }
    };

    {
        const __nv_bfloat16* qsrc = q + base + (size_t)(qt * 64) * D_;
#pragma unroll
        for (int it = 0; it < 2; it++) {
            const int idx = tid + it * 256;
            const int row = idx >> 3, c = idx & 7;
            cp_async16(smc + row * 144 + c * 16, qsrc + (size_t)row * D_ + c * 8);
        }
    }
    load_kv(0, 0);
    if (qt == 0) load_vl(0);
    cp_commit();

    float acc[4][4]  = {};
    float dsum[4][2] = {};
    int stage = 0;

    for (int kt = 0; kt <= qt; kt++) {
        cp_wait<0>();
        __syncthreads();

        if (kt < qt) {
            load_kv(stage ^ 1, kt + 1);
            if (kt + 1 == qt) load_vl(qt);
            cp_commit();
        }

        float s[4][4] = {};
        const uint32_t* Ka = (const uint32_t*)(smc + offK[stage]) +
                             (wm * 16 + grp) * KPB36;
        const uint32_t* Qbase32 = (const uint32_t*)smc;
#pragma unroll
        for (int ks = 0; ks < 4; ks++) {
            const int k32 = ks * 8;
            uint32_t a[4];
            a[0] = Ka[k32 + tg];
            a[1] = Ka[8 * KPB36 + k32 + tg];
            a[2] = Ka[k32 + tg + 4];
            a[3] = Ka[8 * KPB36 + k32 + tg + 4];
#pragma unroll
            for (int nf = 0; nf < 4; nf++) {
                const uint32_t* Qp = Qbase32 +
                    (wn * 32 + nf * 8 + grp) * KPB36 + k32 + tg;
                uint32_t bb[2] = { Qp[0], Qp[4] };
                MMA_BF16(s[nf], a, bb);
            }
        }

        const int kg0 = kt * 64 + wm * 16 + grp;
        const int kloc = wm * 16 + grp;
#pragma unroll
        for (int nf = 0; nf < 4; nf++) {
            const int qg0  = qt * 64 + wn * 32 + nf * 8 + 2 * tg;
            const int qloc = wn * 32 + nf * 8 + 2 * tg;
            float d0, d1, d2, d3;
            {
                float x = s[nf][0] * (1.f / 4096.f);
                d0 = (kg0 <= qg0)     ? x * (1.f + x * (0.5f + x * (1.f / 6.f))) : -1.f;
                x = s[nf][1] * (1.f / 4096.f);
                d1 = (kg0 <= qg0 + 1) ? x * (1.f + x * (0.5f + x * (1.f / 6.f))) : -1.f;
                x = s[nf][2] * (1.f / 4096.f);
                d2 = (kg0 + 8 <= qg0)     ? x * (1.f + x * (0.5f + x * (1.f / 6.f))) : -1.f;
                x = s[nf][3] * (1.f / 4096.f);
                d3 = (kg0 + 8 <= qg0 + 1) ? x * (1.f + x * (0.5f + x * (1.f / 6.f))) : -1.f;
            }
            dsum[nf][0] += d0 + d2;
            dsum[nf][1] += d1 + d3;
            Dh[qloc * QP + kloc]           = d0;
            Dh[(qloc + 1) * QP + kloc]     = d1;
            Dh[qloc * QP + kloc + 8]       = d2;
            Dh[(qloc + 1) * QP + kloc + 8] = d3;
        }
        __syncthreads();

        const float* Da = Dh + (wm * 16 + grp) * QP;
        const float* Vhs = (const float*)(smc + offV[stage]);
        const bool diag = (kt == qt);
#pragma unroll
        for (int ks = 0; ks < 8; ks++) {
            const int kb = ks * 8;
            uint32_t a[4];
            a[0] = __float_as_uint(Da[kb + tg]);
            a[1] = __float_as_uint(Da[8 * QP + kb + tg]);
            a[2] = __float_as_uint(Da[kb + tg + 4]);
            a[3] = __float_as_uint(Da[8 * QP + kb + tg + 4]);
#pragma unroll
            for (int nf = 0; nf < 4; nf++) {
                const float* Vb = Vhs + (kb + tg) * VP + wn * 32 + nf * 8 + grp;
                uint32_t bh2[2] = { __float_as_uint(Vb[0]), __float_as_uint(Vb[4 * VP]) };
                MMA_TF32(acc[nf], a, bh2);
            }
            if (diag) {
#pragma unroll
                for (int nf = 0; nf < 4; nf++) {
                    const float* Vb = Vls + (kb + tg) * VP + wn * 32 + nf * 8 + grp;
                    uint32_t bl2[2] = { __float_as_uint(Vb[0]), __float_as_uint(Vb[4 * VP]) };
                    MMA_TF32(acc[nf], a, bl2);
                }
            }
        }
        stage ^= 1;
    }

#pragma unroll
    for (int off = 16; off >= 4; off >>= 1)
#pragma unroll
        for (int nf = 0; nf < 4; nf++) {
            dsum[nf][0] += __shfl_xor_sync(0xffffffffu, dsum[nf][0], off);
            dsum[nf][1] += __shfl_xor_sync(0xffffffffu, dsum[nf][1], off);
        }
    if (grp == 0) {
#pragma unroll
        for (int nf = 0; nf < 4; nf++) {
            Lred[wm * 64 + wn * 32 + nf * 8 + 2 * tg]     = dsum[nf][0];
            Lred[wm * 64 + wn * 32 + nf * 8 + 2 * tg + 1] = dsum[nf][1];
        }
    }
    __syncthreads();

    const float* Cs = csum + (((size_t)b * H_ + h) * 32 + qt) * 64;
    const float nk = 64.0f * (float)(qt + 1);
    const int r0 = wm * 16 + grp, r1 = r0 + 8;
    float l0 = nk, l1 = nk;
#pragma unroll
    for (int w = 0; w < 4; w++) {
        l0 += Lred[w * 64 + r0];
        l1 += Lred[w * 64 + r1];
    }
    const float inv0 = 1.0f / l0, inv1 = 1.0f / l1;
#pragma unroll
    for (int nf = 0; nf < 4; nf++) {
        const int dcol = wn * 32 + nf * 8 + 2 * tg;
        const float cs0 = Cs[dcol], cs1 = Cs[dcol + 1];
        const float o00 = (acc[nf][0] + cs0) * inv0;
        const float o01 = (acc[nf][1] + cs1) * inv0;
        const float o10 = (acc[nf][2] + cs0) * inv1;
        const float o11 = (acc[nf][3] + cs1) * inv1;
        __nv_bfloat16 h0, h1, l0b, l1b;
        const size_t a0 = base + (size_t)(qt * 64 + r0) * D_ + dcol;
        const size_t a1 = base + (size_t)(qt * 64 + r1) * D_ + dcol;
        split_bf16(o00, h0, l0b); split_bf16(o01, h1, l1b);
        *(__nv_bfloat162*)&ch[a0] = __nv_bfloat162{h0, h1};
        *(__nv_bfloat162*)&cl[a0] = __nv_bfloat162{l0b, l1b};
        split_bf16(o10, h0, l0b); split_bf16(o11, h1, l1b);
        *(__nv_bfloat162*)&ch[a1] = __nv_bfloat162{h0, h1};
        *(__nv_bfloat162*)&cl[a1] = __nv_bfloat162{l0b, l1b};
    }
}

// ---------------------------------------------------------------------------
// Launch
// ---------------------------------------------------------------------------
extern "C" void kernel_launch(void* const* d_in, const int* in_sizes, int n_in,
                              void* d_out, int out_size) {
    const float* x  = (const float*)d_in[0];
    const float* Wq = (const float*)d_in[1];
    const float* Wk = (const float*)d_in[2];
    const float* Wv = (const float*)d_in[3];
    const float* Wo = (const float*)d_in[4];
    const float* bo = (const float*)d_in[5];
    float* out = (float*)d_out;

    __nv_bfloat16 *pq, *pk;
    float *pv, *pvl, *pcs;
    cudaGetSymbolAddress((void**)&pq, g_q);
    cudaGetSymbolAddress((void**)&pk, g_k);
    cudaGetSymbolAddress((void**)&pv, g_v);
    cudaGetSymbolAddress((void**)&pvl, g_vl);
    cudaGetSymbolAddress((void**)&pcs, g_cs);
    __nv_bfloat16 *pxh, *pxl, *pch, *pcl, *pwh, *pwl;
    cudaGetSymbolAddress((void**)&pxh, g_xh);
    cudaGetSymbolAddress((void**)&pxl, g_xl);
    cudaGetSymbolAddress((void**)&pch, g_ch);
    cudaGetSymbolAddress((void**)&pcl, g_cl);
    cudaGetSymbolAddress((void**)&pwh, g_wh);
    cudaGetSymbolAddress((void**)&pwl, g_wl);

    const int gemm_smem = 2 * STAGE * (int)sizeof(__nv_bfloat16);  // 81920 B
    cudaFuncSetAttribute(gemm_bf16x3, cudaFuncAttributeMaxDynamicSharedMemorySize,
                         gemm_smem);
    const int attn_smem = 101376;
    cudaFuncSetAttribute(attn_mma, cudaFuncAttributeMaxDynamicSharedMemorySize,
                         attn_smem);

    // Prep: split x, transpose+split the 4 weights
    fsplit<<<M_ * D_ / 4 / 256, 256>>>(x, pxh, pxl);
    wsplit_t<<<dim3(32, 32, 4), 256>>>(Wq, Wk, Wv, Wo, pwh, pwl);

    // Fused Q/K/V projection; epilogue emits q,k bf16 and v tf32 hi/lo
    dim3 gqkv(3 * D_ / 128, M_ / 128);   // (24, 64)
    gemm_bf16x3<<<gqkv, 256, gemm_smem>>>(pxh, pxl, pwh, pwl, nullptr, nullptr,
                                          pq, pk, pv, pvl, 1);

    // Prefix tile colsums of V
    vtilesum<<<dim3(32, H_, B_), 64>>>(pv, pvl, pcs);
    vprefix<<<dim3(H_, B_), 64>>>(pcs);

    // Attention; epilogue writes ctx directly as bf16 hi/lo planes
    dim3 gattn(S_ / 64, H_, B_);         // (32, 16, 4)
    attn_mma<<<gattn, 256, attn_smem>>>(pq, pk, pv, pvl, pcs, pch, pcl);

    // Output projection (fp32 + bias)
    dim3 gout(D_ / 128, M_ / 128);       // (8, 64)
    gemm_bf16x3<<<gout, 256, gemm_smem>>>(pch, pcl, pwh + 3 * (size_t)D_ * D_,
                                          pwl + 3 * (size_t)D_ * D_, bo, out,
                                          nullptr, nullptr, nullptr, nullptr, 0);
}

// round 15
// speedup vs baseline: 3.9380x; 1.2930x over previous
#include <cuda_runtime.h>
#include <cuda_bf16.h>
#include <cstdint>

// Problem constants
#define B_  4
#define S_  2048
#define D_  1024
#define H_  16
#define HD_ 64
#define M_  (B_ * S_)   // 8192 rows

// Scratch (allocation-free rule: __device__ globals)
__device__ __nv_bfloat16 g_q[M_ * D_];            // bf16 Q [tok][D]
__device__ __nv_bfloat16 g_k[M_ * D_];            // bf16 K [tok][D]
__device__ __nv_bfloat16 g_vt[B_ * H_ * 64 * S_];   // V^T hi [(b,h,d)][s]
__device__ __nv_bfloat16 g_vlt[B_ * H_ * 64 * S_];  // V^T lo
__device__ float g_cs[B_ * H_ * 32 * 64];         // prefix tile colsums of V
__device__ __nv_bfloat16 g_xh[M_ * D_], g_xl[M_ * D_];    // x hi/lo
__device__ __nv_bfloat16 g_ch[M_ * D_], g_cl[M_ * D_];    // ctx hi/lo
__device__ __nv_bfloat16 g_wh[4 * D_ * D_];               // W^T hi [N][K] x4
__device__ __nv_bfloat16 g_wl[4 * D_ * D_];               // W^T lo

// ---------------------------------------------------------------------------
// cp.async helpers
// ---------------------------------------------------------------------------
__device__ __forceinline__ void cp_async16(void* smem, const void* gmem) {
    uint32_t s = (uint32_t)__cvta_generic_to_shared(smem);
    asm volatile("cp.async.cg.shared.global [%0], [%1], 16;\n" :: "r"(s), "l"(gmem));
}
__device__ __forceinline__ void cp_commit() {
    asm volatile("cp.async.commit_group;\n");
}
template <int N>
__device__ __forceinline__ void cp_wait() {
    asm volatile("cp.async.wait_group %0;\n" :: "n"(N));
}

#define MMA_BF16(c, a, b)                                                     \
    asm volatile(                                                             \
        "mma.sync.aligned.m16n8k16.row.col.f32.bf16.bf16.f32 "                \
        "{%0,%1,%2,%3},{%4,%5,%6,%7},{%8,%9},{%0,%1,%2,%3};"                  \
        : "+f"(c[0]), "+f"(c[1]), "+f"(c[2]), "+f"(c[3])                      \
        : "r"(a[0]), "r"(a[1]), "r"(a[2]), "r"(a[3]), "r"(b[0]), "r"(b[1]))

__device__ __forceinline__ void split_bf16(float x, __nv_bfloat16& h, __nv_bfloat16& l) {
    h = __float2bfloat16_rn(x);
    l = __float2bfloat16_rn(x - __bfloat162float(h));
}

// ---------------------------------------------------------------------------
// Prep: elementwise fp32 -> bf16 hi/lo split (x).
// ---------------------------------------------------------------------------
__global__ __launch_bounds__(256) void fsplit(const float* __restrict__ src,
                                              __nv_bfloat16* __restrict__ h,
                                              __nv_bfloat16* __restrict__ l) {
    const int i = blockIdx.x * 256 + threadIdx.x;
    float4 v = ((const float4*)src)[i];
    __nv_bfloat16 h0, h1, h2, h3, l0, l1, l2, l3;
    split_bf16(v.x, h0, l0);
    split_bf16(v.y, h1, l1);
    split_bf16(v.z, h2, l2);
    split_bf16(v.w, h3, l3);
    __nv_bfloat162* hp = (__nv_bfloat162*)h;
    __nv_bfloat162* lp = (__nv_bfloat162*)l;
    hp[2 * i]     = __nv_bfloat162{h0, h1};
    hp[2 * i + 1] = __nv_bfloat162{h2, h3};
    lp[2 * i]     = __nv_bfloat162{l0, l1};
    lp[2 * i + 1] = __nv_bfloat162{l2, l3};
}

// ---------------------------------------------------------------------------
// Prep: W [K][N] -> W^T hi/lo bf16 [N][K], 32x32 smem tile transpose.
// ---------------------------------------------------------------------------
__global__ __launch_bounds__(256) void wsplit_t(const float* __restrict__ W0,
                                                const float* __restrict__ W1,
                                                const float* __restrict__ W2,
                                                const float* __restrict__ W3,
                                                __nv_bfloat16* __restrict__ dh,
                                                __nv_bfloat16* __restrict__ dl) {
    __shared__ float t[32][33];
    const float* W = (blockIdx.z == 0) ? W0 : (blockIdx.z == 1) ? W1
                   : (blockIdx.z == 2) ? W2 : W3;
    dh += (size_t)blockIdx.z * D_ * D_;
    dl += (size_t)blockIdx.z * D_ * D_;
    const int kx = blockIdx.x * 32, ny = blockIdx.y * 32;
    const int tx = threadIdx.x & 31, ty = threadIdx.x >> 5;
#pragma unroll
    for (int r = 0; r < 4; r++) {
        const int row = ty + r * 8;
        t[row][tx] = W[(size_t)(kx + row) * D_ + ny + tx];
    }
    __syncthreads();
#pragma unroll
    for (int r = 0; r < 4; r++) {
        const int row = ty + r * 8;
        __nv_bfloat16 h, l;
        split_bf16(t[tx][row], h, l);
        dh[(size_t)(ny + row) * D_ + kx + tx] = h;
        dl[(size_t)(ny + row) * D_ + kx + tx] = l;
    }
}

// ---------------------------------------------------------------------------
// Prep: per-tile column sums of V (hi+lo, V^T layout), then prefix over tiles.
// ---------------------------------------------------------------------------
__global__ __launch_bounds__(64) void vtilesum(const __nv_bfloat16* __restrict__ vt,
                                               const __nv_bfloat16* __restrict__ vlt,
                                               float* __restrict__ cs) {
    const int t = blockIdx.x, h = blockIdx.y, b = blockIdx.z, d = threadIdx.x;
    const size_t base = (((size_t)b * H_ + h) * 64 + d) * S_ + t * 64;
    const __nv_bfloat162* ph = (const __nv_bfloat162*)(vt + base);
    const __nv_bfloat162* pl = (const __nv_bfloat162*)(vlt + base);
    float s = 0.f;
#pragma unroll 8
    for (int i = 0; i < 32; i++) {
        __nv_bfloat162 a = ph[i], bb = pl[i];
        s += __bfloat162float(a.x) + __bfloat162float(a.y) +
             __bfloat162float(bb.x) + __bfloat162float(bb.y);
    }
    cs[(((size_t)b * H_ + h) * 32 + t) * 64 + d] = s;
}
__global__ __launch_bounds__(64) void vprefix(float* __restrict__ cs) {
    const int h = blockIdx.x, b = blockIdx.y, d = threadIdx.x;
    float s = 0.f;
    for (int t = 0; t < 32; t++) {
        const size_t off = (((size_t)b * H_ + h) * 32 + t) * 64 + d;
        s += cs[off];
        cs[off] = s;
    }
}

// ---------------------------------------------------------------------------
// bf16 tensor-core GEMM, fused over up to 3 weights, sel = blockIdx.x>>3.
// qkv_mode=1: sel 0/1 -> 1-pass bf16 (hh only; q,k need only bf16 accuracy),
//             sel 2   -> 3-pass bf16x3, epilogue smem-transposes v and emits
//                        V^T hi/lo bf16 planes [(b,h,d)][s].
// qkv_mode=0: 3-pass, fp32 + bias.
// Single-sync pipelined mainloop, 2 CTAs/SM.
// ---------------------------------------------------------------------------
#define GP 40                     // smem pitch in bf16
#define PLANE (128 * GP)          // 5120 bf16 per plane
#define STAGE (4 * PLANE)         // Ah, Al, Bh, Bl

__global__ __launch_bounds__(256, 2) void gemm_bf16x3(
    const __nv_bfloat16* __restrict__ Ah, const __nv_bfloat16* __restrict__ Al,
    const __nv_bfloat16* __restrict__ BhBase,
    const __nv_bfloat16* __restrict__ BlBase,
    const float* __restrict__ bias, float* __restrict__ Cf,
    __nv_bfloat16* __restrict__ Qo, __nv_bfloat16* __restrict__ Ko,
    __nv_bfloat16* __restrict__ Vto, __nv_bfloat16* __restrict__ Vlto,
    int qkv_mode) {
    const int K = D_, N = D_;
    extern __shared__ __nv_bfloat16 smb[];

    const int sel = blockIdx.x >> 3;
    const int bx = blockIdx.x & 7;
    const int by = blockIdx.y;
    const bool full = (qkv_mode == 0) || (sel == 2);
    const __nv_bfloat16* Bh = BhBase + (size_t)sel * D_ * D_;
    const __nv_bfloat16* Bl = BlBase + (size_t)sel * D_ * D_;

    const int tid = threadIdx.x;
    const int wid = tid >> 5, lane = tid & 31;
    const int grp = lane >> 2, tg = lane & 3;
    const int wm = wid & 3;
    const int wn = wid >> 2;

    float acc[2][8][4] = {};

    const __nv_bfloat16* srcA_h = Ah + (size_t)(by * 128) * K;
    const __nv_bfloat16* srcA_l = Al + (size_t)(by * 128) * K;
    const __nv_bfloat16* srcB_h = Bh + (size_t)(bx * 128) * K;
    const __nv_bfloat16* srcB_l = Bl + (size_t)(bx * 128) * K;

    auto load_stage = [&](int stage, int k0) {
        __nv_bfloat16* s = smb + stage * STAGE;
        const __nv_bfloat16* srcs[4] = {srcA_h + k0, srcA_l + k0,
                                        srcB_h + k0, srcB_l + k0};
#pragma unroll
        for (int plane = 0; plane < 4; plane++) {
            if (!full && (plane & 1)) continue;   // lo planes unused in 1-pass
#pragma unroll
            for (int half = 0; half < 2; half++) {
                const int idx = tid + half * 256;
                const int row = idx >> 2, c = idx & 3;
                cp_async16(s + plane * PLANE + row * GP + c * 8,
                           srcs[plane] + (size_t)row * K + c * 8);
            }
        }
    };

    auto compute = [&](int stage) {
        const uint32_t* b32 = (const uint32_t*)(smb + stage * STAGE);
        const uint32_t* pAh = b32 + (wm * 32 + grp) * 20;
        const uint32_t* pAl = pAh + PLANE / 2;
        const uint32_t* pBh = b32 + 2 * (PLANE / 2) + (wn * 64 + grp) * 20;
        const uint32_t* pBl = pBh + PLANE / 2;
#pragma unroll
        for (int ks = 0; ks < 2; ks++) {
            const int k32 = ks * 8;
            uint32_t ah[2][4], bh[8][2];
#pragma unroll
            for (int mf = 0; mf < 2; mf++) {
                const uint32_t* p = pAh + mf * 16 * 20 + k32;
                ah[mf][0] = p[tg];
                ah[mf][1] = p[160 + tg];
                ah[mf][2] = p[tg + 4];
                ah[mf][3] = p[160 + tg + 4];
            }
#pragma unroll
            for (int nf = 0; nf < 8; nf++) {
                const uint32_t* p = pBh + nf * 160 + k32;
                bh[nf][0] = p[tg];
                bh[nf][1] = p[tg + 4];
            }
#pragma unroll
            for (int mf = 0; mf < 2; mf++)
#pragma unroll
                for (int nf = 0; nf < 8; nf++)
                    MMA_BF16(acc[mf][nf], ah[mf], bh[nf]);
            if (full) {
                uint32_t al[2][4], bl[8][2];
#pragma unroll
                for (int mf = 0; mf < 2; mf++) {
                    const uint32_t* q2 = pAl + mf * 16 * 20 + k32;
                    al[mf][0] = q2[tg];
                    al[mf][1] = q2[160 + tg];
                    al[mf][2] = q2[tg + 4];
                    al[mf][3] = q2[160 + tg + 4];
                }
#pragma unroll
                for (int nf = 0; nf < 8; nf++) {
                    const uint32_t* q2 = pBl + nf * 160 + k32;
                    bl[nf][0] = q2[tg];
                    bl[nf][1] = q2[tg + 4];
                }
#pragma unroll
                for (int mf = 0; mf < 2; mf++)
#pragma unroll
                    for (int nf = 0; nf < 8; nf++) {
                        MMA_BF16(acc[mf][nf], al[mf], bh[nf]);
                        MMA_BF16(acc[mf][nf], ah[mf], bl[nf]);
                    }
            }
        }
    };

    load_stage(0, 0);
    cp_commit();

    const int KT = K / 32;   // 32 chunks
    int stage = 0;
    for (int kt = 0; kt < KT; kt++) {
        cp_wait<0>();
        __syncthreads();
        if (kt + 1 < KT) {
            load_stage(stage ^ 1, (kt + 1) * 32);
            cp_commit();
        }
        compute(stage);
        stage ^= 1;
    }

    if (qkv_mode && sel == 2) {
        // V epilogue: smem transpose -> V^T hi/lo bf16 planes, coalesced store
        __syncthreads();                      // mainloop smem reads done
        __nv_bfloat16* Th = smb;              // [128 cols][136]
        __nv_bfloat16* Tl = smb + 128 * 136;
#pragma unroll
        for (int mf = 0; mf < 2; mf++) {
#pragma unroll
            for (int nf = 0; nf < 8; nf++) {
                const int rl0 = wm * 32 + mf * 16 + grp, rl1 = rl0 + 8;
                const int cl0 = wn * 64 + nf * 8 + 2 * tg;
                __nv_bfloat16 h, l;
                split_bf16(acc[mf][nf][0], h, l);
                Th[cl0 * 136 + rl0] = h; Tl[cl0 * 136 + rl0] = l;
                split_bf16(acc[mf][nf][1], h, l);
                Th[(cl0 + 1) * 136 + rl0] = h; Tl[(cl0 + 1) * 136 + rl0] = l;
                split_bf16(acc[mf][nf][2], h, l);
                Th[cl0 * 136 + rl1] = h; Tl[cl0 * 136 + rl1] = l;
                split_bf16(acc[mf][nf][3], h, l);
                Th[(cl0 + 1) * 136 + rl1] = h; Tl[(cl0 + 1) * 136 + rl1] = l;
            }
        }
        __syncthreads();
#pragma unroll 4
        for (int it = 0; it < 32; it++) {
            const int idx = tid + it * 256;     // 8192 u32 per plane
            const int colL = idx >> 6;          // 0..127
            const int tp = idx & 63;            // token pair within tile
            const int token = by * 128 + tp * 2;
            const int b = token >> 11, srow = token & 2047;
            const int hglob = bx * 2 + (colL >> 6);
            const int d = colL & 63;
            const size_t off = (((size_t)b * H_ + hglob) * 64 + d) * S_ + srow;
            *(uint32_t*)&Vto[off]  = *(const uint32_t*)&Th[colL * 136 + tp * 2];
            *(uint32_t*)&Vlto[off] = *(const uint32_t*)&Tl[colL * 136 + tp * 2];
        }
        return;
    }

#pragma unroll
    for (int mf = 0; mf < 2; mf++) {
#pragma unroll
        for (int nf = 0; nf < 8; nf++) {
            const int row = by * 128 + wm * 32 + mf * 16 + grp;
            const int col = bx * 128 + wn * 64 + nf * 8 + 2 * tg;
            const size_t o00 = (size_t)row * N + col;
            const size_t o10 = (size_t)(row + 8) * N + col;
            if (qkv_mode) {
                __nv_bfloat16* O = sel ? Ko : Qo;
                *(__nv_bfloat162*)&O[o00] =
                    __floats2bfloat162_rn(acc[mf][nf][0], acc[mf][nf][1]);
                *(__nv_bfloat162*)&O[o10] =
                    __floats2bfloat162_rn(acc[mf][nf][2], acc[mf][nf][3]);
            } else {
                const float b0 = bias ? bias[col] : 0.f;
                const float b1 = bias ? bias[col + 1] : 0.f;
                Cf[o00]     = acc[mf][nf][0] + b0;
                Cf[o00 + 1] = acc[mf][nf][1] + b1;
                Cf[o10]     = acc[mf][nf][2] + b0;
                Cf[o10 + 1] = acc[mf][nf][3] + b1;
            }
        }
    }
}

// ---------------------------------------------------------------------------
// Tensor-core causal attention, P = 1 + D decomposition, all-bf16 MMAs.
// QK^T: q,k bf16 [tok][d]. DV: D bf16 [q][ktok] (A), V^T bf16 [d][ktok] (B);
// diagonal tile adds a (D, V^T_lo) pass so the -1 masked cancellation against
// the precomputed colsum prefix is exact. K/V^T double-buffered with prefetch.
// Smem (64KB -> 3 CTAs/SM):
//   Qb  [64][72]bf16 @0      Kb0 @9216   Kb1 @18432
//   Db  [64][72]bf16 @27648  Vt0 @36864  Vt1 @46080
//   Vlt @55296               Lred[4][64]f32 @64512   total 65536
// ---------------------------------------------------------------------------
#define KPB36 36   // bf16 tile pitch in u32 (72 bf16 = 144B)

__global__ __launch_bounds__(256, 3) void attn_mma(
    const __nv_bfloat16* __restrict__ q, const __nv_bfloat16* __restrict__ k,
    const __nv_bfloat16* __restrict__ vt, const __nv_bfloat16* __restrict__ vlt,
    const float* __restrict__ csum,
    __nv_bfloat16* __restrict__ ch, __nv_bfloat16* __restrict__ cl) {
    extern __shared__ float sm[];
    char* smc = (char*)sm;
    const uint32_t offK[2]  = {9216u, 18432u};
    const uint32_t offVt[2] = {36864u, 46080u};
    __nv_bfloat16* Db = (__nv_bfloat16*)(smc + 27648);
    char* Vlt = smc + 55296;
    float* Lred = (float*)(smc + 64512);

    const int tid = threadIdx.x;
    const int wid = tid >> 5, lane = tid & 31;
    const int grp = lane >> 2, tg = lane & 3;
    const int wm = wid & 3;            // S^T: k-row group / DV: q-row group
    const int wn = wid >> 2;           // S^T: q-col group / DV: d-col group
    const int qt = (int)gridDim.x - 1 - (int)blockIdx.x;   // heavy first
    const int h = blockIdx.y, b = blockIdx.z;

    const size_t base = ((size_t)b * S_) * D_ + (size_t)h * HD_;
    const size_t vbase = (((size_t)b * H_ + h) * 64) * S_;   // V^T row 0

    auto load_kv = [&](int stage, int kt2) {
        char* Kd = smc + offK[stage];
        char* Vd = smc + offVt[stage];
        const __nv_bfloat16* ksrc = k + base + (size_t)(kt2 * 64) * D_;
        const __nv_bfloat16* vsrc = vt + vbase + kt2 * 64;
#pragma unroll
        for (int it = 0; it < 2; it++) {          // K: 512 x 16B
            const int idx = tid + it * 256;
            const int row = idx >> 3, c = idx & 7;
            cp_async16(Kd + row * 144 + c * 16, ksrc + (size_t)row * D_ + c * 8);
        }
#pragma unroll
        for (int it = 0; it < 2; it++) {          // V^T: 512 x 16B
            const int idx = tid + it * 256;
            const int row = idx >> 3, c = idx & 7;
            cp_async16(Vd + row * 144 + c * 16, vsrc + (size_t)row * S_ + c * 8);
        }
    };
    auto load_vl = [&](int kt2) {
        const __nv_bfloat16* vsrc = vlt + vbase + kt2 * 64;
#pragma unroll
        for (int it = 0; it < 2; it++) {
            const int idx = tid + it * 256;
            const int row = idx >> 3, c = idx & 7;
            cp_async16(Vlt + row * 144 + c * 16, vsrc + (size_t)row * S_ + c * 8);
        }
    };

    {   // Q tile
        const __nv_bfloat16* qsrc = q + base + (size_t)(qt * 64) * D_;
#pragma unroll
        for (int it = 0; it < 2; it++) {
            const int idx = tid + it * 256;
            const int row = idx >> 3, c = idx & 7;
            cp_async16(smc + row * 144 + c * 16, qsrc + (size_t)row * D_ + c * 8);
        }
    }
    load_kv(0, 0);
    if (qt == 0) load_vl(0);
    cp_commit();

    float acc[4][4]  = {};
    float dsum[4][2] = {};
    int stage = 0;

    for (int kt = 0; kt <= qt; kt++) {
        cp_wait<0>();
        __syncthreads();

        if (kt < qt) {
            load_kv(stage ^ 1, kt + 1);
            if (kt + 1 == qt) load_vl(qt);
            cp_commit();
        }

        // S^T = K @ Q^T (m = k-token, n = q-token), bf16
        float s[4][4] = {};
        const uint32_t* Ka = (const uint32_t*)(smc + offK[stage]) +
                             (wm * 16 + grp) * KPB36;
        const uint32_t* Qbase32 = (const uint32_t*)smc;
#pragma unroll
        for (int ks = 0; ks < 4; ks++) {
            const int k32 = ks * 8;
            uint32_t a[4];
            a[0] = Ka[k32 + tg];
            a[1] = Ka[8 * KPB36 + k32 + tg];
            a[2] = Ka[k32 + tg + 4];
            a[3] = Ka[8 * KPB36 + k32 + tg + 4];
#pragma unroll
            for (int nf = 0; nf < 4; nf++) {
                const uint32_t* Qp = Qbase32 +
                    (wn * 32 + nf * 8 + grp) * KPB36 + k32 + tg;
                uint32_t bb[2] = { Qp[0], Qp[4] };
                MMA_BF16(s[nf], a, bb);
            }
        }

        // d = expm1(s/4096); masked -> -1 (exact in bf16). Store D^T bf16.
        const int kg0 = kt * 64 + wm * 16 + grp;
        const int kloc = wm * 16 + grp;
#pragma unroll
        for (int nf = 0; nf < 4; nf++) {
            const int qg0  = qt * 64 + wn * 32 + nf * 8 + 2 * tg;
            const int qloc = wn * 32 + nf * 8 + 2 * tg;
            float d0, d1, d2, d3;
            {
                float x = s[nf][0] * (1.f / 4096.f);
                d0 = (kg0 <= qg0)     ? x * (1.f + x * (0.5f + x * (1.f / 6.f))) : -1.f;
                x = s[nf][1] * (1.f / 4096.f);
                d1 = (kg0 <= qg0 + 1) ? x * (1.f + x * (0.5f + x * (1.f / 6.f))) : -1.f;
                x = s[nf][2] * (1.f / 4096.f);
                d2 = (kg0 + 8 <= qg0)     ? x * (1.f + x * (0.5f + x * (1.f / 6.f))) : -1.f;
                x = s[nf][3] * (1.f / 4096.f);
                d3 = (kg0 + 8 <= qg0 + 1) ? x * (1.f + x * (0.5f + x * (1.f / 6.f))) : -1.f;
            }
            dsum[nf][0] += d0 + d2;
            dsum[nf][1] += d1 + d3;
            Db[qloc * 72 + kloc]           = __float2bfloat16_rn(d0);
            Db[(qloc + 1) * 72 + kloc]     = __float2bfloat16_rn(d1);
            Db[qloc * 72 + kloc + 8]       = __float2bfloat16_rn(d2);
            Db[(qloc + 1) * 72 + kloc + 8] = __float2bfloat16_rn(d3);
        }
        __syncthreads();

        // acc += D @ V (bf16): A = D [q][ktok], B = V^T [d][ktok]
        const uint32_t* Da = (const uint32_t*)Db + (wm * 16 + grp) * KPB36;
        const uint32_t* Vb32 = (const uint32_t*)(smc + offVt[stage]);
        const bool diag = (kt == qt);
#pragma unroll
        for (int ks = 0; ks < 4; ks++) {
            const int k32 = ks * 8;
            uint32_t a[4];
            a[0] = Da[k32 + tg];
            a[1] = Da[8 * KPB36 + k32 + tg];
            a[2] = Da[k32 + tg + 4];
            a[3] = Da[8 * KPB36 + k32 + tg + 4];
#pragma unroll
            for (int nf = 0; nf < 4; nf++) {
                const uint32_t* Vp = Vb32 +
                    (wn * 32 + nf * 8 + grp) * KPB36 + k32 + tg;
                uint32_t bb[2] = { Vp[0], Vp[4] };
                MMA_BF16(acc[nf], a, bb);
            }
            if (diag) {
                const uint32_t* Vl32 = (const uint32_t*)Vlt;
#pragma unroll
                for (int nf = 0; nf < 4; nf++) {
                    const uint32_t* Vp = Vl32 +
                        (wn * 32 + nf * 8 + grp) * KPB36 + k32 + tg;
                    uint32_t bb[2] = { Vp[0], Vp[4] };
                    MMA_BF16(acc[nf], a, bb);
                }
            }
        }
        stage ^= 1;
    }

    // Reduce dsum over grp lanes
#pragma unroll
    for (int off = 16; off >= 4; off >>= 1)
#pragma unroll
        for (int nf = 0; nf < 4; nf++) {
            dsum[nf][0] += __shfl_xor_sync(0xffffffffu, dsum[nf][0], off);
            dsum[nf][1] += __shfl_xor_sync(0xffffffffu, dsum[nf][1], off);
        }
    if (grp == 0) {
#pragma unroll
        for (int nf = 0; nf < 4; nf++) {
            Lred[wm * 64 + wn * 32 + nf * 8 + 2 * tg]     = dsum[nf][0];
            Lred[wm * 64 + wn * 32 + nf * 8 + 2 * tg + 1] = dsum[nf][1];
        }
    }
    __syncthreads();

    // Epilogue: O = (acc + prefix_colsum) / l, written as bf16 hi/lo
    const float* Cs = csum + (((size_t)b * H_ + h) * 32 + qt) * 64;
    const float nk = 64.0f * (float)(qt + 1);
    const int r0 = wm * 16 + grp, r1 = r0 + 8;
    float l0 = nk, l1 = nk;
#pragma unroll
    for (int w = 0; w < 4; w++) {
        l0 += Lred[w * 64 + r0];
        l1 += Lred[w * 64 + r1];
    }
    const float inv0 = 1.0f / l0, inv1 = 1.0f / l1;
#pragma unroll
    for (int nf = 0; nf < 4; nf++) {
        const int dcol = wn * 32 + nf * 8 + 2 * tg;
        const float cs0 = Cs[dcol], cs1 = Cs[dcol + 1];
        const float o00 = (acc[nf][0] + cs0) * inv0;
        const float o01 = (acc[nf][1] + cs1) * inv0;
        const float o10 = (acc[nf][2] + cs0) * inv1;
        const float o11 = (acc[nf][3] + cs1) * inv1;
        __nv_bfloat16 h0, h1, l0b, l1b;
        const size_t a0 = base + (size_t)(qt * 64 + r0) * D_ + dcol;
        const size_t a1 = base + (size_t)(qt * 64 + r1) * D_ + dcol;
        split_bf16(o00, h0, l0b); split_bf16(o01, h1, l1b);
        *(__nv_bfloat162*)&ch[a0] = __nv_bfloat162{h0, h1};
        *(__nv_bfloat162*)&cl[a0] = __nv_bfloat162{l0b, l1b};
        split_bf16(o10, h0, l0b); split_bf16(o11, h1, l1b);
        *(__nv_bfloat162*)&ch[a1] = __nv_bfloat162{h0, h1};
        *(__nv_bfloat162*)&cl[a1] = __nv_bfloat162{l0b, l1b};
    }
}

// ---------------------------------------------------------------------------
// Launch
// ---------------------------------------------------------------------------
extern "C" void kernel_launch(void* const* d_in, const int* in_sizes, int n_in,
                              void* d_out, int out_size) {
    const float* x  = (const float*)d_in[0];
    const float* Wq = (const float*)d_in[1];
    const float* Wk = (const float*)d_in[2];
    const float* Wv = (const float*)d_in[3];
    const float* Wo = (const float*)d_in[4];
    const float* bo = (const float*)d_in[5];
    float* out = (float*)d_out;

    __nv_bfloat16 *pq, *pk, *pvt, *pvlt;
    float *pcs;
    cudaGetSymbolAddress((void**)&pq, g_q);
    cudaGetSymbolAddress((void**)&pk, g_k);
    cudaGetSymbolAddress((void**)&pvt, g_vt);
    cudaGetSymbolAddress((void**)&pvlt, g_vlt);
    cudaGetSymbolAddress((void**)&pcs, g_cs);
    __nv_bfloat16 *pxh, *pxl, *pch, *pcl, *pwh, *pwl;
    cudaGetSymbolAddress((void**)&pxh, g_xh);
    cudaGetSymbolAddress((void**)&pxl, g_xl);
    cudaGetSymbolAddress((void**)&pch, g_ch);
    cudaGetSymbolAddress((void**)&pcl, g_cl);
    cudaGetSymbolAddress((void**)&pwh, g_wh);
    cudaGetSymbolAddress((void**)&pwl, g_wl);

    const int gemm_smem = 2 * STAGE * (int)sizeof(__nv_bfloat16);  // 81920 B
    cudaFuncSetAttribute(gemm_bf16x3, cudaFuncAttributeMaxDynamicSharedMemorySize,
                         gemm_smem);
    const int attn_smem = 65536;
    cudaFuncSetAttribute(attn_mma, cudaFuncAttributeMaxDynamicSharedMemorySize,
                         attn_smem);

    // Prep
    fsplit<<<M_ * D_ / 4 / 256, 256>>>(x, pxh, pxl);
    wsplit_t<<<dim3(32, 32, 4), 256>>>(Wq, Wk, Wv, Wo, pwh, pwl);

    // Fused Q/K/V projection (Q,K 1-pass; V 3-pass with V^T hi/lo epilogue)
    dim3 gqkv(3 * D_ / 128, M_ / 128);   // (24, 64)
    gemm_bf16x3<<<gqkv, 256, gemm_smem>>>(pxh, pxl, pwh, pwl, nullptr, nullptr,
                                          pq, pk, pvt, pvlt, 1);

    // Prefix tile colsums of V
    vtilesum<<<dim3(32, H_, B_), 64>>>(pvt, pvlt, pcs);
    vprefix<<<dim3(H_, B_), 64>>>(pcs);

    // Attention (all-bf16 MMAs, 3 CTAs/SM); epilogue emits ctx bf16 hi/lo
    dim3 gattn(S_ / 64, H_, B_);         // (32, 16, 4)
    attn_mma<<<gattn, 256, attn_smem>>>(pq, pk, pvt, pvlt, pcs, pch, pcl);

    // Output projection (3-pass, fp32 + bias)
    dim3 gout(D_ / 128, M_ / 128);       // (8, 64)
    gemm_bf16x3<<<gout, 256, gemm_smem>>>(pch, pcl, pwh + 3 * (size_t)D_ * D_,
                                          pwl + 3 * (size_t)D_ * D_, bo, out,
                                          nullptr, nullptr, nullptr, nullptr, 0);
}